// round 2
// baseline (speedup 1.0000x reference)
#include <cuda_runtime.h>
#include <math.h>

#define Bc 2
#define Sc 2048
#define Dc 1024
#define Hc 8
#define HDc 128
#define Mc (Bc*Sc)   // 4096

// scratch: [B,H,S,HD] fp32, 16MB each
__device__ float g_Q[Bc*Hc*Sc*HDc];
__device__ float g_K[Bc*Hc*Sc*HDc];
__device__ float g_V[Bc*Hc*Sc*HDc];

// ------------------------------------------------------------------
// Projection GEMM: C[m,n] = A[m,:]@W[:,n] + bias[n], scattered to [B,H,S,HD]
// BM=64, BN=64, BK=16, 256 threads, 4x4 micro-tile
// ------------------------------------------------------------------
#define BM 64
#define BN 64
#define BK 16

__global__ __launch_bounds__(256) void proj_kernel(
    const float* __restrict__ q, const float* __restrict__ k, const float* __restrict__ v,
    const float* __restrict__ Wq, const float* __restrict__ bq,
    const float* __restrict__ Wk, const float* __restrict__ bk,
    const float* __restrict__ Wv, const float* __restrict__ bv)
{
    const float* A; const float* W; const float* bias; float* out;
    if (blockIdx.z == 0)      { A = q; W = Wq; bias = bq; out = g_Q; }
    else if (blockIdx.z == 1) { A = k; W = Wk; bias = bk; out = g_K; }
    else                      { A = v; W = Wv; bias = bv; out = g_V; }

    __shared__ float As[BK][BM + 1];
    __shared__ float Bs[BK][BN];

    const int tid = threadIdx.x;
    const int tx  = tid & 15;
    const int ty  = tid >> 4;
    const int m0  = blockIdx.y * BM;
    const int n0  = blockIdx.x * BN;

    const int arow = tid >> 2;
    const int acol = (tid & 3) << 2;
    const int brow = tid >> 4;
    const int bcol = (tid & 15) << 2;

    float acc[4][4] = {};

    for (int k0 = 0; k0 < Dc; k0 += BK) {
        float4 a4 = *(const float4*)(A + (size_t)(m0 + arow) * Dc + k0 + acol);
        As[acol + 0][arow] = a4.x;
        As[acol + 1][arow] = a4.y;
        As[acol + 2][arow] = a4.z;
        As[acol + 3][arow] = a4.w;
        *(float4*)(&Bs[brow][bcol]) =
            *(const float4*)(W + (size_t)(k0 + brow) * Dc + n0 + bcol);
        __syncthreads();

        #pragma unroll
        for (int kk = 0; kk < BK; kk++) {
            float a[4], bb[4];
            #pragma unroll
            for (int i = 0; i < 4; i++) a[i] = As[kk][ty * 4 + i];
            float4 b4 = *(const float4*)(&Bs[kk][tx * 4]);
            bb[0] = b4.x; bb[1] = b4.y; bb[2] = b4.z; bb[3] = b4.w;
            #pragma unroll
            for (int i = 0; i < 4; i++)
                #pragma unroll
                for (int j = 0; j < 4; j++)
                    acc[i][j] += a[i] * bb[j];
        }
        __syncthreads();
    }

    #pragma unroll
    for (int i = 0; i < 4; i++) {
        int m = m0 + ty * 4 + i;
        int b = m >> 11;
        int s = m & (Sc - 1);
        #pragma unroll
        for (int j = 0; j < 4; j++) {
            int n  = n0 + tx * 4 + j;
            int h  = n >> 7;
            int hd = n & (HDc - 1);
            out[(((size_t)(b * Hc + h)) * Sc + s) * HDc + hd] = acc[i][j] + bias[n];
        }
    }
}

// ------------------------------------------------------------------
// Flash attention: 64 q-rows per block, 64-key tiles, online softmax.
// ------------------------------------------------------------------
#define TQ 64
#define TK 64
#define QSTR 129
#define KSTR 65
#define SSTR 65

#define SM_Q   0
#define SM_KV  (TQ * QSTR)
#define SM_S   (SM_KV + HDc * KSTR)
#define SM_M   (SM_S + TQ * SSTR)
#define SM_L   (SM_M + TQ)
#define SM_A   (SM_L + TQ)
#define ATTN_SMEM_FLOATS (SM_A + TQ)
#define ATTN_SMEM_BYTES  (ATTN_SMEM_FLOATS * 4)

__global__ __launch_bounds__(256) void attn_kernel(
    const unsigned int* __restrict__ mask, float* __restrict__ out)
{
    extern __shared__ float smem[];
    float* sQ   = smem + SM_Q;
    float* sKV  = smem + SM_KV;
    float* sS   = smem + SM_S;
    float* mrow = smem + SM_M;
    float* lrow = smem + SM_L;
    float* arow = smem + SM_A;

    const int tid  = threadIdx.x;
    const int bh   = blockIdx.y;
    const int b    = bh >> 3;
    const int h    = bh & (Hc - 1);
    const int q0   = blockIdx.x * TQ;
    const int tx   = tid & 15;
    const int ty   = tid >> 4;
    const int warp = tid >> 5;
    const int lane = tid & 31;

    const float* Qg = g_Q + (size_t)bh * Sc * HDc;
    const float* Kg = g_K + (size_t)bh * Sc * HDc;
    const float* Vg = g_V + (size_t)bh * Sc * HDc;
    // mask is [B,1,S,S] of 4-byte elements (int32 or float32 bool encoding);
    // nonzero bits == True for both encodings.
    const unsigned int* maskb = mask + (size_t)b * Sc * Sc;

    for (int i = tid; i < TQ * HDc; i += 256) {
        int r = i >> 7, d = i & (HDc - 1);
        sQ[r * QSTR + d] = Qg[(size_t)(q0 + r) * HDc + d];
    }
    if (tid < TQ) { mrow[tid] = -1e30f; lrow[tid] = 0.0f; }

    float oacc[8][4] = {};
    const float scale = 0.08838834764831845f;  // 1/sqrt(128)

    for (int kt = 0; kt < Sc / TK; kt++) {
        const int k0 = kt * TK;
        __syncthreads();

        for (int i = tid; i < TK * HDc; i += 256) {
            int kk = i >> 7, d = i & (HDc - 1);
            sKV[d * KSTR + kk] = Kg[(size_t)(k0 + kk) * HDc + d];
        }
        __syncthreads();

        float sacc[4][4] = {};
        #pragma unroll 4
        for (int d = 0; d < HDc; d++) {
            float a[4], bb[4];
            #pragma unroll
            for (int i = 0; i < 4; i++) a[i] = sQ[(ty + 16 * i) * QSTR + d];
            #pragma unroll
            for (int j = 0; j < 4; j++) bb[j] = sKV[d * KSTR + tx + 16 * j];
            #pragma unroll
            for (int i = 0; i < 4; i++)
                #pragma unroll
                for (int j = 0; j < 4; j++)
                    sacc[i][j] += a[i] * bb[j];
        }
        #pragma unroll
        for (int i = 0; i < 4; i++) {
            int qr = ty + 16 * i;
            const unsigned int* mr = maskb + (size_t)(q0 + qr) * Sc + k0;
            #pragma unroll
            for (int j = 0; j < 4; j++) {
                int kc = tx + 16 * j;
                float vsc = (mr[kc] != 0u) ? -1e6f : sacc[i][j];
                sS[qr * SSTR + kc] = vsc * scale;
            }
        }
        __syncthreads();

        for (int i = tid; i < TK * HDc; i += 256)
            sKV[i] = Vg[(size_t)k0 * HDc + i];

        if (tid < TQ) {
            int r = tid;
            float mold = mrow[r];
            float rmax = -1e30f;
            for (int kk = 0; kk < TK; kk++) rmax = fmaxf(rmax, sS[r * SSTR + kk]);
            float mnew = fmaxf(mold, rmax);
            float al   = __expf(mold - mnew);
            float sum  = 0.0f;
            for (int kk = 0; kk < TK; kk++) {
                float p = __expf(sS[r * SSTR + kk] - mnew);
                sS[r * SSTR + kk] = p;
                sum += p;
            }
            mrow[r] = mnew;
            lrow[r] = lrow[r] * al + sum;
            arow[r] = al;
        }
        __syncthreads();

        #pragma unroll
        for (int i = 0; i < 8; i++) {
            float al = arow[warp * 8 + i];
            #pragma unroll
            for (int t = 0; t < 4; t++) oacc[i][t] *= al;
        }
        #pragma unroll 2
        for (int kk = 0; kk < TK; kk++) {
            float vv[4];
            #pragma unroll
            for (int t = 0; t < 4; t++) vv[t] = sKV[kk * HDc + lane + 32 * t];
            #pragma unroll
            for (int i = 0; i < 8; i++) {
                float p = sS[(warp * 8 + i) * SSTR + kk];
                #pragma unroll
                for (int t = 0; t < 4; t++) oacc[i][t] += p * vv[t];
            }
        }
    }

    #pragma unroll
    for (int i = 0; i < 8; i++) {
        int r = warp * 8 + i;
        float inv = 1.0f / lrow[r];
        float* orow = out + ((size_t)b * Sc + (q0 + r)) * Dc + h * HDc;
        #pragma unroll
        for (int t = 0; t < 4; t++)
            orow[lane + 32 * t] = oacc[i][t] * inv;
    }
}

// ------------------------------------------------------------------
extern "C" void kernel_launch(void* const* d_in, const int* in_sizes, int n_in,
                              void* d_out, int out_size)
{
    const float* q  = (const float*)d_in[0];
    const float* k  = (const float*)d_in[1];
    const float* v  = (const float*)d_in[2];
    const unsigned int* mask = (const unsigned int*)d_in[3];
    const float* Wq = (const float*)d_in[4];
    const float* bq = (const float*)d_in[5];
    const float* Wk = (const float*)d_in[6];
    const float* bk = (const float*)d_in[7];
    const float* Wv = (const float*)d_in[8];
    const float* bv = (const float*)d_in[9];
    float* out = (float*)d_out;

    dim3 pgrid(Dc / BN, Mc / BM, 3);
    proj_kernel<<<pgrid, 256>>>(q, k, v, Wq, bq, Wk, bk, Wv, bv);

    cudaFuncSetAttribute(attn_kernel,
                         cudaFuncAttributeMaxDynamicSharedMemorySize,
                         ATTN_SMEM_BYTES);
    dim3 agrid(Sc / TQ, Bc * Hc);
    attn_kernel<<<agrid, 256, ATTN_SMEM_BYTES>>>(mask, out);
}

// round 4
// speedup vs baseline: 1.2349x; 1.2349x over previous
#include <cuda_runtime.h>
#include <math.h>

#define Bc 2
#define Sc 2048
#define Dc 1024
#define Hc 8
#define HDc 128
#define Mc (Bc*Sc)   // 4096

// scratch: [B,H,S,HD] fp32
__device__ float g_Q[Bc*Hc*Sc*HDc];
__device__ float g_K[Bc*Hc*Sc*HDc];
__device__ float g_V[Bc*Hc*Sc*HDc];

// ------------------------------------------------------------------
// Projection GEMM: 128x128x16 tile, 256 threads, 8x8 micro-tile
// ------------------------------------------------------------------
#define BM 128
#define BN 128
#define BK 16
#define ASTR 132

__global__ __launch_bounds__(256, 2) void proj_kernel(
    const float* __restrict__ q, const float* __restrict__ k, const float* __restrict__ v,
    const float* __restrict__ Wq, const float* __restrict__ bq,
    const float* __restrict__ Wk, const float* __restrict__ bk,
    const float* __restrict__ Wv, const float* __restrict__ bv)
{
    const float* A; const float* W; const float* bias; float* out;
    if (blockIdx.z == 0)      { A = q; W = Wq; bias = bq; out = g_Q; }
    else if (blockIdx.z == 1) { A = k; W = Wk; bias = bk; out = g_K; }
    else                      { A = v; W = Wv; bias = bv; out = g_V; }

    __shared__ float As[BK][ASTR];   // A transposed: As[k][m]
    __shared__ float Bs[BK][BN];

    const int tid = threadIdx.x;
    const int tx  = tid & 15;        // col micro (8 cols)
    const int ty  = tid >> 4;        // row micro (8 rows)
    const int m0  = blockIdx.y * BM;
    const int n0  = blockIdx.x * BN;

    const int arow = tid >> 1;            // 0..127
    const int acol = (tid & 1) * 8;       // 0 or 8
    const int brow = tid >> 4;            // 0..15
    const int bcol = (tid & 15) * 8;      // 0..120

    float acc[8][8] = {};

    for (int k0 = 0; k0 < Dc; k0 += BK) {
        float4 a0 = *(const float4*)(A + (size_t)(m0 + arow) * Dc + k0 + acol);
        float4 a1 = *(const float4*)(A + (size_t)(m0 + arow) * Dc + k0 + acol + 4);
        As[acol + 0][arow] = a0.x; As[acol + 1][arow] = a0.y;
        As[acol + 2][arow] = a0.z; As[acol + 3][arow] = a0.w;
        As[acol + 4][arow] = a1.x; As[acol + 5][arow] = a1.y;
        As[acol + 6][arow] = a1.z; As[acol + 7][arow] = a1.w;
        *(float4*)(&Bs[brow][bcol])     = *(const float4*)(W + (size_t)(k0 + brow) * Dc + n0 + bcol);
        *(float4*)(&Bs[brow][bcol + 4]) = *(const float4*)(W + (size_t)(k0 + brow) * Dc + n0 + bcol + 4);
        __syncthreads();

        #pragma unroll
        for (int kk = 0; kk < BK; kk++) {
            float4 av0 = *(const float4*)(&As[kk][ty * 8]);
            float4 av1 = *(const float4*)(&As[kk][ty * 8 + 4]);
            float4 bv0 = *(const float4*)(&Bs[kk][tx * 8]);
            float4 bv1 = *(const float4*)(&Bs[kk][tx * 8 + 4]);
            float a[8] = {av0.x, av0.y, av0.z, av0.w, av1.x, av1.y, av1.z, av1.w};
            float b[8] = {bv0.x, bv0.y, bv0.z, bv0.w, bv1.x, bv1.y, bv1.z, bv1.w};
            #pragma unroll
            for (int i = 0; i < 8; i++)
                #pragma unroll
                for (int j = 0; j < 8; j++)
                    acc[i][j] += a[i] * b[j];
        }
        __syncthreads();
    }

    // epilogue: BN=128 -> head constant per block; hd = tx*8+j contiguous
    const int h = n0 >> 7;
    float bvec[8];
    #pragma unroll
    for (int j = 0; j < 8; j++) bvec[j] = bias[n0 + tx * 8 + j];

    #pragma unroll
    for (int i = 0; i < 8; i++) {
        int m = m0 + ty * 8 + i;
        int b = m >> 11;
        int s = m & (Sc - 1);
        float* dst = out + (((size_t)(b * Hc + h)) * Sc + s) * HDc + tx * 8;
        float4 o0 = {acc[i][0] + bvec[0], acc[i][1] + bvec[1], acc[i][2] + bvec[2], acc[i][3] + bvec[3]};
        float4 o1 = {acc[i][4] + bvec[4], acc[i][5] + bvec[5], acc[i][6] + bvec[6], acc[i][7] + bvec[7]};
        *(float4*)(dst)     = o0;
        *(float4*)(dst + 4) = o1;
    }
}

// ------------------------------------------------------------------
// Flash attention: 64 q-rows, 64-key tiles, in-register softmax w/ shfl
// smem: sQ[64][132], sKV (K rows [64][132] / V rows [64][128]), sS[64][65]
// ------------------------------------------------------------------
#define TQ 64
#define TK 64
#define QSTR 132
#define KSTR 132
#define VSTR 128
#define SSTR 65

#define SM_Q   0
#define SM_KV  (TQ * QSTR)
#define SM_S   (SM_KV + TK * KSTR)
#define SM_M   (SM_S + TQ * SSTR)
#define SM_L   (SM_M + TQ)
#define SM_A   (SM_L + TQ)
#define ATTN_SMEM_FLOATS (SM_A + TQ)
#define ATTN_SMEM_BYTES  (ATTN_SMEM_FLOATS * 4)

__global__ __launch_bounds__(256, 2) void attn_kernel(
    const unsigned int* __restrict__ mask, float* __restrict__ out)
{
    extern __shared__ float smem[];
    float* sQ   = smem + SM_Q;
    float* sKV  = smem + SM_KV;
    float* sS   = smem + SM_S;
    float* mrow = smem + SM_M;
    float* lrow = smem + SM_L;
    float* arow = smem + SM_A;

    const int tid  = threadIdx.x;
    const int bh   = blockIdx.y;
    const int b    = bh >> 3;
    const int h    = bh & (Hc - 1);
    const int q0   = blockIdx.x * TQ;
    const int tx   = tid & 15;
    const int ty   = tid >> 4;
    const int warp = tid >> 5;
    const int lane = tid & 31;

    const float* Qg = g_Q + (size_t)bh * Sc * HDc;
    const float* Kg = g_K + (size_t)bh * Sc * HDc;
    const float* Vg = g_V + (size_t)bh * Sc * HDc;
    const unsigned int* maskb = mask + (size_t)b * Sc * Sc;

    // Q tile load (float4)
    for (int idx = tid; idx < TQ * HDc / 4; idx += 256) {
        int r = idx >> 5, d4 = (idx & 31) * 4;
        *(float4*)(&sQ[r * QSTR + d4]) = *(const float4*)(Qg + (size_t)(q0 + r) * HDc + d4);
    }
    if (tid < TQ) { mrow[tid] = -1e30f; lrow[tid] = 0.0f; }

    float oacc[8][4] = {};   // rows warp*8+i ; cols lane*4+t
    const float scale = 0.08838834764831845f;  // 1/sqrt(128)

    for (int kt = 0; kt < Sc / TK; kt++) {
        const int k0 = kt * TK;
        __syncthreads();   // prior PV / Q-load done before overwriting sKV

        // K tile, row-major (float4)
        for (int idx = tid; idx < TK * HDc / 4; idx += 256) {
            int kk = idx >> 5, d4 = (idx & 31) * 4;
            *(float4*)(&sKV[kk * KSTR + d4]) = *(const float4*)(Kg + (size_t)(k0 + kk) * HDc + d4);
        }
        __syncthreads();

        // scores: rows ty+16i, cols tx+16j, float4 over d
        float sacc[4][4] = {};
        #pragma unroll 2
        for (int d = 0; d < HDc; d += 4) {
            float4 a[4], bb[4];
            #pragma unroll
            for (int i = 0; i < 4; i++) a[i]  = *(const float4*)(&sQ[(ty + 16 * i) * QSTR + d]);
            #pragma unroll
            for (int j = 0; j < 4; j++) bb[j] = *(const float4*)(&sKV[(tx + 16 * j) * KSTR + d]);
            #pragma unroll
            for (int i = 0; i < 4; i++)
                #pragma unroll
                for (int j = 0; j < 4; j++) {
                    sacc[i][j] += a[i].x * bb[j].x;
                    sacc[i][j] += a[i].y * bb[j].y;
                    sacc[i][j] += a[i].z * bb[j].z;
                    sacc[i][j] += a[i].w * bb[j].w;
                }
        }

        // mask (before scale), in-register online softmax per row (16 lanes/row)
        #pragma unroll
        for (int i = 0; i < 4; i++) {
            int qr = ty + 16 * i;
            const unsigned int* mr = maskb + (size_t)(q0 + qr) * Sc + k0;
            float p[4];
            float rmax = -1e30f;
            #pragma unroll
            for (int j = 0; j < 4; j++) {
                float vsc = (mr[tx + 16 * j] != 0u) ? -1e6f : sacc[i][j];
                p[j] = vsc * scale;
                rmax = fmaxf(rmax, p[j]);
            }
            float mold = mrow[qr];           // read BEFORE shfl sync; write is after
            #pragma unroll
            for (int o = 8; o > 0; o >>= 1)
                rmax = fmaxf(rmax, __shfl_xor_sync(0xffffffffu, rmax, o, 16));
            float mnew = fmaxf(mold, rmax);
            float sum = 0.0f;
            #pragma unroll
            for (int j = 0; j < 4; j++) {
                p[j] = __expf(p[j] - mnew);
                sum += p[j];
                sS[qr * SSTR + tx + 16 * j] = p[j];
            }
            #pragma unroll
            for (int o = 8; o > 0; o >>= 1)
                sum += __shfl_xor_sync(0xffffffffu, sum, o, 16);
            if (tx == 0) {
                float al = __expf(mold - mnew);
                mrow[qr] = mnew;
                arow[qr] = al;
                lrow[qr] = lrow[qr] * al + sum;
            }
        }
        __syncthreads();

        // V tile (overwrites sKV)
        for (int idx = tid; idx < TK * HDc / 4; idx += 256) {
            int kk = idx >> 5, d4 = (idx & 31) * 4;
            *(float4*)(&sKV[kk * VSTR + d4]) = *(const float4*)(Vg + (size_t)(k0 + kk) * HDc + d4);
        }
        __syncthreads();

        // rescale O, then PV
        #pragma unroll
        for (int i = 0; i < 8; i++) {
            float al = arow[warp * 8 + i];
            #pragma unroll
            for (int t = 0; t < 4; t++) oacc[i][t] *= al;
        }
        #pragma unroll 2
        for (int kk = 0; kk < TK; kk++) {
            float4 vv = *(const float4*)(&sKV[kk * VSTR + lane * 4]);
            #pragma unroll
            for (int i = 0; i < 8; i++) {
                float p = sS[(warp * 8 + i) * SSTR + kk];
                oacc[i][0] += p * vv.x;
                oacc[i][1] += p * vv.y;
                oacc[i][2] += p * vv.z;
                oacc[i][3] += p * vv.w;
            }
        }
    }

    // epilogue
    #pragma unroll
    for (int i = 0; i < 8; i++) {
        int r = warp * 8 + i;
        float inv = 1.0f / lrow[r];
        float* orow = out + ((size_t)b * Sc + (q0 + r)) * Dc + h * HDc;
        float4 o = {oacc[i][0] * inv, oacc[i][1] * inv, oacc[i][2] * inv, oacc[i][3] * inv};
        *(float4*)(orow + lane * 4) = o;
    }
}

// ------------------------------------------------------------------
extern "C" void kernel_launch(void* const* d_in, const int* in_sizes, int n_in,
                              void* d_out, int out_size)
{
    const float* q  = (const float*)d_in[0];
    const float* k  = (const float*)d_in[1];
    const float* v  = (const float*)d_in[2];
    const unsigned int* mask = (const unsigned int*)d_in[3];
    const float* Wq = (const float*)d_in[4];
    const float* bq = (const float*)d_in[5];
    const float* Wk = (const float*)d_in[6];
    const float* bk = (const float*)d_in[7];
    const float* Wv = (const float*)d_in[8];
    const float* bv = (const float*)d_in[9];
    float* out = (float*)d_out;

    dim3 pgrid(Dc / BN, Mc / BM, 3);
    proj_kernel<<<pgrid, 256>>>(q, k, v, Wq, bq, Wk, bk, Wv, bv);

    cudaFuncSetAttribute(attn_kernel,
                         cudaFuncAttributeMaxDynamicSharedMemorySize,
                         ATTN_SMEM_BYTES);
    dim3 agrid(Sc / TQ, Bc * Hc);
    attn_kernel<<<agrid, 256, ATTN_SMEM_BYTES>>>(mask, out);
}

// round 5
// speedup vs baseline: 3.3071x; 2.6780x over previous
#include <cuda_runtime.h>
#include <math.h>

#define Bc 2
#define Sc 2048
#define Dc 1024
#define Hc 8
#define HDc 128
#define Mc (Bc*Sc)   // 4096

// scratch: [B,H,S,HD] fp32 (tf32-rounded values)
__device__ float g_Q[Bc*Hc*Sc*HDc];
__device__ float g_K[Bc*Hc*Sc*HDc];
__device__ float g_V[Bc*Hc*Sc*HDc];

__device__ __forceinline__ unsigned f2tf(float x) {
    unsigned u;
    asm("cvt.rna.tf32.f32 %0, %1;" : "=r"(u) : "f"(x));
    return u;
}

__device__ __forceinline__ void mma8(float* c,
    unsigned a0, unsigned a1, unsigned a2, unsigned a3,
    unsigned b0, unsigned b1)
{
    asm volatile(
        "mma.sync.aligned.m16n8k8.row.col.f32.tf32.tf32.f32 "
        "{%0,%1,%2,%3}, {%4,%5,%6,%7}, {%8,%9}, {%0,%1,%2,%3};"
        : "+f"(c[0]), "+f"(c[1]), "+f"(c[2]), "+f"(c[3])
        : "r"(a0), "r"(a1), "r"(a2), "r"(a3), "r"(b0), "r"(b1));
}

// ------------------------------------------------------------------
// Projection GEMM (tf32 MMA): 128x128 tile, BK=32, 8 warps x (32x64)
// ------------------------------------------------------------------
#define PASTR 36    // 4g+t bank pattern
#define PBSTR 136   // 8t+g bank pattern

__global__ __launch_bounds__(256, 2) void proj_kernel(
    const float* __restrict__ q, const float* __restrict__ k, const float* __restrict__ v,
    const float* __restrict__ Wq, const float* __restrict__ bq,
    const float* __restrict__ Wk, const float* __restrict__ bk,
    const float* __restrict__ Wv, const float* __restrict__ bv)
{
    const float* A; const float* W; const float* bias; float* out;
    if (blockIdx.z == 0)      { A = q; W = Wq; bias = bq; out = g_Q; }
    else if (blockIdx.z == 1) { A = k; W = Wk; bias = bk; out = g_K; }
    else                      { A = v; W = Wv; bias = bv; out = g_V; }

    __shared__ float As[128 * PASTR];   // row-major [m][k], tf32
    __shared__ float Bs[32 * PBSTR];    // row-major [k][n], tf32

    const int tid  = threadIdx.x;
    const int warp = tid >> 5;
    const int lane = tid & 31;
    const int g    = lane >> 2;
    const int t    = lane & 3;

    const int m0 = blockIdx.y * 128;
    const int n0 = blockIdx.x * 128;
    const int wm = (warp & 3) * 32;
    const int wn = (warp >> 2) * 64;

    float C[2][8][4] = {};

    for (int k0 = 0; k0 < Dc; k0 += 32) {
        __syncthreads();
        #pragma unroll
        for (int i = 0; i < 4; i++) {
            int idx = tid + 256 * i;
            int ar = idx >> 3, ac = (idx & 7) << 2;
            float4 av = *(const float4*)(A + (size_t)(m0 + ar) * Dc + k0 + ac);
            As[ar * PASTR + ac + 0] = __uint_as_float(f2tf(av.x));
            As[ar * PASTR + ac + 1] = __uint_as_float(f2tf(av.y));
            As[ar * PASTR + ac + 2] = __uint_as_float(f2tf(av.z));
            As[ar * PASTR + ac + 3] = __uint_as_float(f2tf(av.w));
            int br = idx >> 5, bc = (idx & 31) << 2;
            float4 wv = *(const float4*)(W + (size_t)(k0 + br) * Dc + n0 + bc);
            Bs[br * PBSTR + bc + 0] = __uint_as_float(f2tf(wv.x));
            Bs[br * PBSTR + bc + 1] = __uint_as_float(f2tf(wv.y));
            Bs[br * PBSTR + bc + 2] = __uint_as_float(f2tf(wv.z));
            Bs[br * PBSTR + bc + 3] = __uint_as_float(f2tf(wv.w));
        }
        __syncthreads();

        #pragma unroll
        for (int ks = 0; ks < 4; ks++) {
            unsigned a[2][4];
            #pragma unroll
            for (int mi = 0; mi < 2; mi++) {
                int ab = (wm + mi * 16 + g) * PASTR + ks * 8 + t;
                a[mi][0] = __float_as_uint(As[ab]);
                a[mi][1] = __float_as_uint(As[ab + 8 * PASTR]);
                a[mi][2] = __float_as_uint(As[ab + 4]);
                a[mi][3] = __float_as_uint(As[ab + 8 * PASTR + 4]);
            }
            #pragma unroll
            for (int ni = 0; ni < 8; ni++) {
                int bb = (ks * 8 + t) * PBSTR + wn + ni * 8 + g;
                unsigned b0 = __float_as_uint(Bs[bb]);
                unsigned b1 = __float_as_uint(Bs[bb + 4 * PBSTR]);
                mma8(C[0][ni], a[0][0], a[0][1], a[0][2], a[0][3], b0, b1);
                mma8(C[1][ni], a[1][0], a[1][1], a[1][2], a[1][3], b0, b1);
            }
        }
    }

    // epilogue: bias, tf32-round, scatter to [B,H,S,HD]
    const int h = blockIdx.x;  // n0/128
    #pragma unroll
    for (int mi = 0; mi < 2; mi++) {
        int row0 = m0 + wm + mi * 16 + g;
        #pragma unroll
        for (int ni = 0; ni < 8; ni++) {
            int col = wn + ni * 8 + 2 * t;
            float b0v = bias[n0 + col], b1v = bias[n0 + col + 1];
            int r0 = row0;
            int bb0 = r0 >> 11, s0 = r0 & (Sc - 1);
            float* d0 = out + (((size_t)(bb0 * Hc + h)) * Sc + s0) * HDc + col;
            float2 o0 = {__uint_as_float(f2tf(C[mi][ni][0] + b0v)),
                         __uint_as_float(f2tf(C[mi][ni][1] + b1v))};
            *(float2*)d0 = o0;
            int r1 = row0 + 8;
            int bb1 = r1 >> 11, s1 = r1 & (Sc - 1);
            float* d1 = out + (((size_t)(bb1 * Hc + h)) * Sc + s1) * HDc + col;
            float2 o1 = {__uint_as_float(f2tf(C[mi][ni][2] + b0v)),
                         __uint_as_float(f2tf(C[mi][ni][3] + b1v))};
            *(float2*)d1 = o1;
        }
    }
}

// ------------------------------------------------------------------
// Flash attention with tf32 MMA. 64 q-rows, 64-key tiles, 8 warps.
// QK: warp = rows (w&3)*16, cols (w>>2)*32 (4 n8-tiles)
// PV: warp = rows (w&3)*16, dcols (w>>2)*64 (8 n8-tiles)
// ------------------------------------------------------------------
#define QSTR 132
#define KSTR 132
#define VSTR 136
#define SSTR 68

#define SM_Q   0
#define SM_KV  (64 * QSTR)
#define SM_S   (SM_KV + 64 * VSTR)
#define SM_M   (SM_S + 64 * SSTR)
#define SM_L   (SM_M + 64)
#define SM_A   (SM_L + 64)
#define ATTN_SMEM_FLOATS (SM_A + 64)
#define ATTN_SMEM_BYTES  (ATTN_SMEM_FLOATS * 4)

__global__ __launch_bounds__(256, 2) void attn_kernel(
    const unsigned int* __restrict__ mask, float* __restrict__ out)
{
    extern __shared__ float smem[];
    float* sQ   = smem + SM_Q;
    float* sKV  = smem + SM_KV;
    float* sS   = smem + SM_S;
    float* mrow = smem + SM_M;
    float* lrow = smem + SM_L;
    float* arow = smem + SM_A;

    const int tid  = threadIdx.x;
    const int warp = tid >> 5;
    const int lane = tid & 31;
    const int g    = lane >> 2;
    const int t    = lane & 3;

    const int bh = blockIdx.y;
    const int b  = bh >> 3;
    const int h  = bh & (Hc - 1);
    const int q0 = blockIdx.x * 64;

    const int qr0 = (warp & 3) * 16;   // row base (QK and PV)
    const int kn0 = (warp >> 2) * 32;  // QK col base
    const int vd0 = (warp >> 2) * 64;  // PV dcol base

    const float* Qg = g_Q + (size_t)bh * Sc * HDc;
    const float* Kg = g_K + (size_t)bh * Sc * HDc;
    const float* Vg = g_V + (size_t)bh * Sc * HDc;
    const unsigned int* maskb = mask + (size_t)b * Sc * Sc;

    // Q tile (already tf32-rounded in proj)
    #pragma unroll
    for (int i = 0; i < 8; i++) {
        int idx = tid + 256 * i;
        int r = idx >> 5, d = (idx & 31) << 2;
        *(float4*)(&sQ[r * QSTR + d]) = *(const float4*)(Qg + (size_t)(q0 + r) * HDc + d);
    }
    if (tid < 64) { mrow[tid] = -1e30f; lrow[tid] = 0.0f; }

    float O[8][4] = {};
    const float scale = 0.08838834764831845f;  // 1/sqrt(128)

    for (int kt = 0; kt < Sc / 64; kt++) {
        const int k0 = kt * 64;
        __syncthreads();   // protect sKV from prior PV reads

        // K tile
        #pragma unroll
        for (int i = 0; i < 8; i++) {
            int idx = tid + 256 * i;
            int r = idx >> 5, d = (idx & 31) << 2;
            *(float4*)(&sKV[r * KSTR + d]) = *(const float4*)(Kg + (size_t)(k0 + r) * HDc + d);
        }
        __syncthreads();

        // QK^T: S[16 x 32] per warp via m16n8k8 tf32
        float S[4][4] = {};
        #pragma unroll
        for (int ks = 0; ks < 16; ks++) {
            int ab = (qr0 + g) * QSTR + ks * 8 + t;
            unsigned a0 = __float_as_uint(sQ[ab]);
            unsigned a1 = __float_as_uint(sQ[ab + 8 * QSTR]);
            unsigned a2 = __float_as_uint(sQ[ab + 4]);
            unsigned a3 = __float_as_uint(sQ[ab + 8 * QSTR + 4]);
            #pragma unroll
            for (int ni = 0; ni < 4; ni++) {
                int bb = (kn0 + ni * 8 + g) * KSTR + ks * 8 + t;
                unsigned b0 = __float_as_uint(sKV[bb]);
                unsigned b1 = __float_as_uint(sKV[bb + 4]);
                mma8(S[ni], a0, a1, a2, a3, b0, b1);
            }
        }
        // store raw S to sS
        #pragma unroll
        for (int ni = 0; ni < 4; ni++) {
            int col = kn0 + ni * 8 + 2 * t;
            *(float2*)(&sS[(qr0 + g) * SSTR + col])     = make_float2(S[ni][0], S[ni][1]);
            *(float2*)(&sS[(qr0 + g + 8) * SSTR + col]) = make_float2(S[ni][2], S[ni][3]);
        }
        __syncthreads();

        // V tile (overwrites K region)
        #pragma unroll
        for (int i = 0; i < 8; i++) {
            int idx = tid + 256 * i;
            int r = idx >> 5, d = (idx & 31) << 2;
            *(float4*)(&sKV[r * VSTR + d]) = *(const float4*)(Vg + (size_t)(k0 + r) * HDc + d);
        }

        // softmax: row = tid>>2, 4 lanes per row, 16 cols each
        {
            int r  = tid >> 2;
            int qt = tid & 3;
            float* srow = &sS[r * SSTR + qt * 16];
            const uint4* mr4 = (const uint4*)(maskb + (size_t)(q0 + r) * Sc + k0 + qt * 16);
            float p[16];
            float rmax = -1e30f;
            #pragma unroll
            for (int j = 0; j < 4; j++) {
                float4 sv = *(const float4*)(&srow[4 * j]);
                uint4  mv = mr4[j];
                p[4*j+0] = (mv.x ? -1e6f : sv.x) * scale;
                p[4*j+1] = (mv.y ? -1e6f : sv.y) * scale;
                p[4*j+2] = (mv.z ? -1e6f : sv.z) * scale;
                p[4*j+3] = (mv.w ? -1e6f : sv.w) * scale;
                #pragma unroll
                for (int e = 0; e < 4; e++) rmax = fmaxf(rmax, p[4*j+e]);
            }
            rmax = fmaxf(rmax, __shfl_xor_sync(0xffffffffu, rmax, 1));
            rmax = fmaxf(rmax, __shfl_xor_sync(0xffffffffu, rmax, 2));
            float mold = mrow[r];
            float mnew = fmaxf(mold, rmax);
            float sum = 0.0f;
            #pragma unroll
            for (int j = 0; j < 4; j++) {
                float4 pv;
                pv.x = __uint_as_float(f2tf(__expf(p[4*j+0] - mnew)));
                pv.y = __uint_as_float(f2tf(__expf(p[4*j+1] - mnew)));
                pv.z = __uint_as_float(f2tf(__expf(p[4*j+2] - mnew)));
                pv.w = __uint_as_float(f2tf(__expf(p[4*j+3] - mnew)));
                sum += pv.x + pv.y + pv.z + pv.w;
                *(float4*)(&srow[4 * j]) = pv;
            }
            sum += __shfl_xor_sync(0xffffffffu, sum, 1);
            sum += __shfl_xor_sync(0xffffffffu, sum, 2);
            if (qt == 0) {
                float al = __expf(mold - mnew);
                mrow[r] = mnew;
                arow[r] = al;
                lrow[r] = lrow[r] * al + sum;
            }
        }
        __syncthreads();

        // rescale O, then PV: ctx[16 x 64] per warp
        {
            float al0 = arow[qr0 + g];
            float al1 = arow[qr0 + g + 8];
            #pragma unroll
            for (int ni = 0; ni < 8; ni++) {
                O[ni][0] *= al0; O[ni][1] *= al0;
                O[ni][2] *= al1; O[ni][3] *= al1;
            }
        }
        #pragma unroll
        for (int ks = 0; ks < 8; ks++) {
            int ab = (qr0 + g) * SSTR + ks * 8 + t;
            unsigned a0 = __float_as_uint(sS[ab]);
            unsigned a1 = __float_as_uint(sS[ab + 8 * SSTR]);
            unsigned a2 = __float_as_uint(sS[ab + 4]);
            unsigned a3 = __float_as_uint(sS[ab + 8 * SSTR + 4]);
            #pragma unroll
            for (int ni = 0; ni < 8; ni++) {
                int bb = (ks * 8 + t) * VSTR + vd0 + ni * 8 + g;
                unsigned b0 = __float_as_uint(sKV[bb]);
                unsigned b1 = __float_as_uint(sKV[bb + 4 * VSTR]);
                mma8(O[ni], a0, a1, a2, a3, b0, b1);
            }
        }
    }

    // epilogue: normalize by l, write [B,S,D]
    {
        float linv0 = 1.0f / lrow[qr0 + g];
        float linv1 = 1.0f / lrow[qr0 + g + 8];
        int row0 = q0 + qr0 + g;
        #pragma unroll
        for (int ni = 0; ni < 8; ni++) {
            int col = vd0 + ni * 8 + 2 * t;
            float* d0 = out + ((size_t)b * Sc + row0) * Dc + h * HDc + col;
            *(float2*)d0 = make_float2(O[ni][0] * linv0, O[ni][1] * linv0);
            float* d1 = out + ((size_t)b * Sc + row0 + 8) * Dc + h * HDc + col;
            *(float2*)d1 = make_float2(O[ni][2] * linv1, O[ni][3] * linv1);
        }
    }
}

// ------------------------------------------------------------------
extern "C" void kernel_launch(void* const* d_in, const int* in_sizes, int n_in,
                              void* d_out, int out_size)
{
    const float* q  = (const float*)d_in[0];
    const float* k  = (const float*)d_in[1];
    const float* v  = (const float*)d_in[2];
    const unsigned int* mask = (const unsigned int*)d_in[3];
    const float* Wq = (const float*)d_in[4];
    const float* bq = (const float*)d_in[5];
    const float* Wk = (const float*)d_in[6];
    const float* bk = (const float*)d_in[7];
    const float* Wv = (const float*)d_in[8];
    const float* bv = (const float*)d_in[9];
    float* out = (float*)d_out;

    dim3 pgrid(Dc / 128, Mc / 128, 3);
    proj_kernel<<<pgrid, 256>>>(q, k, v, Wq, bq, Wk, bk, Wv, bv);

    cudaFuncSetAttribute(attn_kernel,
                         cudaFuncAttributeMaxDynamicSharedMemorySize,
                         ATTN_SMEM_BYTES);
    dim3 agrid(Sc / 64, Bc * Hc);
    attn_kernel<<<agrid, 256, ATTN_SMEM_BYTES>>>(mask, out);
}

// round 6
// speedup vs baseline: 3.3771x; 1.0212x over previous
#include <cuda_runtime.h>
#include <math.h>

#define Bc 2
#define Sc 2048
#define Dc 1024
#define Hc 8
#define HDc 128
#define Mc (Bc*Sc)   // 4096

// scratch (tf32-rounded fp32): Q,K as [B,H,S,HD]; V as [B,H,HD,S] (transposed!)
__device__ float g_Q[Bc*Hc*Sc*HDc];
__device__ float g_K[Bc*Hc*Sc*HDc];
__device__ float g_V[Bc*Hc*Sc*HDc];

__device__ __forceinline__ unsigned f2tf(float x) {
    unsigned u;
    asm("cvt.rna.tf32.f32 %0, %1;" : "=r"(u) : "f"(x));
    return u;
}

__device__ __forceinline__ void mma8(float* c,
    unsigned a0, unsigned a1, unsigned a2, unsigned a3,
    unsigned b0, unsigned b1)
{
    asm volatile(
        "mma.sync.aligned.m16n8k8.row.col.f32.tf32.tf32.f32 "
        "{%0,%1,%2,%3}, {%4,%5,%6,%7}, {%8,%9}, {%0,%1,%2,%3};"
        : "+f"(c[0]), "+f"(c[1]), "+f"(c[2]), "+f"(c[3])
        : "r"(a0), "r"(a1), "r"(a2), "r"(a3), "r"(b0), "r"(b1));
}

__device__ __forceinline__ void ldsm4(unsigned& r0, unsigned& r1, unsigned& r2, unsigned& r3,
                                      unsigned addr)
{
    asm volatile("ldmatrix.sync.aligned.m8n8.x4.shared.b16 {%0,%1,%2,%3}, [%4];"
        : "=r"(r0), "=r"(r1), "=r"(r2), "=r"(r3) : "r"(addr));
}

// ------------------------------------------------------------------
// Projection GEMM (tf32 MMA): 128x128 tile, BK=32, 8 warps x (32x64)
// A fragments via ldmatrix; V output stored transposed [B,H,HD,S].
// ------------------------------------------------------------------
#define PASTR 36
#define PBSTR 136

__global__ __launch_bounds__(256, 2) void proj_kernel(
    const float* __restrict__ q, const float* __restrict__ k, const float* __restrict__ v,
    const float* __restrict__ Wq, const float* __restrict__ bq,
    const float* __restrict__ Wk, const float* __restrict__ bk,
    const float* __restrict__ Wv, const float* __restrict__ bv)
{
    const float* A; const float* W; const float* bias; float* out;
    if (blockIdx.z == 0)      { A = q; W = Wq; bias = bq; out = g_Q; }
    else if (blockIdx.z == 1) { A = k; W = Wk; bias = bk; out = g_K; }
    else                      { A = v; W = Wv; bias = bv; out = g_V; }

    __shared__ float As[128 * PASTR];   // [m][k] tf32
    __shared__ float Bs[32 * PBSTR];    // [k][n] tf32

    const int tid  = threadIdx.x;
    const int warp = tid >> 5;
    const int lane = tid & 31;
    const int g    = lane >> 2;
    const int t    = lane & 3;

    const int m0 = blockIdx.y * 128;
    const int n0 = blockIdx.x * 128;
    const int wm = (warp & 3) * 32;
    const int wn = (warp >> 2) * 64;

    const unsigned aBase = (unsigned)__cvta_generic_to_shared(As)
        + (((wm + (lane & 7) + ((lane >> 3) & 1) * 8) * PASTR + (lane >> 4) * 4) << 2);

    float C[2][8][4] = {};

    for (int k0 = 0; k0 < Dc; k0 += 32) {
        __syncthreads();
        #pragma unroll
        for (int i = 0; i < 4; i++) {
            int idx = tid + 256 * i;
            int ar = idx >> 3, ac = (idx & 7) << 2;
            float4 av = *(const float4*)(A + (size_t)(m0 + ar) * Dc + k0 + ac);
            As[ar * PASTR + ac + 0] = __uint_as_float(f2tf(av.x));
            As[ar * PASTR + ac + 1] = __uint_as_float(f2tf(av.y));
            As[ar * PASTR + ac + 2] = __uint_as_float(f2tf(av.z));
            As[ar * PASTR + ac + 3] = __uint_as_float(f2tf(av.w));
            int br = idx >> 5, bc = (idx & 31) << 2;
            float4 wv = *(const float4*)(W + (size_t)(k0 + br) * Dc + n0 + bc);
            Bs[br * PBSTR + bc + 0] = __uint_as_float(f2tf(wv.x));
            Bs[br * PBSTR + bc + 1] = __uint_as_float(f2tf(wv.y));
            Bs[br * PBSTR + bc + 2] = __uint_as_float(f2tf(wv.z));
            Bs[br * PBSTR + bc + 3] = __uint_as_float(f2tf(wv.w));
        }
        __syncthreads();

        #pragma unroll
        for (int ks = 0; ks < 4; ks++) {
            unsigned a[2][4];
            #pragma unroll
            for (int mi = 0; mi < 2; mi++)
                ldsm4(a[mi][0], a[mi][1], a[mi][2], a[mi][3],
                      aBase + (unsigned)((mi * 16 * PASTR + ks * 8) << 2));
            #pragma unroll
            for (int ni = 0; ni < 8; ni++) {
                int bb = (ks * 8 + t) * PBSTR + wn + ni * 8 + g;
                unsigned b0 = __float_as_uint(Bs[bb]);
                unsigned b1 = __float_as_uint(Bs[bb + 4 * PBSTR]);
                mma8(C[0][ni], a[0][0], a[0][1], a[0][2], a[0][3], b0, b1);
                mma8(C[1][ni], a[1][0], a[1][1], a[1][2], a[1][3], b0, b1);
            }
        }
    }

    const int h = blockIdx.x;
    if (blockIdx.z != 2) {
        // Q/K: [B,H,S,HD]
        #pragma unroll
        for (int mi = 0; mi < 2; mi++) {
            int row0 = m0 + wm + mi * 16 + g;
            #pragma unroll
            for (int ni = 0; ni < 8; ni++) {
                int col = wn + ni * 8 + 2 * t;
                float b0v = bias[n0 + col], b1v = bias[n0 + col + 1];
                int bb0 = row0 >> 11, s0 = row0 & (Sc - 1);
                float* d0 = out + (((size_t)(bb0 * Hc + h)) * Sc + s0) * HDc + col;
                *(float2*)d0 = make_float2(__uint_as_float(f2tf(C[mi][ni][0] + b0v)),
                                           __uint_as_float(f2tf(C[mi][ni][1] + b1v)));
                int r1 = row0 + 8;
                int bb1 = r1 >> 11, s1 = r1 & (Sc - 1);
                float* d1 = out + (((size_t)(bb1 * Hc + h)) * Sc + s1) * HDc + col;
                *(float2*)d1 = make_float2(__uint_as_float(f2tf(C[mi][ni][2] + b0v)),
                                           __uint_as_float(f2tf(C[mi][ni][3] + b1v)));
            }
        }
    } else {
        // V: [B,H,HD,S]
        #pragma unroll
        for (int mi = 0; mi < 2; mi++) {
            int row0 = m0 + wm + mi * 16 + g;
            #pragma unroll
            for (int ni = 0; ni < 8; ni++) {
                int col = wn + ni * 8 + 2 * t;
                float b0v = bias[n0 + col], b1v = bias[n0 + col + 1];
                int bb0 = row0 >> 11, s0 = row0 & (Sc - 1);
                float* base0 = out + ((size_t)(bb0 * Hc + h)) * HDc * Sc;
                base0[(size_t)col * Sc + s0]       = __uint_as_float(f2tf(C[mi][ni][0] + b0v));
                base0[(size_t)(col + 1) * Sc + s0] = __uint_as_float(f2tf(C[mi][ni][1] + b1v));
                int r1 = row0 + 8;
                int bb1 = r1 >> 11, s1 = r1 & (Sc - 1);
                float* base1 = out + ((size_t)(bb1 * Hc + h)) * HDc * Sc;
                base1[(size_t)col * Sc + s1]       = __uint_as_float(f2tf(C[mi][ni][2] + b0v));
                base1[(size_t)(col + 1) * Sc + s1] = __uint_as_float(f2tf(C[mi][ni][3] + b1v));
            }
        }
    }
}

// ------------------------------------------------------------------
// Flash attention, tf32 MMA + ldmatrix fragment feeds.
// 64 q-rows, 64-key tiles, 8 warps: QK warp tile 16x32, PV 16x64.
// sVT holds V transposed [d][key].
// ------------------------------------------------------------------
#define QSTR  132
#define KSTR  132
#define VTSTR 68
#define SSTR  68

#define SM_Q   0
#define SM_KV  (64 * QSTR)             // K tile 64*132=8448 or VT tile 128*68=8704
#define SM_S   (SM_KV + 128 * VTSTR)
#define SM_M   (SM_S + 64 * SSTR)
#define SM_L   (SM_M + 64)
#define SM_A   (SM_L + 64)
#define ATTN_SMEM_FLOATS (SM_A + 64)
#define ATTN_SMEM_BYTES  (ATTN_SMEM_FLOATS * 4)

__global__ __launch_bounds__(256, 2) void attn_kernel(
    const unsigned int* __restrict__ mask, float* __restrict__ out)
{
    extern __shared__ float smem[];
    float* sQ   = smem + SM_Q;
    float* sKV  = smem + SM_KV;
    float* sS   = smem + SM_S;
    float* mrow = smem + SM_M;
    float* lrow = smem + SM_L;
    float* arow = smem + SM_A;

    const int tid  = threadIdx.x;
    const int warp = tid >> 5;
    const int lane = tid & 31;
    const int g    = lane >> 2;
    const int t    = lane & 3;

    const int bh = blockIdx.y;
    const int b  = bh >> 3;
    const int h  = bh & (Hc - 1);
    const int q0 = blockIdx.x * 64;

    const int qr0 = (warp & 3) * 16;
    const int kn0 = (warp >> 2) * 32;
    const int vd0 = (warp >> 2) * 64;

    const float* Qg = g_Q + (size_t)bh * Sc * HDc;
    const float* Kg = g_K + (size_t)bh * Sc * HDc;
    const float* Vg = g_V + (size_t)bh * HDc * Sc;   // [HD][S]
    const unsigned int* maskb = mask + (size_t)b * Sc * Sc;

    const unsigned sbase = (unsigned)__cvta_generic_to_shared(smem);
    // ldmatrix lane-address bases (bytes)
    const unsigned aQ = sbase + ((SM_Q  + (qr0 + (lane & 7) + ((lane >> 3) & 1) * 8) * QSTR  + (lane >> 4) * 4) << 2);
    const unsigned bK = sbase + ((SM_KV + (kn0 + ((lane >> 4) & 1) * 8 + (lane & 7)) * KSTR  + ((lane >> 3) & 1) * 4) << 2);
    const unsigned aS = sbase + ((SM_S  + (qr0 + (lane & 7) + ((lane >> 3) & 1) * 8) * SSTR  + (lane >> 4) * 4) << 2);
    const unsigned bV = sbase + ((SM_KV + (vd0 + ((lane >> 4) & 1) * 8 + (lane & 7)) * VTSTR + ((lane >> 3) & 1) * 4) << 2);

    // Q tile
    #pragma unroll
    for (int i = 0; i < 8; i++) {
        int idx = tid + 256 * i;
        int r = idx >> 5, d = (idx & 31) << 2;
        *(float4*)(&sQ[r * QSTR + d]) = *(const float4*)(Qg + (size_t)(q0 + r) * HDc + d);
    }
    if (tid < 64) { mrow[tid] = -1e30f; lrow[tid] = 0.0f; }

    float O[8][4] = {};
    const float scale = 0.08838834764831845f;  // 1/sqrt(128)

    for (int kt = 0; kt < Sc / 64; kt++) {
        const int k0 = kt * 64;
        __syncthreads();

        // K tile [key][d]
        #pragma unroll
        for (int i = 0; i < 8; i++) {
            int idx = tid + 256 * i;
            int r = idx >> 5, d = (idx & 31) << 2;
            *(float4*)(&sKV[r * KSTR + d]) = *(const float4*)(Kg + (size_t)(k0 + r) * HDc + d);
        }
        __syncthreads();

        // QK^T via ldmatrix-fed m16n8k8
        float S[4][4] = {};
        #pragma unroll
        for (int ks = 0; ks < 16; ks++) {
            unsigned a0, a1, a2, a3;
            ldsm4(a0, a1, a2, a3, aQ + (unsigned)(ks * 32));
            #pragma unroll
            for (int nii = 0; nii < 2; nii++) {
                unsigned b0, b1, b2, b3;
                ldsm4(b0, b1, b2, b3, bK + (unsigned)(((nii * 16 * KSTR) << 2) + ks * 32));
                mma8(S[nii * 2],     a0, a1, a2, a3, b0, b1);
                mma8(S[nii * 2 + 1], a0, a1, a2, a3, b2, b3);
            }
        }
        #pragma unroll
        for (int ni = 0; ni < 4; ni++) {
            int col = kn0 + ni * 8 + 2 * t;
            *(float2*)(&sS[(qr0 + g) * SSTR + col])     = make_float2(S[ni][0], S[ni][1]);
            *(float2*)(&sS[(qr0 + g + 8) * SSTR + col]) = make_float2(S[ni][2], S[ni][3]);
        }
        __syncthreads();

        // V^T tile [d][key] (overwrites K region)
        #pragma unroll
        for (int i = 0; i < 8; i++) {
            int idx = tid + 256 * i;            // 128 d-rows x 16 float4
            int d = idx >> 4, c4 = (idx & 15) << 2;
            *(float4*)(&sKV[d * VTSTR + c4]) = *(const float4*)(Vg + (size_t)d * Sc + k0 + c4);
        }

        // softmax: row = tid>>2, 4 lanes/row
        {
            int r  = tid >> 2;
            int qt = tid & 3;
            float* srow = &sS[r * SSTR + qt * 16];
            const uint4* mr4 = (const uint4*)(maskb + (size_t)(q0 + r) * Sc + k0 + qt * 16);
            float p[16];
            float rmax = -1e30f;
            #pragma unroll
            for (int j = 0; j < 4; j++) {
                float4 sv = *(const float4*)(&srow[4 * j]);
                uint4  mv = mr4[j];
                p[4*j+0] = (mv.x ? -1e6f : sv.x) * scale;
                p[4*j+1] = (mv.y ? -1e6f : sv.y) * scale;
                p[4*j+2] = (mv.z ? -1e6f : sv.z) * scale;
                p[4*j+3] = (mv.w ? -1e6f : sv.w) * scale;
                #pragma unroll
                for (int e = 0; e < 4; e++) rmax = fmaxf(rmax, p[4*j+e]);
            }
            rmax = fmaxf(rmax, __shfl_xor_sync(0xffffffffu, rmax, 1));
            rmax = fmaxf(rmax, __shfl_xor_sync(0xffffffffu, rmax, 2));
            float mold = mrow[r];
            float mnew = fmaxf(mold, rmax);
            float sum = 0.0f;
            #pragma unroll
            for (int j = 0; j < 4; j++) {
                float4 pv;
                pv.x = __uint_as_float(f2tf(__expf(p[4*j+0] - mnew)));
                pv.y = __uint_as_float(f2tf(__expf(p[4*j+1] - mnew)));
                pv.z = __uint_as_float(f2tf(__expf(p[4*j+2] - mnew)));
                pv.w = __uint_as_float(f2tf(__expf(p[4*j+3] - mnew)));
                sum += pv.x + pv.y + pv.z + pv.w;
                *(float4*)(&srow[4 * j]) = pv;
            }
            sum += __shfl_xor_sync(0xffffffffu, sum, 1);
            sum += __shfl_xor_sync(0xffffffffu, sum, 2);
            if (qt == 0) {
                float al = __expf(mold - mnew);
                mrow[r] = mnew;
                arow[r] = al;
                lrow[r] = lrow[r] * al + sum;
            }
        }
        __syncthreads();

        // rescale O, then PV via ldmatrix-fed MMA
        {
            float al0 = arow[qr0 + g];
            float al1 = arow[qr0 + g + 8];
            #pragma unroll
            for (int ni = 0; ni < 8; ni++) {
                O[ni][0] *= al0; O[ni][1] *= al0;
                O[ni][2] *= al1; O[ni][3] *= al1;
            }
        }
        #pragma unroll
        for (int ks = 0; ks < 8; ks++) {
            unsigned a0, a1, a2, a3;
            ldsm4(a0, a1, a2, a3, aS + (unsigned)(ks * 32));
            #pragma unroll
            for (int nii = 0; nii < 4; nii++) {
                unsigned b0, b1, b2, b3;
                ldsm4(b0, b1, b2, b3, bV + (unsigned)(((nii * 16 * VTSTR) << 2) + ks * 32));
                mma8(O[nii * 2],     a0, a1, a2, a3, b0, b1);
                mma8(O[nii * 2 + 1], a0, a1, a2, a3, b2, b3);
            }
        }
    }

    // epilogue
    {
        float linv0 = 1.0f / lrow[qr0 + g];
        float linv1 = 1.0f / lrow[qr0 + g + 8];
        int row0 = q0 + qr0 + g;
        #pragma unroll
        for (int ni = 0; ni < 8; ni++) {
            int col = vd0 + ni * 8 + 2 * t;
            float* d0 = out + ((size_t)b * Sc + row0) * Dc + h * HDc + col;
            *(float2*)d0 = make_float2(O[ni][0] * linv0, O[ni][1] * linv0);
            float* d1 = out + ((size_t)b * Sc + row0 + 8) * Dc + h * HDc + col;
            *(float2*)d1 = make_float2(O[ni][2] * linv1, O[ni][3] * linv1);
        }
    }
}

// ------------------------------------------------------------------
extern "C" void kernel_launch(void* const* d_in, const int* in_sizes, int n_in,
                              void* d_out, int out_size)
{
    const float* q  = (const float*)d_in[0];
    const float* k  = (const float*)d_in[1];
    const float* v  = (const float*)d_in[2];
    const unsigned int* mask = (const unsigned int*)d_in[3];
    const float* Wq = (const float*)d_in[4];
    const float* bq = (const float*)d_in[5];
    const float* Wk = (const float*)d_in[6];
    const float* bk = (const float*)d_in[7];
    const float* Wv = (const float*)d_in[8];
    const float* bv = (const float*)d_in[9];
    float* out = (float*)d_out;

    dim3 pgrid(Dc / 128, Mc / 128, 3);
    proj_kernel<<<pgrid, 256>>>(q, k, v, Wq, bq, Wk, bk, Wv, bv);

    cudaFuncSetAttribute(attn_kernel,
                         cudaFuncAttributeMaxDynamicSharedMemorySize,
                         ATTN_SMEM_BYTES);
    dim3 agrid(Sc / 64, Bc * Hc);
    attn_kernel<<<agrid, 256, ATTN_SMEM_BYTES>>>(mask, out);
}

// round 7
// speedup vs baseline: 3.5170x; 1.0414x over previous
#include <cuda_runtime.h>
#include <math.h>

#define Bc 2
#define Sc 2048
#define Dc 1024
#define Hc 8
#define HDc 128
#define Mc (Bc*Sc)   // 4096

// scratch (tf32-rounded fp32): Q,K as [B,H,S,HD]; V as [B,H,HD,S] (transposed)
__device__ float g_Q[Bc*Hc*Sc*HDc];
__device__ float g_K[Bc*Hc*Sc*HDc];
__device__ float g_V[Bc*Hc*Sc*HDc];

__device__ __forceinline__ unsigned f2tf(float x) {
    unsigned u;
    asm("cvt.rna.tf32.f32 %0, %1;" : "=r"(u) : "f"(x));
    return u;
}

__device__ __forceinline__ void mma8(float* c,
    unsigned a0, unsigned a1, unsigned a2, unsigned a3,
    unsigned b0, unsigned b1)
{
    asm volatile(
        "mma.sync.aligned.m16n8k8.row.col.f32.tf32.tf32.f32 "
        "{%0,%1,%2,%3}, {%4,%5,%6,%7}, {%8,%9}, {%0,%1,%2,%3};"
        : "+f"(c[0]), "+f"(c[1]), "+f"(c[2]), "+f"(c[3])
        : "r"(a0), "r"(a1), "r"(a2), "r"(a3), "r"(b0), "r"(b1));
}

__device__ __forceinline__ void ldsm4(unsigned& r0, unsigned& r1, unsigned& r2, unsigned& r3,
                                      unsigned addr)
{
    asm volatile("ldmatrix.sync.aligned.m8n8.x4.shared.b16 {%0,%1,%2,%3}, [%4];"
        : "=r"(r0), "=r"(r1), "=r"(r2), "=r"(r3) : "r"(addr));
}

// ------------------------------------------------------------------
// Projection GEMM (tf32 MMA): 128x128 tile, BK=32, 8 warps x (32x64)
// V output stored transposed [B,H,HD,S].
// ------------------------------------------------------------------
#define PASTR 36
#define PBSTR 136

__global__ __launch_bounds__(256, 2) void proj_kernel(
    const float* __restrict__ q, const float* __restrict__ k, const float* __restrict__ v,
    const float* __restrict__ Wq, const float* __restrict__ bq,
    const float* __restrict__ Wk, const float* __restrict__ bk,
    const float* __restrict__ Wv, const float* __restrict__ bv)
{
    const float* A; const float* W; const float* bias; float* out;
    if (blockIdx.z == 0)      { A = q; W = Wq; bias = bq; out = g_Q; }
    else if (blockIdx.z == 1) { A = k; W = Wk; bias = bk; out = g_K; }
    else                      { A = v; W = Wv; bias = bv; out = g_V; }

    __shared__ float As[128 * PASTR];
    __shared__ float Bs[32 * PBSTR];

    const int tid  = threadIdx.x;
    const int warp = tid >> 5;
    const int lane = tid & 31;
    const int g    = lane >> 2;
    const int t    = lane & 3;

    const int m0 = blockIdx.y * 128;
    const int n0 = blockIdx.x * 128;
    const int wm = (warp & 3) * 32;
    const int wn = (warp >> 2) * 64;

    const unsigned aBase = (unsigned)__cvta_generic_to_shared(As)
        + (((wm + (lane & 7) + ((lane >> 3) & 1) * 8) * PASTR + (lane >> 4) * 4) << 2);

    float C[2][8][4] = {};

    for (int k0 = 0; k0 < Dc; k0 += 32) {
        __syncthreads();
        #pragma unroll
        for (int i = 0; i < 4; i++) {
            int idx = tid + 256 * i;
            int ar = idx >> 3, ac = (idx & 7) << 2;
            float4 av = *(const float4*)(A + (size_t)(m0 + ar) * Dc + k0 + ac);
            As[ar * PASTR + ac + 0] = __uint_as_float(f2tf(av.x));
            As[ar * PASTR + ac + 1] = __uint_as_float(f2tf(av.y));
            As[ar * PASTR + ac + 2] = __uint_as_float(f2tf(av.z));
            As[ar * PASTR + ac + 3] = __uint_as_float(f2tf(av.w));
            int br = idx >> 5, bc = (idx & 31) << 2;
            float4 wv = *(const float4*)(W + (size_t)(k0 + br) * Dc + n0 + bc);
            Bs[br * PBSTR + bc + 0] = __uint_as_float(f2tf(wv.x));
            Bs[br * PBSTR + bc + 1] = __uint_as_float(f2tf(wv.y));
            Bs[br * PBSTR + bc + 2] = __uint_as_float(f2tf(wv.z));
            Bs[br * PBSTR + bc + 3] = __uint_as_float(f2tf(wv.w));
        }
        __syncthreads();

        #pragma unroll
        for (int ks = 0; ks < 4; ks++) {
            unsigned a[2][4];
            #pragma unroll
            for (int mi = 0; mi < 2; mi++)
                ldsm4(a[mi][0], a[mi][1], a[mi][2], a[mi][3],
                      aBase + (unsigned)((mi * 16 * PASTR + ks * 8) << 2));
            #pragma unroll
            for (int ni = 0; ni < 8; ni++) {
                int bb = (ks * 8 + t) * PBSTR + wn + ni * 8 + g;
                unsigned b0 = __float_as_uint(Bs[bb]);
                unsigned b1 = __float_as_uint(Bs[bb + 4 * PBSTR]);
                mma8(C[0][ni], a[0][0], a[0][1], a[0][2], a[0][3], b0, b1);
                mma8(C[1][ni], a[1][0], a[1][1], a[1][2], a[1][3], b0, b1);
            }
        }
    }

    const int h = blockIdx.x;
    if (blockIdx.z != 2) {
        #pragma unroll
        for (int mi = 0; mi < 2; mi++) {
            int row0 = m0 + wm + mi * 16 + g;
            #pragma unroll
            for (int ni = 0; ni < 8; ni++) {
                int col = wn + ni * 8 + 2 * t;
                float b0v = bias[n0 + col], b1v = bias[n0 + col + 1];
                int bb0 = row0 >> 11, s0 = row0 & (Sc - 1);
                float* d0 = out + (((size_t)(bb0 * Hc + h)) * Sc + s0) * HDc + col;
                *(float2*)d0 = make_float2(__uint_as_float(f2tf(C[mi][ni][0] + b0v)),
                                           __uint_as_float(f2tf(C[mi][ni][1] + b1v)));
                int r1 = row0 + 8;
                int bb1 = r1 >> 11, s1 = r1 & (Sc - 1);
                float* d1 = out + (((size_t)(bb1 * Hc + h)) * Sc + s1) * HDc + col;
                *(float2*)d1 = make_float2(__uint_as_float(f2tf(C[mi][ni][2] + b0v)),
                                           __uint_as_float(f2tf(C[mi][ni][3] + b1v)));
            }
        }
    } else {
        #pragma unroll
        for (int mi = 0; mi < 2; mi++) {
            int row0 = m0 + wm + mi * 16 + g;
            #pragma unroll
            for (int ni = 0; ni < 8; ni++) {
                int col = wn + ni * 8 + 2 * t;
                float b0v = bias[n0 + col], b1v = bias[n0 + col + 1];
                int bb0 = row0 >> 11, s0 = row0 & (Sc - 1);
                float* base0 = out + ((size_t)(bb0 * Hc + h)) * HDc * Sc;
                base0[(size_t)col * Sc + s0]       = __uint_as_float(f2tf(C[mi][ni][0] + b0v));
                base0[(size_t)(col + 1) * Sc + s0] = __uint_as_float(f2tf(C[mi][ni][1] + b1v));
                int r1 = row0 + 8;
                int bb1 = r1 >> 11, s1 = r1 & (Sc - 1);
                float* base1 = out + ((size_t)(bb1 * Hc + h)) * HDc * Sc;
                base1[(size_t)col * Sc + s1]       = __uint_as_float(f2tf(C[mi][ni][2] + b0v));
                base1[(size_t)(col + 1) * Sc + s1] = __uint_as_float(f2tf(C[mi][ni][3] + b1v));
            }
        }
    }
}

// ------------------------------------------------------------------
// Flash attention, TQ=128 q-rows, TK=64.  8 warps.
// QK: 4 row-groups(32) x 2 col-groups(32).  PV: 4 row-groups(32) x 2 d-groups(64).
// ------------------------------------------------------------------
#define QSTR  132
#define KSTR  132
#define VTSTR 68
#define SSTR  68

#define SM_Q   0
#define SM_KV  (128 * QSTR)            // max(K 64*132=8448, VT 128*68=8704)
#define SM_S   (SM_KV + 128 * VTSTR)
#define SM_M   (SM_S + 128 * SSTR)
#define SM_L   (SM_M + 128)
#define SM_A   (SM_L + 128)
#define ATTN_SMEM_FLOATS (SM_A + 128)
#define ATTN_SMEM_BYTES  (ATTN_SMEM_FLOATS * 4)

__global__ __launch_bounds__(256, 1) void attn_kernel(
    const unsigned int* __restrict__ mask, float* __restrict__ out)
{
    extern __shared__ float smem[];
    float* sQ   = smem + SM_Q;
    float* sKV  = smem + SM_KV;
    float* sS   = smem + SM_S;
    float* mrow = smem + SM_M;
    float* lrow = smem + SM_L;
    float* arow = smem + SM_A;

    const int tid  = threadIdx.x;
    const int warp = tid >> 5;
    const int lane = tid & 31;
    const int g    = lane >> 2;
    const int t    = lane & 3;

    const int bh = blockIdx.y;
    const int b  = bh >> 3;
    const int h  = bh & (Hc - 1);
    const int q0 = blockIdx.x * 128;

    const int rw = (warp & 3) * 32;    // QK + PV row base
    const int cw = (warp >> 2) * 32;   // QK col base
    const int dw = (warp >> 2) * 64;   // PV dcol base

    const float* Qg = g_Q + (size_t)bh * Sc * HDc;
    const float* Kg = g_K + (size_t)bh * Sc * HDc;
    const float* Vg = g_V + (size_t)bh * HDc * Sc;   // [HD][S]
    const unsigned int* maskb = mask + (size_t)b * Sc * Sc;

    const unsigned sbase = (unsigned)__cvta_generic_to_shared(smem);
    const unsigned aQ = sbase + ((SM_Q  + (rw + (lane & 7) + ((lane >> 3) & 1) * 8) * QSTR  + (lane >> 4) * 4) << 2);
    const unsigned bK = sbase + ((SM_KV + (cw + ((lane >> 4) & 1) * 8 + (lane & 7)) * KSTR  + ((lane >> 3) & 1) * 4) << 2);
    const unsigned aS = sbase + ((SM_S  + (rw + (lane & 7) + ((lane >> 3) & 1) * 8) * SSTR  + (lane >> 4) * 4) << 2);
    const unsigned bV = sbase + ((SM_KV + (dw + ((lane >> 4) & 1) * 8 + (lane & 7)) * VTSTR + ((lane >> 3) & 1) * 4) << 2);

    // Q tile: 128 rows x 128 d
    #pragma unroll
    for (int i = 0; i < 16; i++) {
        int idx = tid + 256 * i;
        int r = idx >> 5, d = (idx & 31) << 2;
        *(float4*)(&sQ[r * QSTR + d]) = *(const float4*)(Qg + (size_t)(q0 + r) * HDc + d);
    }
    if (tid < 128) { mrow[tid] = -1e30f; lrow[tid] = 0.0f; }

    float O[2][8][4] = {};
    const float scale = 0.08838834764831845f;  // 1/sqrt(128)

    for (int kt = 0; kt < Sc / 64; kt++) {
        const int k0 = kt * 64;
        __syncthreads();

        // K tile [key][d]: 64 x 128
        #pragma unroll
        for (int i = 0; i < 8; i++) {
            int idx = tid + 256 * i;
            int r = idx >> 5, d = (idx & 31) << 2;
            *(float4*)(&sKV[r * KSTR + d]) = *(const float4*)(Kg + (size_t)(k0 + r) * HDc + d);
        }
        __syncthreads();

        // QK^T: warp tile 32x32
        float S[2][4][4] = {};
        #pragma unroll
        for (int ks = 0; ks < 16; ks++) {
            unsigned a[2][4];
            #pragma unroll
            for (int mi = 0; mi < 2; mi++)
                ldsm4(a[mi][0], a[mi][1], a[mi][2], a[mi][3],
                      aQ + (unsigned)(((mi * 16 * QSTR) << 2) + ks * 32));
            #pragma unroll
            for (int nii = 0; nii < 2; nii++) {
                unsigned b0, b1, b2, b3;
                ldsm4(b0, b1, b2, b3, bK + (unsigned)(((nii * 16 * KSTR) << 2) + ks * 32));
                #pragma unroll
                for (int mi = 0; mi < 2; mi++) {
                    mma8(S[mi][nii * 2],     a[mi][0], a[mi][1], a[mi][2], a[mi][3], b0, b1);
                    mma8(S[mi][nii * 2 + 1], a[mi][0], a[mi][1], a[mi][2], a[mi][3], b2, b3);
                }
            }
        }
        #pragma unroll
        for (int mi = 0; mi < 2; mi++) {
            int qr = rw + mi * 16 + g;
            #pragma unroll
            for (int ni = 0; ni < 4; ni++) {
                int col = cw + ni * 8 + 2 * t;
                *(float2*)(&sS[qr * SSTR + col])       = make_float2(S[mi][ni][0], S[mi][ni][1]);
                *(float2*)(&sS[(qr + 8) * SSTR + col]) = make_float2(S[mi][ni][2], S[mi][ni][3]);
            }
        }
        __syncthreads();

        // V^T tile [d][key]: 128 x 64 (overwrites K region)
        #pragma unroll
        for (int i = 0; i < 8; i++) {
            int idx = tid + 256 * i;
            int d = idx >> 4, c4 = (idx & 15) << 2;
            *(float4*)(&sKV[d * VTSTR + c4]) = *(const float4*)(Vg + (size_t)d * Sc + k0 + c4);
        }

        // softmax: 2 lanes/row, 32 cols each
        {
            int r  = tid >> 1;
            int qt = tid & 1;
            float* srow = &sS[r * SSTR + qt * 32];
            const uint4* mr4 = (const uint4*)(maskb + (size_t)(q0 + r) * Sc + k0 + qt * 32);
            float p[32];
            float rmax = -1e30f;
            #pragma unroll
            for (int j = 0; j < 8; j++) {
                float4 sv = *(const float4*)(&srow[4 * j]);
                uint4  mv = mr4[j];
                p[4*j+0] = (mv.x ? -1e6f : sv.x) * scale;
                p[4*j+1] = (mv.y ? -1e6f : sv.y) * scale;
                p[4*j+2] = (mv.z ? -1e6f : sv.z) * scale;
                p[4*j+3] = (mv.w ? -1e6f : sv.w) * scale;
                #pragma unroll
                for (int e = 0; e < 4; e++) rmax = fmaxf(rmax, p[4*j+e]);
            }
            rmax = fmaxf(rmax, __shfl_xor_sync(0xffffffffu, rmax, 1));
            float mold = mrow[r];
            float mnew = fmaxf(mold, rmax);
            float sum = 0.0f;
            #pragma unroll
            for (int j = 0; j < 8; j++) {
                float4 pv;
                pv.x = __uint_as_float(f2tf(__expf(p[4*j+0] - mnew)));
                pv.y = __uint_as_float(f2tf(__expf(p[4*j+1] - mnew)));
                pv.z = __uint_as_float(f2tf(__expf(p[4*j+2] - mnew)));
                pv.w = __uint_as_float(f2tf(__expf(p[4*j+3] - mnew)));
                sum += pv.x + pv.y + pv.z + pv.w;
                *(float4*)(&srow[4 * j]) = pv;
            }
            sum += __shfl_xor_sync(0xffffffffu, sum, 1);
            if (qt == 0) {
                float al = __expf(mold - mnew);
                mrow[r] = mnew;
                arow[r] = al;
                lrow[r] = lrow[r] * al + sum;
            }
        }
        __syncthreads();

        // rescale O, then PV: warp tile 32 rows x 64 dcols
        #pragma unroll
        for (int mi = 0; mi < 2; mi++) {
            float al0 = arow[rw + mi * 16 + g];
            float al1 = arow[rw + mi * 16 + 8 + g];
            #pragma unroll
            for (int ni = 0; ni < 8; ni++) {
                O[mi][ni][0] *= al0; O[mi][ni][1] *= al0;
                O[mi][ni][2] *= al1; O[mi][ni][3] *= al1;
            }
        }
        #pragma unroll
        for (int ks = 0; ks < 8; ks++) {
            unsigned a[2][4];
            #pragma unroll
            for (int mi = 0; mi < 2; mi++)
                ldsm4(a[mi][0], a[mi][1], a[mi][2], a[mi][3],
                      aS + (unsigned)(((mi * 16 * SSTR) << 2) + ks * 32));
            #pragma unroll
            for (int nii = 0; nii < 4; nii++) {
                unsigned b0, b1, b2, b3;
                ldsm4(b0, b1, b2, b3, bV + (unsigned)(((nii * 16 * VTSTR) << 2) + ks * 32));
                #pragma unroll
                for (int mi = 0; mi < 2; mi++) {
                    mma8(O[mi][nii * 2],     a[mi][0], a[mi][1], a[mi][2], a[mi][3], b0, b1);
                    mma8(O[mi][nii * 2 + 1], a[mi][0], a[mi][1], a[mi][2], a[mi][3], b2, b3);
                }
            }
        }
    }

    // epilogue
    #pragma unroll
    for (int mi = 0; mi < 2; mi++) {
        float linv0 = 1.0f / lrow[rw + mi * 16 + g];
        float linv1 = 1.0f / lrow[rw + mi * 16 + 8 + g];
        int row0 = q0 + rw + mi * 16 + g;
        #pragma unroll
        for (int ni = 0; ni < 8; ni++) {
            int col = dw + ni * 8 + 2 * t;
            float* d0 = out + ((size_t)b * Sc + row0) * Dc + h * HDc + col;
            *(float2*)d0 = make_float2(O[mi][ni][0] * linv0, O[mi][ni][1] * linv0);
            float* d1 = out + ((size_t)b * Sc + row0 + 8) * Dc + h * HDc + col;
            *(float2*)d1 = make_float2(O[mi][ni][2] * linv1, O[mi][ni][3] * linv1);
        }
    }
}

// ------------------------------------------------------------------
extern "C" void kernel_launch(void* const* d_in, const int* in_sizes, int n_in,
                              void* d_out, int out_size)
{
    const float* q  = (const float*)d_in[0];
    const float* k  = (const float*)d_in[1];
    const float* v  = (const float*)d_in[2];
    const unsigned int* mask = (const unsigned int*)d_in[3];
    const float* Wq = (const float*)d_in[4];
    const float* bq = (const float*)d_in[5];
    const float* Wk = (const float*)d_in[6];
    const float* bk = (const float*)d_in[7];
    const float* Wv = (const float*)d_in[8];
    const float* bv = (const float*)d_in[9];
    float* out = (float*)d_out;

    dim3 pgrid(Dc / 128, Mc / 128, 3);
    proj_kernel<<<pgrid, 256>>>(q, k, v, Wq, bq, Wk, bk, Wv, bv);

    cudaFuncSetAttribute(attn_kernel,
                         cudaFuncAttributeMaxDynamicSharedMemorySize,
                         ATTN_SMEM_BYTES);
    dim3 agrid(Sc / 128, Bc * Hc);
    attn_kernel<<<agrid, 256, ATTN_SMEM_BYTES>>>(mask, out);
}

// round 8
// speedup vs baseline: 3.8929x; 1.1069x over previous
#include <cuda_runtime.h>
#include <math.h>

#define Bc 2
#define Sc 2048
#define Dc 1024
#define Hc 8
#define HDc 128
#define Mc (Bc*Sc)   // 4096

// scratch (tf32-rounded fp32): Q,K as [B,H,S,HD]; V as [B,H,HD,S] (transposed)
__device__ float g_Q[Bc*Hc*Sc*HDc];
__device__ float g_K[Bc*Hc*Sc*HDc];
__device__ float g_V[Bc*Hc*Sc*HDc];

__device__ __forceinline__ unsigned f2tf(float x) {
    unsigned u;
    asm("cvt.rna.tf32.f32 %0, %1;" : "=r"(u) : "f"(x));
    return u;
}

__device__ __forceinline__ void mma8(float* c,
    unsigned a0, unsigned a1, unsigned a2, unsigned a3,
    unsigned b0, unsigned b1)
{
    asm volatile(
        "mma.sync.aligned.m16n8k8.row.col.f32.tf32.tf32.f32 "
        "{%0,%1,%2,%3}, {%4,%5,%6,%7}, {%8,%9}, {%0,%1,%2,%3};"
        : "+f"(c[0]), "+f"(c[1]), "+f"(c[2]), "+f"(c[3])
        : "r"(a0), "r"(a1), "r"(a2), "r"(a3), "r"(b0), "r"(b1));
}

__device__ __forceinline__ void ldsm4(unsigned& r0, unsigned& r1, unsigned& r2, unsigned& r3,
                                      unsigned addr)
{
    asm volatile("ldmatrix.sync.aligned.m8n8.x4.shared.b16 {%0,%1,%2,%3}, [%4];"
        : "=r"(r0), "=r"(r1), "=r"(r2), "=r"(r3) : "r"(addr));
}

__device__ __forceinline__ void cpa16(unsigned dst, const void* src) {
    asm volatile("cp.async.cg.shared.global [%0], [%1], 16;" :: "r"(dst), "l"(src));
}
#define CP_COMMIT() asm volatile("cp.async.commit_group;")
#define CP_WAIT1()  asm volatile("cp.async.wait_group 1;")
#define CP_WAIT0()  asm volatile("cp.async.wait_group 0;")

// ------------------------------------------------------------------
// Projection GEMM (tf32 MMA): 128x128 tile, BK=32, 8 warps x (32x64)
// V output stored transposed [B,H,HD,S].
// ------------------------------------------------------------------
#define PASTR 36
#define PBSTR 136

__global__ __launch_bounds__(256, 2) void proj_kernel(
    const float* __restrict__ q, const float* __restrict__ k, const float* __restrict__ v,
    const float* __restrict__ Wq, const float* __restrict__ bq,
    const float* __restrict__ Wk, const float* __restrict__ bk,
    const float* __restrict__ Wv, const float* __restrict__ bv)
{
    const float* A; const float* W; const float* bias; float* out;
    if (blockIdx.z == 0)      { A = q; W = Wq; bias = bq; out = g_Q; }
    else if (blockIdx.z == 1) { A = k; W = Wk; bias = bk; out = g_K; }
    else                      { A = v; W = Wv; bias = bv; out = g_V; }

    __shared__ float As[128 * PASTR];
    __shared__ float Bs[32 * PBSTR];

    const int tid  = threadIdx.x;
    const int warp = tid >> 5;
    const int lane = tid & 31;
    const int g    = lane >> 2;
    const int t    = lane & 3;

    const int m0 = blockIdx.y * 128;
    const int n0 = blockIdx.x * 128;
    const int wm = (warp & 3) * 32;
    const int wn = (warp >> 2) * 64;

    const unsigned aBase = (unsigned)__cvta_generic_to_shared(As)
        + (((wm + (lane & 7) + ((lane >> 3) & 1) * 8) * PASTR + (lane >> 4) * 4) << 2);

    float C[2][8][4] = {};

    for (int k0 = 0; k0 < Dc; k0 += 32) {
        __syncthreads();
        #pragma unroll
        for (int i = 0; i < 4; i++) {
            int idx = tid + 256 * i;
            int ar = idx >> 3, ac = (idx & 7) << 2;
            float4 av = *(const float4*)(A + (size_t)(m0 + ar) * Dc + k0 + ac);
            As[ar * PASTR + ac + 0] = __uint_as_float(f2tf(av.x));
            As[ar * PASTR + ac + 1] = __uint_as_float(f2tf(av.y));
            As[ar * PASTR + ac + 2] = __uint_as_float(f2tf(av.z));
            As[ar * PASTR + ac + 3] = __uint_as_float(f2tf(av.w));
            int br = idx >> 5, bc = (idx & 31) << 2;
            float4 wv = *(const float4*)(W + (size_t)(k0 + br) * Dc + n0 + bc);
            Bs[br * PBSTR + bc + 0] = __uint_as_float(f2tf(wv.x));
            Bs[br * PBSTR + bc + 1] = __uint_as_float(f2tf(wv.y));
            Bs[br * PBSTR + bc + 2] = __uint_as_float(f2tf(wv.z));
            Bs[br * PBSTR + bc + 3] = __uint_as_float(f2tf(wv.w));
        }
        __syncthreads();

        #pragma unroll
        for (int ks = 0; ks < 4; ks++) {
            unsigned a[2][4];
            #pragma unroll
            for (int mi = 0; mi < 2; mi++)
                ldsm4(a[mi][0], a[mi][1], a[mi][2], a[mi][3],
                      aBase + (unsigned)((mi * 16 * PASTR + ks * 8) << 2));
            #pragma unroll
            for (int ni = 0; ni < 8; ni++) {
                int bb = (ks * 8 + t) * PBSTR + wn + ni * 8 + g;
                unsigned b0 = __float_as_uint(Bs[bb]);
                unsigned b1 = __float_as_uint(Bs[bb + 4 * PBSTR]);
                mma8(C[0][ni], a[0][0], a[0][1], a[0][2], a[0][3], b0, b1);
                mma8(C[1][ni], a[1][0], a[1][1], a[1][2], a[1][3], b0, b1);
            }
        }
    }

    const int h = blockIdx.x;
    if (blockIdx.z != 2) {
        #pragma unroll
        for (int mi = 0; mi < 2; mi++) {
            int row0 = m0 + wm + mi * 16 + g;
            #pragma unroll
            for (int ni = 0; ni < 8; ni++) {
                int col = wn + ni * 8 + 2 * t;
                float b0v = bias[n0 + col], b1v = bias[n0 + col + 1];
                int bb0 = row0 >> 11, s0 = row0 & (Sc - 1);
                float* d0 = out + (((size_t)(bb0 * Hc + h)) * Sc + s0) * HDc + col;
                *(float2*)d0 = make_float2(__uint_as_float(f2tf(C[mi][ni][0] + b0v)),
                                           __uint_as_float(f2tf(C[mi][ni][1] + b1v)));
                int r1 = row0 + 8;
                int bb1 = r1 >> 11, s1 = r1 & (Sc - 1);
                float* d1 = out + (((size_t)(bb1 * Hc + h)) * Sc + s1) * HDc + col;
                *(float2*)d1 = make_float2(__uint_as_float(f2tf(C[mi][ni][2] + b0v)),
                                           __uint_as_float(f2tf(C[mi][ni][3] + b1v)));
            }
        }
    } else {
        #pragma unroll
        for (int mi = 0; mi < 2; mi++) {
            int row0 = m0 + wm + mi * 16 + g;
            #pragma unroll
            for (int ni = 0; ni < 8; ni++) {
                int col = wn + ni * 8 + 2 * t;
                float b0v = bias[n0 + col], b1v = bias[n0 + col + 1];
                int bb0 = row0 >> 11, s0 = row0 & (Sc - 1);
                float* base0 = out + ((size_t)(bb0 * Hc + h)) * HDc * Sc;
                base0[(size_t)col * Sc + s0]       = __uint_as_float(f2tf(C[mi][ni][0] + b0v));
                base0[(size_t)(col + 1) * Sc + s0] = __uint_as_float(f2tf(C[mi][ni][1] + b1v));
                int r1 = row0 + 8;
                int bb1 = r1 >> 11, s1 = r1 & (Sc - 1);
                float* base1 = out + ((size_t)(bb1 * Hc + h)) * HDc * Sc;
                base1[(size_t)col * Sc + s1]       = __uint_as_float(f2tf(C[mi][ni][2] + b0v));
                base1[(size_t)(col + 1) * Sc + s1] = __uint_as_float(f2tf(C[mi][ni][3] + b1v));
            }
        }
    }
}

// ------------------------------------------------------------------
// Flash attention, TQ=128, TK=64, cp.async pipelined K/V/mask.
// ------------------------------------------------------------------
#define QSTR  132
#define KSTR  132
#define VTSTR 68
#define SSTR  68
#define MSTR  68

#define SM_Q    0
#define SM_K    (128 * QSTR)               // 16896
#define SM_VT   (SM_K   + 64 * KSTR)       // +8448
#define SM_S    (SM_VT  + 128 * VTSTR)     // +8704
#define SM_MSK  (SM_S   + 128 * SSTR)      // +8704
#define SM_M    (SM_MSK + 128 * MSTR)      // +8704
#define SM_L    (SM_M + 128)
#define SM_A    (SM_L + 128)
#define ATTN_SMEM_FLOATS (SM_A + 128)
#define ATTN_SMEM_BYTES  (ATTN_SMEM_FLOATS * 4)

#define NTILE (Sc / 64)

__global__ __launch_bounds__(256, 1) void attn_kernel(
    const unsigned int* __restrict__ mask, float* __restrict__ out)
{
    extern __shared__ float smem[];
    float* sQ   = smem + SM_Q;
    float* sS   = smem + SM_S;
    float* mrow = smem + SM_M;
    float* lrow = smem + SM_L;
    float* arow = smem + SM_A;
    const unsigned int* sMsk = (const unsigned int*)(smem + SM_MSK);

    const int tid  = threadIdx.x;
    const int warp = tid >> 5;
    const int lane = tid & 31;
    const int g    = lane >> 2;
    const int t    = lane & 3;

    const int bh = blockIdx.y;
    const int b  = bh >> 3;
    const int h  = bh & (Hc - 1);
    const int q0 = blockIdx.x * 128;

    const int rw = (warp & 3) * 32;
    const int cw = (warp >> 2) * 32;
    const int dw = (warp >> 2) * 64;

    const float* Qg = g_Q + (size_t)bh * Sc * HDc;
    const float* Kg = g_K + (size_t)bh * Sc * HDc;
    const float* Vg = g_V + (size_t)bh * HDc * Sc;   // [HD][S]
    const unsigned int* maskb = mask + (size_t)b * Sc * Sc;

    const unsigned sbase = (unsigned)__cvta_generic_to_shared(smem);
    const unsigned aQ = sbase + ((SM_Q  + (rw + (lane & 7) + ((lane >> 3) & 1) * 8) * QSTR  + (lane >> 4) * 4) << 2);
    const unsigned bK = sbase + ((SM_K  + (cw + ((lane >> 4) & 1) * 8 + (lane & 7)) * KSTR  + ((lane >> 3) & 1) * 4) << 2);
    const unsigned aS = sbase + ((SM_S  + (rw + (lane & 7) + ((lane >> 3) & 1) * 8) * SSTR  + (lane >> 4) * 4) << 2);
    const unsigned bV = sbase + ((SM_VT + (dw + ((lane >> 4) & 1) * 8 + (lane & 7)) * VTSTR + ((lane >> 3) & 1) * 4) << 2);

    // prefetch helpers (each thread: 8 x 16B per tile per stream)
    auto prefK = [&](int kt) {
        const float* src = Kg + (size_t)kt * 64 * HDc;
        #pragma unroll
        for (int i = 0; i < 8; i++) {
            int idx = tid + 256 * i;
            int r = idx >> 5, d = (idx & 31) << 2;
            cpa16(sbase + ((SM_K + r * KSTR + d) << 2), src + (size_t)r * HDc + d);
        }
    };
    auto prefV = [&](int kt) {
        const float* src = Vg + kt * 64;
        #pragma unroll
        for (int i = 0; i < 8; i++) {
            int idx = tid + 256 * i;
            int d = idx >> 4, c4 = (idx & 15) << 2;
            cpa16(sbase + ((SM_VT + d * VTSTR + c4) << 2), src + (size_t)d * Sc + c4);
        }
    };
    auto prefM = [&](int kt) {
        const unsigned int* src = maskb + (size_t)q0 * Sc + kt * 64;
        #pragma unroll
        for (int i = 0; i < 8; i++) {
            int idx = tid + 256 * i;
            int r = idx >> 4, c = (idx & 15) << 2;
            cpa16(sbase + ((SM_MSK + r * MSTR + c) << 2), src + (size_t)r * Sc + c);
        }
    };

    // Q tile: 128 x 128
    #pragma unroll
    for (int i = 0; i < 16; i++) {
        int idx = tid + 256 * i;
        int r = idx >> 5, d = (idx & 31) << 2;
        *(float4*)(&sQ[r * QSTR + d]) = *(const float4*)(Qg + (size_t)(q0 + r) * HDc + d);
    }
    if (tid < 128) { mrow[tid] = -1e30f; lrow[tid] = 0.0f; }

    prefK(0); CP_COMMIT();
    prefV(0); prefM(0); CP_COMMIT();

    float O[2][8][4] = {};
    const float scale = 0.08838834764831845f;  // 1/sqrt(128)

    for (int kt = 0; kt < NTILE; kt++) {
        const int ktn = (kt + 1 < NTILE) ? kt + 1 : NTILE - 1;

        CP_WAIT1();          // K_kt landed ({V,M}_kt may pend)
        __syncthreads();

        // QK^T: warp tile 32x32
        float S[2][4][4] = {};
        #pragma unroll
        for (int ks = 0; ks < 16; ks++) {
            unsigned a[2][4];
            #pragma unroll
            for (int mi = 0; mi < 2; mi++)
                ldsm4(a[mi][0], a[mi][1], a[mi][2], a[mi][3],
                      aQ + (unsigned)(((mi * 16 * QSTR) << 2) + ks * 32));
            #pragma unroll
            for (int nii = 0; nii < 2; nii++) {
                unsigned b0, b1, b2, b3;
                ldsm4(b0, b1, b2, b3, bK + (unsigned)(((nii * 16 * KSTR) << 2) + ks * 32));
                #pragma unroll
                for (int mi = 0; mi < 2; mi++) {
                    mma8(S[mi][nii * 2],     a[mi][0], a[mi][1], a[mi][2], a[mi][3], b0, b1);
                    mma8(S[mi][nii * 2 + 1], a[mi][0], a[mi][1], a[mi][2], a[mi][3], b2, b3);
                }
            }
        }
        #pragma unroll
        for (int mi = 0; mi < 2; mi++) {
            int qr = rw + mi * 16 + g;
            #pragma unroll
            for (int ni = 0; ni < 4; ni++) {
                int col = cw + ni * 8 + 2 * t;
                *(float2*)(&sS[qr * SSTR + col])       = make_float2(S[mi][ni][0], S[mi][ni][1]);
                *(float2*)(&sS[(qr + 8) * SSTR + col]) = make_float2(S[mi][ni][2], S[mi][ni][3]);
            }
        }
        __syncthreads();     // S visible, K buffer free

        prefK(ktn); CP_COMMIT();

        CP_WAIT1();          // {V,M}_kt landed (K_ktn may pend)
        __syncthreads();

        // softmax: 2 lanes/row, 32 cols each (mask from smem)
        {
            int r  = tid >> 1;
            int qt = tid & 1;
            float* srow = &sS[r * SSTR + qt * 32];
            const uint4* mr4 = (const uint4*)(sMsk + r * MSTR + qt * 32);
            float p[32];
            float rmax = -1e30f;
            #pragma unroll
            for (int j = 0; j < 8; j++) {
                float4 sv = *(const float4*)(&srow[4 * j]);
                uint4  mv = mr4[j];
                p[4*j+0] = (mv.x ? -1e6f : sv.x) * scale;
                p[4*j+1] = (mv.y ? -1e6f : sv.y) * scale;
                p[4*j+2] = (mv.z ? -1e6f : sv.z) * scale;
                p[4*j+3] = (mv.w ? -1e6f : sv.w) * scale;
                #pragma unroll
                for (int e = 0; e < 4; e++) rmax = fmaxf(rmax, p[4*j+e]);
            }
            rmax = fmaxf(rmax, __shfl_xor_sync(0xffffffffu, rmax, 1));
            float mold = mrow[r];
            float mnew = fmaxf(mold, rmax);
            float sum = 0.0f;
            #pragma unroll
            for (int j = 0; j < 8; j++) {
                float4 pv;
                pv.x = __uint_as_float(f2tf(__expf(p[4*j+0] - mnew)));
                pv.y = __uint_as_float(f2tf(__expf(p[4*j+1] - mnew)));
                pv.z = __uint_as_float(f2tf(__expf(p[4*j+2] - mnew)));
                pv.w = __uint_as_float(f2tf(__expf(p[4*j+3] - mnew)));
                sum += pv.x + pv.y + pv.z + pv.w;
                *(float4*)(&srow[4 * j]) = pv;
            }
            sum += __shfl_xor_sync(0xffffffffu, sum, 1);
            if (qt == 0) {
                float al = __expf(mold - mnew);
                mrow[r] = mnew;
                arow[r] = al;
                lrow[r] = lrow[r] * al + sum;
            }
        }
        __syncthreads();     // P visible, mask buffer free

        // rescale O, then PV: warp tile 32 rows x 64 dcols
        #pragma unroll
        for (int mi = 0; mi < 2; mi++) {
            float al0 = arow[rw + mi * 16 + g];
            float al1 = arow[rw + mi * 16 + 8 + g];
            #pragma unroll
            for (int ni = 0; ni < 8; ni++) {
                O[mi][ni][0] *= al0; O[mi][ni][1] *= al0;
                O[mi][ni][2] *= al1; O[mi][ni][3] *= al1;
            }
        }
        #pragma unroll
        for (int ks = 0; ks < 8; ks++) {
            unsigned a[2][4];
            #pragma unroll
            for (int mi = 0; mi < 2; mi++)
                ldsm4(a[mi][0], a[mi][1], a[mi][2], a[mi][3],
                      aS + (unsigned)(((mi * 16 * SSTR) << 2) + ks * 32));
            #pragma unroll
            for (int nii = 0; nii < 4; nii++) {
                unsigned b0, b1, b2, b3;
                ldsm4(b0, b1, b2, b3, bV + (unsigned)(((nii * 16 * VTSTR) << 2) + ks * 32));
                #pragma unroll
                for (int mi = 0; mi < 2; mi++) {
                    mma8(O[mi][nii * 2],     a[mi][0], a[mi][1], a[mi][2], a[mi][3], b0, b1);
                    mma8(O[mi][nii * 2 + 1], a[mi][0], a[mi][1], a[mi][2], a[mi][3], b2, b3);
                }
            }
        }
        __syncthreads();     // V + S buffers free

        prefV(ktn); prefM(ktn); CP_COMMIT();
    }

    CP_WAIT0();

    // epilogue
    #pragma unroll
    for (int mi = 0; mi < 2; mi++) {
        float linv0 = 1.0f / lrow[rw + mi * 16 + g];
        float linv1 = 1.0f / lrow[rw + mi * 16 + 8 + g];
        int row0 = q0 + rw + mi * 16 + g;
        #pragma unroll
        for (int ni = 0; ni < 8; ni++) {
            int col = dw + ni * 8 + 2 * t;
            float* d0 = out + ((size_t)b * Sc + row0) * Dc + h * HDc + col;
            *(float2*)d0 = make_float2(O[mi][ni][0] * linv0, O[mi][ni][1] * linv0);
            float* d1 = out + ((size_t)b * Sc + row0 + 8) * Dc + h * HDc + col;
            *(float2*)d1 = make_float2(O[mi][ni][2] * linv1, O[mi][ni][3] * linv1);
        }
    }
}

// ------------------------------------------------------------------
extern "C" void kernel_launch(void* const* d_in, const int* in_sizes, int n_in,
                              void* d_out, int out_size)
{
    const float* q  = (const float*)d_in[0];
    const float* k  = (const float*)d_in[1];
    const float* v  = (const float*)d_in[2];
    const unsigned int* mask = (const unsigned int*)d_in[3];
    const float* Wq = (const float*)d_in[4];
    const float* bq = (const float*)d_in[5];
    const float* Wk = (const float*)d_in[6];
    const float* bk = (const float*)d_in[7];
    const float* Wv = (const float*)d_in[8];
    const float* bv = (const float*)d_in[9];
    float* out = (float*)d_out;

    dim3 pgrid(Dc / 128, Mc / 128, 3);
    proj_kernel<<<pgrid, 256>>>(q, k, v, Wq, bq, Wk, bk, Wv, bv);

    cudaFuncSetAttribute(attn_kernel,
                         cudaFuncAttributeMaxDynamicSharedMemorySize,
                         ATTN_SMEM_BYTES);
    dim3 agrid(Sc / 128, Bc * Hc);
    attn_kernel<<<agrid, 256, ATTN_SMEM_BYTES>>>(mask, out);
}

// round 9
// speedup vs baseline: 4.1296x; 1.0608x over previous
#include <cuda_runtime.h>
#include <math.h>

#define Bc 2
#define Sc 2048
#define Dc 1024
#define Hc 8
#define HDc 128
#define Mc (Bc*Sc)   // 4096

// scratch (tf32-rounded fp32): Q,K as [B,H,S,HD]; V as [B,H,HD,S] (transposed)
__device__ float g_Q[Bc*Hc*Sc*HDc];
__device__ float g_K[Bc*Hc*Sc*HDc];
__device__ float g_V[Bc*Hc*Sc*HDc];
// tf32-rounded copies of inputs
__device__ float g_qc[Mc*Dc];
__device__ float g_kc[Mc*Dc];
__device__ float g_vc[Mc*Dc];
__device__ float g_wq[Dc*Dc];
__device__ float g_wk[Dc*Dc];
__device__ float g_wv[Dc*Dc];

__device__ __forceinline__ unsigned f2tf(float x) {
    unsigned u;
    asm("cvt.rna.tf32.f32 %0, %1;" : "=r"(u) : "f"(x));
    return u;
}

__device__ __forceinline__ void mma8(float* c,
    unsigned a0, unsigned a1, unsigned a2, unsigned a3,
    unsigned b0, unsigned b1)
{
    asm volatile(
        "mma.sync.aligned.m16n8k8.row.col.f32.tf32.tf32.f32 "
        "{%0,%1,%2,%3}, {%4,%5,%6,%7}, {%8,%9}, {%0,%1,%2,%3};"
        : "+f"(c[0]), "+f"(c[1]), "+f"(c[2]), "+f"(c[3])
        : "r"(a0), "r"(a1), "r"(a2), "r"(a3), "r"(b0), "r"(b1));
}

__device__ __forceinline__ void ldsm4(unsigned& r0, unsigned& r1, unsigned& r2, unsigned& r3,
                                      unsigned addr)
{
    asm volatile("ldmatrix.sync.aligned.m8n8.x4.shared.b16 {%0,%1,%2,%3}, [%4];"
        : "=r"(r0), "=r"(r1), "=r"(r2), "=r"(r3) : "r"(addr));
}

__device__ __forceinline__ void cpa16(unsigned dst, const void* src) {
    asm volatile("cp.async.cg.shared.global [%0], [%1], 16;" :: "r"(dst), "l"(src));
}
#define CP_COMMIT() asm volatile("cp.async.commit_group;")
#define CP_WAIT1()  asm volatile("cp.async.wait_group 1;")
#define CP_WAIT0()  asm volatile("cp.async.wait_group 0;")

// ------------------------------------------------------------------
// Pre-convert: tf32-round inputs into scratch (bit-identical to rounding
// at smem-store time, which is what proj used to do).
// ------------------------------------------------------------------
__global__ __launch_bounds__(256) void cvt_kernel(
    const float* __restrict__ q, const float* __restrict__ k, const float* __restrict__ v,
    const float* __restrict__ Wq, const float* __restrict__ Wk, const float* __restrict__ Wv)
{
    const float* src; float* dst; int n;
    switch (blockIdx.y) {
        case 0: src = q;  dst = g_qc; n = Mc*Dc; break;
        case 1: src = k;  dst = g_kc; n = Mc*Dc; break;
        case 2: src = v;  dst = g_vc; n = Mc*Dc; break;
        case 3: src = Wq; dst = g_wq; n = Dc*Dc; break;
        case 4: src = Wk; dst = g_wk; n = Dc*Dc; break;
        default: src = Wv; dst = g_wv; n = Dc*Dc; break;
    }
    int idx = (blockIdx.x * 256 + threadIdx.x) * 4;
    if (idx < n) {
        float4 vv = *(const float4*)(src + idx);
        float4 o;
        o.x = __uint_as_float(f2tf(vv.x));
        o.y = __uint_as_float(f2tf(vv.y));
        o.z = __uint_as_float(f2tf(vv.z));
        o.w = __uint_as_float(f2tf(vv.w));
        *(float4*)(dst + idx) = o;
    }
}

// ------------------------------------------------------------------
// Projection GEMM (tf32 MMA): 128x128 tile, BK=32, 8 warps x (32x64)
// cp.async 2-stage double buffer; inputs pre-converted. Dynamic smem.
// V output stored transposed [B,H,HD,S].
// ------------------------------------------------------------------
#define PASTR 36
#define PBSTR 136
#define ABUF  (128 * PASTR)        // 4608 floats per A buffer
#define BBUF  (32 * PBSTR)         // 4352 floats per B buffer
#define PSM_B (2 * ABUF)
#define PROJ_SMEM_FLOATS (2 * ABUF + 2 * BBUF)
#define PROJ_SMEM_BYTES  (PROJ_SMEM_FLOATS * 4)

__global__ __launch_bounds__(256, 2) void proj_kernel(
    const float* __restrict__ bq, const float* __restrict__ bk, const float* __restrict__ bv)
{
    extern __shared__ float psm[];

    const float* A; const float* W; const float* bias; float* out;
    if (blockIdx.z == 0)      { A = g_qc; W = g_wq; bias = bq; out = g_Q; }
    else if (blockIdx.z == 1) { A = g_kc; W = g_wk; bias = bk; out = g_K; }
    else                      { A = g_vc; W = g_wv; bias = bv; out = g_V; }

    const int tid  = threadIdx.x;
    const int warp = tid >> 5;
    const int lane = tid & 31;
    const int g    = lane >> 2;
    const int t    = lane & 3;

    const int m0 = blockIdx.y * 128;
    const int n0 = blockIdx.x * 128;
    const int wm = (warp & 3) * 32;
    const int wn = (warp >> 2) * 64;

    const unsigned sbase = (unsigned)__cvta_generic_to_shared(psm);
    const unsigned aB0 = sbase
        + (((wm + (lane & 7) + ((lane >> 3) & 1) * 8) * PASTR + (lane >> 4) * 4) << 2);

    auto prefA = [&](int k0, int buf) {
        const float* src = A + (size_t)m0 * Dc + k0;
        unsigned dstb = sbase + ((buf * ABUF) << 2);
        #pragma unroll
        for (int i = 0; i < 4; i++) {
            int idx = tid + 256 * i;
            int r = idx >> 3, kc = (idx & 7) << 2;
            cpa16(dstb + ((r * PASTR + kc) << 2), src + (size_t)r * Dc + kc);
        }
    };
    auto prefB = [&](int k0, int buf) {
        const float* src = W + (size_t)k0 * Dc + n0;
        unsigned dstb = sbase + ((PSM_B + buf * BBUF) << 2);
        #pragma unroll
        for (int i = 0; i < 4; i++) {
            int idx = tid + 256 * i;
            int r = idx >> 5, nc = (idx & 31) << 2;
            cpa16(dstb + ((r * PBSTR + nc) << 2), src + (size_t)r * Dc + nc);
        }
    };

    float C[2][8][4] = {};

    prefA(0, 0); prefB(0, 0); CP_COMMIT();

    for (int it = 0; it < Dc / 32; it++) {
        CP_WAIT0();
        __syncthreads();
        if (it + 1 < Dc / 32) {
            prefA((it + 1) * 32, (it + 1) & 1);
            prefB((it + 1) * 32, (it + 1) & 1);
            CP_COMMIT();
        }
        const int buf = it & 1;
        const unsigned aBase = aB0 + (unsigned)((buf * ABUF) << 2);
        const float* BsBuf = psm + PSM_B + buf * BBUF;

        #pragma unroll
        for (int ks = 0; ks < 4; ks++) {
            unsigned a[2][4];
            #pragma unroll
            for (int mi = 0; mi < 2; mi++)
                ldsm4(a[mi][0], a[mi][1], a[mi][2], a[mi][3],
                      aBase + (unsigned)((mi * 16 * PASTR + ks * 8) << 2));
            #pragma unroll
            for (int ni = 0; ni < 8; ni++) {
                int bb = (ks * 8 + t) * PBSTR + wn + ni * 8 + g;
                unsigned b0 = __float_as_uint(BsBuf[bb]);
                unsigned b1 = __float_as_uint(BsBuf[bb + 4 * PBSTR]);
                mma8(C[0][ni], a[0][0], a[0][1], a[0][2], a[0][3], b0, b1);
                mma8(C[1][ni], a[1][0], a[1][1], a[1][2], a[1][3], b0, b1);
            }
        }
        __syncthreads();
    }

    const int h = blockIdx.x;
    if (blockIdx.z != 2) {
        #pragma unroll
        for (int mi = 0; mi < 2; mi++) {
            int row0 = m0 + wm + mi * 16 + g;
            #pragma unroll
            for (int ni = 0; ni < 8; ni++) {
                int col = wn + ni * 8 + 2 * t;
                float b0v = bias[n0 + col], b1v = bias[n0 + col + 1];
                int bb0 = row0 >> 11, s0 = row0 & (Sc - 1);
                float* d0 = out + (((size_t)(bb0 * Hc + h)) * Sc + s0) * HDc + col;
                *(float2*)d0 = make_float2(__uint_as_float(f2tf(C[mi][ni][0] + b0v)),
                                           __uint_as_float(f2tf(C[mi][ni][1] + b1v)));
                int r1 = row0 + 8;
                int bb1 = r1 >> 11, s1 = r1 & (Sc - 1);
                float* d1 = out + (((size_t)(bb1 * Hc + h)) * Sc + s1) * HDc + col;
                *(float2*)d1 = make_float2(__uint_as_float(f2tf(C[mi][ni][2] + b0v)),
                                           __uint_as_float(f2tf(C[mi][ni][3] + b1v)));
            }
        }
    } else {
        #pragma unroll
        for (int mi = 0; mi < 2; mi++) {
            int row0 = m0 + wm + mi * 16 + g;
            #pragma unroll
            for (int ni = 0; ni < 8; ni++) {
                int col = wn + ni * 8 + 2 * t;
                float b0v = bias[n0 + col], b1v = bias[n0 + col + 1];
                int bb0 = row0 >> 11, s0 = row0 & (Sc - 1);
                float* base0 = out + ((size_t)(bb0 * Hc + h)) * HDc * Sc;
                base0[(size_t)col * Sc + s0]       = __uint_as_float(f2tf(C[mi][ni][0] + b0v));
                base0[(size_t)(col + 1) * Sc + s0] = __uint_as_float(f2tf(C[mi][ni][1] + b1v));
                int r1 = row0 + 8;
                int bb1 = r1 >> 11, s1 = r1 & (Sc - 1);
                float* base1 = out + ((size_t)(bb1 * Hc + h)) * HDc * Sc;
                base1[(size_t)col * Sc + s1]       = __uint_as_float(f2tf(C[mi][ni][2] + b0v));
                base1[(size_t)(col + 1) * Sc + s1] = __uint_as_float(f2tf(C[mi][ni][3] + b1v));
            }
        }
    }
}

// ------------------------------------------------------------------
// Flash attention, TQ=128, TK=64, cp.async pipelined K/V/mask.
// (unchanged from round 8)
// ------------------------------------------------------------------
#define QSTR  132
#define KSTR  132
#define VTSTR 68
#define SSTR  68
#define MSTR  68

#define SM_Q    0
#define SM_K    (128 * QSTR)
#define SM_VT   (SM_K   + 64 * KSTR)
#define SM_S    (SM_VT  + 128 * VTSTR)
#define SM_MSK  (SM_S   + 128 * SSTR)
#define SM_M    (SM_MSK + 128 * MSTR)
#define SM_L    (SM_M + 128)
#define SM_A    (SM_L + 128)
#define ATTN_SMEM_FLOATS (SM_A + 128)
#define ATTN_SMEM_BYTES  (ATTN_SMEM_FLOATS * 4)

#define NTILE (Sc / 64)

__global__ __launch_bounds__(256, 1) void attn_kernel(
    const unsigned int* __restrict__ mask, float* __restrict__ out)
{
    extern __shared__ float smem[];
    float* sQ   = smem + SM_Q;
    float* sS   = smem + SM_S;
    float* mrow = smem + SM_M;
    float* lrow = smem + SM_L;
    float* arow = smem + SM_A;
    const unsigned int* sMsk = (const unsigned int*)(smem + SM_MSK);

    const int tid  = threadIdx.x;
    const int warp = tid >> 5;
    const int lane = tid & 31;
    const int g    = lane >> 2;
    const int t    = lane & 3;

    const int bh = blockIdx.y;
    const int b  = bh >> 3;
    const int h  = bh & (Hc - 1);
    const int q0 = blockIdx.x * 128;

    const int rw = (warp & 3) * 32;
    const int cw = (warp >> 2) * 32;
    const int dw = (warp >> 2) * 64;

    const float* Qg = g_Q + (size_t)bh * Sc * HDc;
    const float* Kg = g_K + (size_t)bh * Sc * HDc;
    const float* Vg = g_V + (size_t)bh * HDc * Sc;
    const unsigned int* maskb = mask + (size_t)b * Sc * Sc;

    const unsigned sbase = (unsigned)__cvta_generic_to_shared(smem);
    const unsigned aQ = sbase + ((SM_Q  + (rw + (lane & 7) + ((lane >> 3) & 1) * 8) * QSTR  + (lane >> 4) * 4) << 2);
    const unsigned bK = sbase + ((SM_K  + (cw + ((lane >> 4) & 1) * 8 + (lane & 7)) * KSTR  + ((lane >> 3) & 1) * 4) << 2);
    const unsigned aS = sbase + ((SM_S  + (rw + (lane & 7) + ((lane >> 3) & 1) * 8) * SSTR  + (lane >> 4) * 4) << 2);
    const unsigned bV = sbase + ((SM_VT + (dw + ((lane >> 4) & 1) * 8 + (lane & 7)) * VTSTR + ((lane >> 3) & 1) * 4) << 2);

    auto prefK = [&](int kt) {
        const float* src = Kg + (size_t)kt * 64 * HDc;
        #pragma unroll
        for (int i = 0; i < 8; i++) {
            int idx = tid + 256 * i;
            int r = idx >> 5, d = (idx & 31) << 2;
            cpa16(sbase + ((SM_K + r * KSTR + d) << 2), src + (size_t)r * HDc + d);
        }
    };
    auto prefV = [&](int kt) {
        const float* src = Vg + kt * 64;
        #pragma unroll
        for (int i = 0; i < 8; i++) {
            int idx = tid + 256 * i;
            int d = idx >> 4, c4 = (idx & 15) << 2;
            cpa16(sbase + ((SM_VT + d * VTSTR + c4) << 2), src + (size_t)d * Sc + c4);
        }
    };
    auto prefM = [&](int kt) {
        const unsigned int* src = maskb + (size_t)q0 * Sc + kt * 64;
        #pragma unroll
        for (int i = 0; i < 8; i++) {
            int idx = tid + 256 * i;
            int r = idx >> 4, c = (idx & 15) << 2;
            cpa16(sbase + ((SM_MSK + r * MSTR + c) << 2), src + (size_t)r * Sc + c);
        }
    };

    #pragma unroll
    for (int i = 0; i < 16; i++) {
        int idx = tid + 256 * i;
        int r = idx >> 5, d = (idx & 31) << 2;
        *(float4*)(&sQ[r * QSTR + d]) = *(const float4*)(Qg + (size_t)(q0 + r) * HDc + d);
    }
    if (tid < 128) { mrow[tid] = -1e30f; lrow[tid] = 0.0f; }

    prefK(0); CP_COMMIT();
    prefV(0); prefM(0); CP_COMMIT();

    float O[2][8][4] = {};
    const float scale = 0.08838834764831845f;  // 1/sqrt(128)

    for (int kt = 0; kt < NTILE; kt++) {
        const int ktn = (kt + 1 < NTILE) ? kt + 1 : NTILE - 1;

        CP_WAIT1();
        __syncthreads();

        float S[2][4][4] = {};
        #pragma unroll
        for (int ks = 0; ks < 16; ks++) {
            unsigned a[2][4];
            #pragma unroll
            for (int mi = 0; mi < 2; mi++)
                ldsm4(a[mi][0], a[mi][1], a[mi][2], a[mi][3],
                      aQ + (unsigned)(((mi * 16 * QSTR) << 2) + ks * 32));
            #pragma unroll
            for (int nii = 0; nii < 2; nii++) {
                unsigned b0, b1, b2, b3;
                ldsm4(b0, b1, b2, b3, bK + (unsigned)(((nii * 16 * KSTR) << 2) + ks * 32));
                #pragma unroll
                for (int mi = 0; mi < 2; mi++) {
                    mma8(S[mi][nii * 2],     a[mi][0], a[mi][1], a[mi][2], a[mi][3], b0, b1);
                    mma8(S[mi][nii * 2 + 1], a[mi][0], a[mi][1], a[mi][2], a[mi][3], b2, b3);
                }
            }
        }
        #pragma unroll
        for (int mi = 0; mi < 2; mi++) {
            int qr = rw + mi * 16 + g;
            #pragma unroll
            for (int ni = 0; ni < 4; ni++) {
                int col = cw + ni * 8 + 2 * t;
                *(float2*)(&sS[qr * SSTR + col])       = make_float2(S[mi][ni][0], S[mi][ni][1]);
                *(float2*)(&sS[(qr + 8) * SSTR + col]) = make_float2(S[mi][ni][2], S[mi][ni][3]);
            }
        }
        __syncthreads();

        prefK(ktn); CP_COMMIT();

        CP_WAIT1();
        __syncthreads();

        {
            int r  = tid >> 1;
            int qt = tid & 1;
            float* srow = &sS[r * SSTR + qt * 32];
            const uint4* mr4 = (const uint4*)(sMsk + r * MSTR + qt * 32);
            float p[32];
            float rmax = -1e30f;
            #pragma unroll
            for (int j = 0; j < 8; j++) {
                float4 sv = *(const float4*)(&srow[4 * j]);
                uint4  mv = mr4[j];
                p[4*j+0] = (mv.x ? -1e6f : sv.x) * scale;
                p[4*j+1] = (mv.y ? -1e6f : sv.y) * scale;
                p[4*j+2] = (mv.z ? -1e6f : sv.z) * scale;
                p[4*j+3] = (mv.w ? -1e6f : sv.w) * scale;
                #pragma unroll
                for (int e = 0; e < 4; e++) rmax = fmaxf(rmax, p[4*j+e]);
            }
            rmax = fmaxf(rmax, __shfl_xor_sync(0xffffffffu, rmax, 1));
            float mold = mrow[r];
            float mnew = fmaxf(mold, rmax);
            float sum = 0.0f;
            #pragma unroll
            for (int j = 0; j < 8; j++) {
                float4 pv;
                pv.x = __uint_as_float(f2tf(__expf(p[4*j+0] - mnew)));
                pv.y = __uint_as_float(f2tf(__expf(p[4*j+1] - mnew)));
                pv.z = __uint_as_float(f2tf(__expf(p[4*j+2] - mnew)));
                pv.w = __uint_as_float(f2tf(__expf(p[4*j+3] - mnew)));
                sum += pv.x + pv.y + pv.z + pv.w;
                *(float4*)(&srow[4 * j]) = pv;
            }
            sum += __shfl_xor_sync(0xffffffffu, sum, 1);
            if (qt == 0) {
                float al = __expf(mold - mnew);
                mrow[r] = mnew;
                arow[r] = al;
                lrow[r] = lrow[r] * al + sum;
            }
        }
        __syncthreads();

        #pragma unroll
        for (int mi = 0; mi < 2; mi++) {
            float al0 = arow[rw + mi * 16 + g];
            float al1 = arow[rw + mi * 16 + 8 + g];
            #pragma unroll
            for (int ni = 0; ni < 8; ni++) {
                O[mi][ni][0] *= al0; O[mi][ni][1] *= al0;
                O[mi][ni][2] *= al1; O[mi][ni][3] *= al1;
            }
        }
        #pragma unroll
        for (int ks = 0; ks < 8; ks++) {
            unsigned a[2][4];
            #pragma unroll
            for (int mi = 0; mi < 2; mi++)
                ldsm4(a[mi][0], a[mi][1], a[mi][2], a[mi][3],
                      aS + (unsigned)(((mi * 16 * SSTR) << 2) + ks * 32));
            #pragma unroll
            for (int nii = 0; nii < 4; nii++) {
                unsigned b0, b1, b2, b3;
                ldsm4(b0, b1, b2, b3, bV + (unsigned)(((nii * 16 * VTSTR) << 2) + ks * 32));
                #pragma unroll
                for (int mi = 0; mi < 2; mi++) {
                    mma8(O[mi][nii * 2],     a[mi][0], a[mi][1], a[mi][2], a[mi][3], b0, b1);
                    mma8(O[mi][nii * 2 + 1], a[mi][0], a[mi][1], a[mi][2], a[mi][3], b2, b3);
                }
            }
        }
        __syncthreads();

        prefV(ktn); prefM(ktn); CP_COMMIT();
    }

    CP_WAIT0();

    #pragma unroll
    for (int mi = 0; mi < 2; mi++) {
        float linv0 = 1.0f / lrow[rw + mi * 16 + g];
        float linv1 = 1.0f / lrow[rw + mi * 16 + 8 + g];
        int row0 = q0 + rw + mi * 16 + g;
        #pragma unroll
        for (int ni = 0; ni < 8; ni++) {
            int col = dw + ni * 8 + 2 * t;
            float* d0 = out + ((size_t)b * Sc + row0) * Dc + h * HDc + col;
            *(float2*)d0 = make_float2(O[mi][ni][0] * linv0, O[mi][ni][1] * linv0);
            float* d1 = out + ((size_t)b * Sc + row0 + 8) * Dc + h * HDc + col;
            *(float2*)d1 = make_float2(O[mi][ni][2] * linv1, O[mi][ni][3] * linv1);
        }
    }
}

// ------------------------------------------------------------------
extern "C" void kernel_launch(void* const* d_in, const int* in_sizes, int n_in,
                              void* d_out, int out_size)
{
    const float* q  = (const float*)d_in[0];
    const float* k  = (const float*)d_in[1];
    const float* v  = (const float*)d_in[2];
    const unsigned int* mask = (const unsigned int*)d_in[3];
    const float* Wq = (const float*)d_in[4];
    const float* bq = (const float*)d_in[5];
    const float* Wk = (const float*)d_in[6];
    const float* bk = (const float*)d_in[7];
    const float* Wv = (const float*)d_in[8];
    const float* bv = (const float*)d_in[9];
    float* out = (float*)d_out;

    dim3 cgrid(Mc * Dc / 4 / 256, 6);
    cvt_kernel<<<cgrid, 256>>>(q, k, v, Wq, Wk, Wv);

    cudaFuncSetAttribute(proj_kernel,
                         cudaFuncAttributeMaxDynamicSharedMemorySize,
                         PROJ_SMEM_BYTES);
    dim3 pgrid(Dc / 128, Mc / 128, 3);
    proj_kernel<<<pgrid, 256, PROJ_SMEM_BYTES>>>(bq, bk, bv);

    cudaFuncSetAttribute(attn_kernel,
                         cudaFuncAttributeMaxDynamicSharedMemorySize,
                         ATTN_SMEM_BYTES);
    dim3 agrid(Sc / 128, Bc * Hc);
    attn_kernel<<<agrid, 256, ATTN_SMEM_BYTES>>>(mask, out);
}

// round 11
// speedup vs baseline: 4.5033x; 1.0905x over previous
#include <cuda_runtime.h>
#include <math.h>

#define Bc 2
#define Sc 2048
#define Dc 1024
#define Hc 8
#define HDc 128
#define Mc (Bc*Sc)   // 4096

// scratch (tf32-rounded fp32): Q,K as [B,H,S,HD]; V as [B,H,HD,S] (transposed)
__device__ float g_Q[Bc*Hc*Sc*HDc];
__device__ float g_K[Bc*Hc*Sc*HDc];
__device__ float g_V[Bc*Hc*Sc*HDc];
// tf32-rounded copies of inputs
__device__ float g_qc[Mc*Dc];
__device__ float g_kc[Mc*Dc];
__device__ float g_vc[Mc*Dc];
__device__ float g_wq[Dc*Dc];
__device__ float g_wk[Dc*Dc];
__device__ float g_wv[Dc*Dc];

__device__ __forceinline__ unsigned f2tf(float x) {
    unsigned u;
    asm("cvt.rna.tf32.f32 %0, %1;" : "=r"(u) : "f"(x));
    return u;
}

__device__ __forceinline__ void mma8(float* c,
    unsigned a0, unsigned a1, unsigned a2, unsigned a3,
    unsigned b0, unsigned b1)
{
    asm volatile(
        "mma.sync.aligned.m16n8k8.row.col.f32.tf32.tf32.f32 "
        "{%0,%1,%2,%3}, {%4,%5,%6,%7}, {%8,%9}, {%0,%1,%2,%3};"
        : "+f"(c[0]), "+f"(c[1]), "+f"(c[2]), "+f"(c[3])
        : "r"(a0), "r"(a1), "r"(a2), "r"(a3), "r"(b0), "r"(b1));
}

__device__ __forceinline__ void ldsm4(unsigned& r0, unsigned& r1, unsigned& r2, unsigned& r3,
                                      unsigned addr)
{
    asm volatile("ldmatrix.sync.aligned.m8n8.x4.shared.b16 {%0,%1,%2,%3}, [%4];"
        : "=r"(r0), "=r"(r1), "=r"(r2), "=r"(r3) : "r"(addr));
}

__device__ __forceinline__ void cpa16(unsigned dst, const void* src) {
    asm volatile("cp.async.cg.shared.global [%0], [%1], 16;" :: "r"(dst), "l"(src));
}
#define CP_COMMIT() asm volatile("cp.async.commit_group;")
#define CP_WAIT1()  asm volatile("cp.async.wait_group 1;")
#define CP_WAIT0()  asm volatile("cp.async.wait_group 0;")

// ------------------------------------------------------------------
// Pre-convert: tf32-round inputs into scratch.
// ------------------------------------------------------------------
__global__ __launch_bounds__(256) void cvt_kernel(
    const float* __restrict__ q, const float* __restrict__ k, const float* __restrict__ v,
    const float* __restrict__ Wq, const float* __restrict__ Wk, const float* __restrict__ Wv)
{
    const float* src; float* dst; int n;
    switch (blockIdx.y) {
        case 0: src = q;  dst = g_qc; n = Mc*Dc; break;
        case 1: src = k;  dst = g_kc; n = Mc*Dc; break;
        case 2: src = v;  dst = g_vc; n = Mc*Dc; break;
        case 3: src = Wq; dst = g_wq; n = Dc*Dc; break;
        case 4: src = Wk; dst = g_wk; n = Dc*Dc; break;
        default: src = Wv; dst = g_wv; n = Dc*Dc; break;
    }
    int idx = (blockIdx.x * 256 + threadIdx.x) * 4;
    if (idx < n) {
        float4 vv = *(const float4*)(src + idx);
        float4 o;
        o.x = __uint_as_float(f2tf(vv.x));
        o.y = __uint_as_float(f2tf(vv.y));
        o.z = __uint_as_float(f2tf(vv.z));
        o.w = __uint_as_float(f2tf(vv.w));
        *(float4*)(dst + idx) = o;
    }
}

// ------------------------------------------------------------------
// Projection GEMM (tf32 mma.sync): 128x128 tile, BK=32, cp.async 2-stage.
// V output stored transposed [B,H,HD,S].
// ------------------------------------------------------------------
#define PASTR 36
#define PBSTR 136
#define ABUF  (128 * PASTR)
#define BBUF  (32 * PBSTR)
#define PSM_B (2 * ABUF)
#define PROJ_SMEM_FLOATS (2 * ABUF + 2 * BBUF)
#define PROJ_SMEM_BYTES  (PROJ_SMEM_FLOATS * 4)

__global__ __launch_bounds__(256, 2) void proj_kernel(
    const float* __restrict__ bq, const float* __restrict__ bk, const float* __restrict__ bv)
{
    extern __shared__ float psm[];

    const float* A; const float* W; const float* bias; float* out;
    if (blockIdx.z == 0)      { A = g_qc; W = g_wq; bias = bq; out = g_Q; }
    else if (blockIdx.z == 1) { A = g_kc; W = g_wk; bias = bk; out = g_K; }
    else                      { A = g_vc; W = g_wv; bias = bv; out = g_V; }

    const int tid  = threadIdx.x;
    const int warp = tid >> 5;
    const int lane = tid & 31;
    const int g    = lane >> 2;
    const int t    = lane & 3;

    const int m0 = blockIdx.y * 128;
    const int n0 = blockIdx.x * 128;
    const int wm = (warp & 3) * 32;
    const int wn = (warp >> 2) * 64;

    const unsigned sbase = (unsigned)__cvta_generic_to_shared(psm);
    const unsigned aB0 = sbase
        + (((wm + (lane & 7) + ((lane >> 3) & 1) * 8) * PASTR + (lane >> 4) * 4) << 2);

    auto prefA = [&](int k0, int buf) {
        const float* src = A + (size_t)m0 * Dc + k0;
        unsigned dstb = sbase + ((buf * ABUF) << 2);
        #pragma unroll
        for (int i = 0; i < 4; i++) {
            int idx = tid + 256 * i;
            int r = idx >> 3, kc = (idx & 7) << 2;
            cpa16(dstb + ((r * PASTR + kc) << 2), src + (size_t)r * Dc + kc);
        }
    };
    auto prefB = [&](int k0, int buf) {
        const float* src = W + (size_t)k0 * Dc + n0;
        unsigned dstb = sbase + ((PSM_B + buf * BBUF) << 2);
        #pragma unroll
        for (int i = 0; i < 4; i++) {
            int idx = tid + 256 * i;
            int r = idx >> 5, nc = (idx & 31) << 2;
            cpa16(dstb + ((r * PBSTR + nc) << 2), src + (size_t)r * Dc + nc);
        }
    };

    float C[2][8][4] = {};

    prefA(0, 0); prefB(0, 0); CP_COMMIT();

    for (int it = 0; it < Dc / 32; it++) {
        CP_WAIT0();
        __syncthreads();
        if (it + 1 < Dc / 32) {
            prefA((it + 1) * 32, (it + 1) & 1);
            prefB((it + 1) * 32, (it + 1) & 1);
            CP_COMMIT();
        }
        const int buf = it & 1;
        const unsigned aBase = aB0 + (unsigned)((buf * ABUF) << 2);
        const float* BsBuf = psm + PSM_B + buf * BBUF;

        #pragma unroll
        for (int ks = 0; ks < 4; ks++) {
            unsigned a[2][4];
            #pragma unroll
            for (int mi = 0; mi < 2; mi++)
                ldsm4(a[mi][0], a[mi][1], a[mi][2], a[mi][3],
                      aBase + (unsigned)((mi * 16 * PASTR + ks * 8) << 2));
            #pragma unroll
            for (int ni = 0; ni < 8; ni++) {
                int bb = (ks * 8 + t) * PBSTR + wn + ni * 8 + g;
                unsigned b0 = __float_as_uint(BsBuf[bb]);
                unsigned b1 = __float_as_uint(BsBuf[bb + 4 * PBSTR]);
                mma8(C[0][ni], a[0][0], a[0][1], a[0][2], a[0][3], b0, b1);
                mma8(C[1][ni], a[1][0], a[1][1], a[1][2], a[1][3], b0, b1);
            }
        }
        __syncthreads();
    }

    const int h = blockIdx.x;
    if (blockIdx.z != 2) {
        #pragma unroll
        for (int mi = 0; mi < 2; mi++) {
            int row0 = m0 + wm + mi * 16 + g;
            #pragma unroll
            for (int ni = 0; ni < 8; ni++) {
                int col = wn + ni * 8 + 2 * t;
                float b0v = bias[n0 + col], b1v = bias[n0 + col + 1];
                int bb0 = row0 >> 11, s0 = row0 & (Sc - 1);
                float* d0 = out + (((size_t)(bb0 * Hc + h)) * Sc + s0) * HDc + col;
                *(float2*)d0 = make_float2(__uint_as_float(f2tf(C[mi][ni][0] + b0v)),
                                           __uint_as_float(f2tf(C[mi][ni][1] + b1v)));
                int r1 = row0 + 8;
                int bb1 = r1 >> 11, s1 = r1 & (Sc - 1);
                float* d1 = out + (((size_t)(bb1 * Hc + h)) * Sc + s1) * HDc + col;
                *(float2*)d1 = make_float2(__uint_as_float(f2tf(C[mi][ni][2] + b0v)),
                                           __uint_as_float(f2tf(C[mi][ni][3] + b1v)));
            }
        }
    } else {
        #pragma unroll
        for (int mi = 0; mi < 2; mi++) {
            int row0 = m0 + wm + mi * 16 + g;
            #pragma unroll
            for (int ni = 0; ni < 8; ni++) {
                int col = wn + ni * 8 + 2 * t;
                float b0v = bias[n0 + col], b1v = bias[n0 + col + 1];
                int bb0 = row0 >> 11, s0 = row0 & (Sc - 1);
                float* base0 = out + ((size_t)(bb0 * Hc + h)) * HDc * Sc;
                base0[(size_t)col * Sc + s0]       = __uint_as_float(f2tf(C[mi][ni][0] + b0v));
                base0[(size_t)(col + 1) * Sc + s0] = __uint_as_float(f2tf(C[mi][ni][1] + b1v));
                int r1 = row0 + 8;
                int bb1 = r1 >> 11, s1 = r1 & (Sc - 1);
                float* base1 = out + ((size_t)(bb1 * Hc + h)) * HDc * Sc;
                base1[(size_t)col * Sc + s1]       = __uint_as_float(f2tf(C[mi][ni][2] + b0v));
                base1[(size_t)(col + 1) * Sc + s1] = __uint_as_float(f2tf(C[mi][ni][3] + b1v));
            }
        }
    }
}

// ------------------------------------------------------------------
// Flash attention: TQ=128, TK=64, cp.async pipelined, REGISTER softmax.
// Mask prefetched with K (group {K,M}); V in its own group.
// ------------------------------------------------------------------
#define QSTR  132
#define KSTR  132
#define VTSTR 68
#define SSTR  68
#define MSTR  68

#define SM_Q    0
#define SM_K    (128 * QSTR)
#define SM_VT   (SM_K   + 64 * KSTR)
#define SM_S    (SM_VT  + 128 * VTSTR)
#define SM_MSK  (SM_S   + 128 * SSTR)
#define SM_M    (SM_MSK + 128 * MSTR)
#define SM_L    (SM_M + 128)
#define SM_PM   (SM_L + 128)
#define SM_PS   (SM_PM + 256)
#define ATTN_SMEM_FLOATS (SM_PS + 256)
#define ATTN_SMEM_BYTES  (ATTN_SMEM_FLOATS * 4)

#define NTILE (Sc / 64)

__global__ __launch_bounds__(256, 1) void attn_kernel(
    const unsigned int* __restrict__ mask, float* __restrict__ out)
{
    extern __shared__ float smem[];
    float* sQ   = smem + SM_Q;
    float* sS   = smem + SM_S;
    float* mrow = smem + SM_M;
    float* lrow = smem + SM_L;
    float* pmax = smem + SM_PM;   // [r][cg]
    float* psum = smem + SM_PS;   // [r][cg]
    const unsigned int* sMsk = (const unsigned int*)(smem + SM_MSK);

    const int tid  = threadIdx.x;
    const int warp = tid >> 5;
    const int lane = tid & 31;
    const int g    = lane >> 2;
    const int t    = lane & 3;

    const int bh = blockIdx.y;
    const int b  = bh >> 3;
    const int h  = bh & (Hc - 1);
    const int q0 = blockIdx.x * 128;

    const int rw = (warp & 3) * 32;
    const int cg = warp >> 2;
    const int cw = cg * 32;
    const int dw = cg * 64;

    const float* Qg = g_Q + (size_t)bh * Sc * HDc;
    const float* Kg = g_K + (size_t)bh * Sc * HDc;
    const float* Vg = g_V + (size_t)bh * HDc * Sc;
    const unsigned int* maskb = mask + (size_t)b * Sc * Sc;

    const unsigned sbase = (unsigned)__cvta_generic_to_shared(smem);
    const unsigned aQ = sbase + ((SM_Q  + (rw + (lane & 7) + ((lane >> 3) & 1) * 8) * QSTR  + (lane >> 4) * 4) << 2);
    const unsigned bK = sbase + ((SM_K  + (cw + ((lane >> 4) & 1) * 8 + (lane & 7)) * KSTR  + ((lane >> 3) & 1) * 4) << 2);
    const unsigned aS = sbase + ((SM_S  + (rw + (lane & 7) + ((lane >> 3) & 1) * 8) * SSTR  + (lane >> 4) * 4) << 2);
    const unsigned bV = sbase + ((SM_VT + (dw + ((lane >> 4) & 1) * 8 + (lane & 7)) * VTSTR + ((lane >> 3) & 1) * 4) << 2);

    auto prefK = [&](int kt) {
        const float* src = Kg + (size_t)kt * 64 * HDc;
        #pragma unroll
        for (int i = 0; i < 8; i++) {
            int idx = tid + 256 * i;
            int r = idx >> 5, d = (idx & 31) << 2;
            cpa16(sbase + ((SM_K + r * KSTR + d) << 2), src + (size_t)r * HDc + d);
        }
    };
    auto prefV = [&](int kt) {
        const float* src = Vg + kt * 64;
        #pragma unroll
        for (int i = 0; i < 8; i++) {
            int idx = tid + 256 * i;
            int d = idx >> 4, c4 = (idx & 15) << 2;
            cpa16(sbase + ((SM_VT + d * VTSTR + c4) << 2), src + (size_t)d * Sc + c4);
        }
    };
    auto prefM = [&](int kt) {
        const unsigned int* src = maskb + (size_t)q0 * Sc + kt * 64;
        #pragma unroll
        for (int i = 0; i < 8; i++) {
            int idx = tid + 256 * i;
            int r = idx >> 4, c = (idx & 15) << 2;
            cpa16(sbase + ((SM_MSK + r * MSTR + c) << 2), src + (size_t)r * Sc + c);
        }
    };

    #pragma unroll
    for (int i = 0; i < 16; i++) {
        int idx = tid + 256 * i;
        int r = idx >> 5, d = (idx & 31) << 2;
        *(float4*)(&sQ[r * QSTR + d]) = *(const float4*)(Qg + (size_t)(q0 + r) * HDc + d);
    }
    if (tid < 128) { mrow[tid] = -1e30f; lrow[tid] = 0.0f; }

    prefK(0); prefM(0); CP_COMMIT();
    prefV(0); CP_COMMIT();

    float O[2][8][4] = {};
    const float scale = 0.08838834764831845f;  // 1/sqrt(128)

    for (int kt = 0; kt < NTILE; kt++) {
        const int ktn = (kt + 1 < NTILE) ? kt + 1 : NTILE - 1;

        CP_WAIT1();          // {K,M}(kt) landed; V(kt) may pend
        __syncthreads();

        // ---- QK^T: warp tile 32x32, fragments stay in registers ----
        float S[2][4][4] = {};
        #pragma unroll
        for (int ks = 0; ks < 16; ks++) {
            unsigned a[2][4];
            #pragma unroll
            for (int mi = 0; mi < 2; mi++)
                ldsm4(a[mi][0], a[mi][1], a[mi][2], a[mi][3],
                      aQ + (unsigned)(((mi * 16 * QSTR) << 2) + ks * 32));
            #pragma unroll
            for (int nii = 0; nii < 2; nii++) {
                unsigned b0, b1, b2, b3;
                ldsm4(b0, b1, b2, b3, bK + (unsigned)(((nii * 16 * KSTR) << 2) + ks * 32));
                #pragma unroll
                for (int mi = 0; mi < 2; mi++) {
                    mma8(S[mi][nii * 2],     a[mi][0], a[mi][1], a[mi][2], a[mi][3], b0, b1);
                    mma8(S[mi][nii * 2 + 1], a[mi][0], a[mi][1], a[mi][2], a[mi][3], b2, b3);
                }
            }
        }

        // ---- Phase A: mask+scale in regs, warp-local row max -> pmax ----
        #pragma unroll
        for (int mi = 0; mi < 2; mi++) {
            int r0 = rw + mi * 16 + g;
            float mx0 = -1e30f, mx1 = -1e30f;
            #pragma unroll
            for (int ni = 0; ni < 4; ni++) {
                int col = cw + ni * 8 + 2 * t;
                uint2 mv0 = *(const uint2*)(sMsk + r0 * MSTR + col);
                uint2 mv1 = *(const uint2*)(sMsk + (r0 + 8) * MSTR + col);
                float v0 = (mv0.x ? -1e6f : S[mi][ni][0]) * scale;
                float v1 = (mv0.y ? -1e6f : S[mi][ni][1]) * scale;
                float v2 = (mv1.x ? -1e6f : S[mi][ni][2]) * scale;
                float v3 = (mv1.y ? -1e6f : S[mi][ni][3]) * scale;
                S[mi][ni][0] = v0; S[mi][ni][1] = v1;
                S[mi][ni][2] = v2; S[mi][ni][3] = v3;
                mx0 = fmaxf(mx0, fmaxf(v0, v1));
                mx1 = fmaxf(mx1, fmaxf(v2, v3));
            }
            mx0 = fmaxf(mx0, __shfl_xor_sync(0xffffffffu, mx0, 1, 4));
            mx0 = fmaxf(mx0, __shfl_xor_sync(0xffffffffu, mx0, 2, 4));
            mx1 = fmaxf(mx1, __shfl_xor_sync(0xffffffffu, mx1, 1, 4));
            mx1 = fmaxf(mx1, __shfl_xor_sync(0xffffffffu, mx1, 2, 4));
            if (t == 0) {
                pmax[r0 * 2 + cg]       = mx0;
                pmax[(r0 + 8) * 2 + cg] = mx1;
            }
        }
        __syncthreads();     // pmax visible; K + mask buffers consumed

        prefK(ktn); prefM(ktn); CP_COMMIT();

        // ---- Phase B: exp in regs, write P + psum ----
        float av[2][2], mn[2][2];
        #pragma unroll
        for (int mi = 0; mi < 2; mi++) {
            int r0 = rw + mi * 16 + g;
            float M0 = fmaxf(pmax[r0 * 2],       pmax[r0 * 2 + 1]);
            float M1 = fmaxf(pmax[(r0 + 8) * 2], pmax[(r0 + 8) * 2 + 1]);
            float mold0 = mrow[r0], mold1 = mrow[r0 + 8];
            float mnew0 = fmaxf(mold0, M0), mnew1 = fmaxf(mold1, M1);
            float s0 = 0.0f, s1 = 0.0f;
            #pragma unroll
            for (int ni = 0; ni < 4; ni++) {
                float p0 = __uint_as_float(f2tf(__expf(S[mi][ni][0] - mnew0)));
                float p1 = __uint_as_float(f2tf(__expf(S[mi][ni][1] - mnew0)));
                float p2 = __uint_as_float(f2tf(__expf(S[mi][ni][2] - mnew1)));
                float p3 = __uint_as_float(f2tf(__expf(S[mi][ni][3] - mnew1)));
                s0 += p0 + p1;
                s1 += p2 + p3;
                int col = cw + ni * 8 + 2 * t;
                *(float2*)(&sS[r0 * SSTR + col])       = make_float2(p0, p1);
                *(float2*)(&sS[(r0 + 8) * SSTR + col]) = make_float2(p2, p3);
            }
            s0 += __shfl_xor_sync(0xffffffffu, s0, 1, 4);
            s0 += __shfl_xor_sync(0xffffffffu, s0, 2, 4);
            s1 += __shfl_xor_sync(0xffffffffu, s1, 1, 4);
            s1 += __shfl_xor_sync(0xffffffffu, s1, 2, 4);
            if (t == 0) {
                psum[r0 * 2 + cg]       = s0;
                psum[(r0 + 8) * 2 + cg] = s1;
            }
            av[mi][0] = __expf(mold0 - mnew0);
            av[mi][1] = __expf(mold1 - mnew1);
            mn[mi][0] = mnew0;
            mn[mi][1] = mnew1;
        }

        CP_WAIT1();          // V(kt) landed; {K,M}(ktn) may pend
        __syncthreads();     // P + psum visible

        // ---- Phase C: m/l update (owner), O rescale (regs), PV ----
        if (cg == 0 && t == 0) {
            #pragma unroll
            for (int mi = 0; mi < 2; mi++) {
                int r0 = rw + mi * 16 + g;
                lrow[r0]     = lrow[r0]     * av[mi][0] + psum[r0 * 2]       + psum[r0 * 2 + 1];
                lrow[r0 + 8] = lrow[r0 + 8] * av[mi][1] + psum[(r0 + 8) * 2] + psum[(r0 + 8) * 2 + 1];
                mrow[r0]     = mn[mi][0];
                mrow[r0 + 8] = mn[mi][1];
            }
        }
        #pragma unroll
        for (int mi = 0; mi < 2; mi++)
            #pragma unroll
            for (int ni = 0; ni < 8; ni++) {
                O[mi][ni][0] *= av[mi][0]; O[mi][ni][1] *= av[mi][0];
                O[mi][ni][2] *= av[mi][1]; O[mi][ni][3] *= av[mi][1];
            }
        #pragma unroll
        for (int ks = 0; ks < 8; ks++) {
            unsigned a[2][4];
            #pragma unroll
            for (int mi = 0; mi < 2; mi++)
                ldsm4(a[mi][0], a[mi][1], a[mi][2], a[mi][3],
                      aS + (unsigned)(((mi * 16 * SSTR) << 2) + ks * 32));
            #pragma unroll
            for (int nii = 0; nii < 4; nii++) {
                unsigned b0, b1, b2, b3;
                ldsm4(b0, b1, b2, b3, bV + (unsigned)(((nii * 16 * VTSTR) << 2) + ks * 32));
                #pragma unroll
                for (int mi = 0; mi < 2; mi++) {
                    mma8(O[mi][nii * 2],     a[mi][0], a[mi][1], a[mi][2], a[mi][3], b0, b1);
                    mma8(O[mi][nii * 2 + 1], a[mi][0], a[mi][1], a[mi][2], a[mi][3], b2, b3);
                }
            }
        }
        __syncthreads();     // V + sS consumed; lrow/mrow updates visible

        prefV(ktn); CP_COMMIT();
    }

    CP_WAIT0();

    // epilogue
    #pragma unroll
    for (int mi = 0; mi < 2; mi++) {
        float linv0 = 1.0f / lrow[rw + mi * 16 + g];
        float linv1 = 1.0f / lrow[rw + mi * 16 + 8 + g];
        int row0 = q0 + rw + mi * 16 + g;
        #pragma unroll
        for (int ni = 0; ni < 8; ni++) {
            int col = dw + ni * 8 + 2 * t;
            float* d0 = out + ((size_t)b * Sc + row0) * Dc + h * HDc + col;
            *(float2*)d0 = make_float2(O[mi][ni][0] * linv0, O[mi][ni][1] * linv0);
            float* d1 = out + ((size_t)b * Sc + row0 + 8) * Dc + h * HDc + col;
            *(float2*)d1 = make_float2(O[mi][ni][2] * linv1, O[mi][ni][3] * linv1);
        }
    }
}

// ------------------------------------------------------------------
extern "C" void kernel_launch(void* const* d_in, const int* in_sizes, int n_in,
                              void* d_out, int out_size)
{
    const float* q  = (const float*)d_in[0];
    const float* k  = (const float*)d_in[1];
    const float* v  = (const float*)d_in[2];
    const unsigned int* mask = (const unsigned int*)d_in[3];
    const float* Wq = (const float*)d_in[4];
    const float* bq = (const float*)d_in[5];
    const float* Wk = (const float*)d_in[6];
    const float* bk = (const float*)d_in[7];
    const float* Wv = (const float*)d_in[8];
    const float* bv = (const float*)d_in[9];
    float* out = (float*)d_out;

    dim3 cgrid(Mc * Dc / 4 / 256, 6);
    cvt_kernel<<<cgrid, 256>>>(q, k, v, Wq, Wk, Wv);

    cudaFuncSetAttribute(proj_kernel,
                         cudaFuncAttributeMaxDynamicSharedMemorySize,
                         PROJ_SMEM_BYTES);
    dim3 pgrid(Dc / 128, Mc / 128, 3);
    proj_kernel<<<pgrid, 256, PROJ_SMEM_BYTES>>>(bq, bk, bv);

    cudaFuncSetAttribute(attn_kernel,
                         cudaFuncAttributeMaxDynamicSharedMemorySize,
                         ATTN_SMEM_BYTES);
    dim3 agrid(Sc / 128, Bc * Hc);
    attn_kernel<<<agrid, 256, ATTN_SMEM_BYTES>>>(mask, out);
}

// round 12
// speedup vs baseline: 4.5535x; 1.0111x over previous
#include <cuda_runtime.h>
#include <math.h>

#define Bc 2
#define Sc 2048
#define Dc 1024
#define Hc 8
#define HDc 128
#define Mc (Bc*Sc)   // 4096

// scratch (tf32-rounded fp32): Q,K as [B,H,S,HD]; V as [B,H,HD,S] (transposed)
__device__ float g_Q[Bc*Hc*Sc*HDc];
__device__ float g_K[Bc*Hc*Sc*HDc];
__device__ float g_V[Bc*Hc*Sc*HDc];
// tf32-rounded copies of inputs; weights stored TRANSPOSED [n][k]
__device__ float g_qc[Mc*Dc];
__device__ float g_kc[Mc*Dc];
__device__ float g_vc[Mc*Dc];
__device__ float g_wq[Dc*Dc];
__device__ float g_wk[Dc*Dc];
__device__ float g_wv[Dc*Dc];

__device__ __forceinline__ unsigned f2tf(float x) {
    unsigned u;
    asm("cvt.rna.tf32.f32 %0, %1;" : "=r"(u) : "f"(x));
    return u;
}

__device__ __forceinline__ void mma8(float* c,
    unsigned a0, unsigned a1, unsigned a2, unsigned a3,
    unsigned b0, unsigned b1)
{
    asm volatile(
        "mma.sync.aligned.m16n8k8.row.col.f32.tf32.tf32.f32 "
        "{%0,%1,%2,%3}, {%4,%5,%6,%7}, {%8,%9}, {%0,%1,%2,%3};"
        : "+f"(c[0]), "+f"(c[1]), "+f"(c[2]), "+f"(c[3])
        : "r"(a0), "r"(a1), "r"(a2), "r"(a3), "r"(b0), "r"(b1));
}

__device__ __forceinline__ void ldsm4(unsigned& r0, unsigned& r1, unsigned& r2, unsigned& r3,
                                      unsigned addr)
{
    asm volatile("ldmatrix.sync.aligned.m8n8.x4.shared.b16 {%0,%1,%2,%3}, [%4];"
        : "=r"(r0), "=r"(r1), "=r"(r2), "=r"(r3) : "r"(addr));
}

__device__ __forceinline__ void cpa16(unsigned dst, const void* src) {
    asm volatile("cp.async.cg.shared.global [%0], [%1], 16;" :: "r"(dst), "l"(src));
}
#define CP_COMMIT() asm volatile("cp.async.commit_group;")
#define CP_WAIT1()  asm volatile("cp.async.wait_group 1;")
#define CP_WAIT0()  asm volatile("cp.async.wait_group 0;")

// ------------------------------------------------------------------
// cvt: tf32-round q,k,v
// ------------------------------------------------------------------
__global__ __launch_bounds__(256) void cvt_kernel(
    const float* __restrict__ q, const float* __restrict__ k, const float* __restrict__ v)
{
    const float* src; float* dst;
    switch (blockIdx.y) {
        case 0: src = q; dst = g_qc; break;
        case 1: src = k; dst = g_kc; break;
        default: src = v; dst = g_vc; break;
    }
    int idx = (blockIdx.x * 256 + threadIdx.x) * 4;
    float4 vv = *(const float4*)(src + idx);
    float4 o;
    o.x = __uint_as_float(f2tf(vv.x));
    o.y = __uint_as_float(f2tf(vv.y));
    o.z = __uint_as_float(f2tf(vv.z));
    o.w = __uint_as_float(f2tf(vv.w));
    *(float4*)(dst + idx) = o;
}

// cvtT: tf32-round + transpose W -> Wt[n][k]
__global__ __launch_bounds__(256) void cvtT_kernel(
    const float* __restrict__ Wq, const float* __restrict__ Wk, const float* __restrict__ Wv)
{
    __shared__ float tile[32][33];
    const float* src; float* dst;
    switch (blockIdx.z) {
        case 0: src = Wq; dst = g_wq; break;
        case 1: src = Wk; dst = g_wk; break;
        default: src = Wv; dst = g_wv; break;
    }
    int x0 = blockIdx.x * 32, y0 = blockIdx.y * 32;   // x=n, y=k
    int tx = threadIdx.x & 31, ty = threadIdx.x >> 5; // 32 x 8
    #pragma unroll
    for (int j = 0; j < 32; j += 8)
        tile[ty + j][tx] = __uint_as_float(f2tf(src[(size_t)(y0 + ty + j) * Dc + x0 + tx]));
    __syncthreads();
    #pragma unroll
    for (int j = 0; j < 32; j += 8)
        dst[(size_t)(x0 + ty + j) * Dc + y0 + tx] = tile[tx][ty + j];
}

// ------------------------------------------------------------------
// Projection GEMM (tf32 mma.sync): 128x128 tile, BK=32, cp.async 2-stage.
// BOTH operands ldmatrix-fed (Wt stored [n][k]). V output [B,H,HD,S].
// ------------------------------------------------------------------
#define PASTR 36
#define PBT   36
#define ABUF  (128 * PASTR)        // 4608 floats
#define BBUF  (128 * PBT)          // 4608 floats
#define PSM_B (2 * ABUF)
#define PROJ_SMEM_FLOATS (2 * ABUF + 2 * BBUF)
#define PROJ_SMEM_BYTES  (PROJ_SMEM_FLOATS * 4)

__global__ __launch_bounds__(256, 2) void proj_kernel(
    const float* __restrict__ bq, const float* __restrict__ bk, const float* __restrict__ bv)
{
    extern __shared__ float psm[];

    const float* A; const float* Wt; const float* bias; float* out;
    if (blockIdx.z == 0)      { A = g_qc; Wt = g_wq; bias = bq; out = g_Q; }
    else if (blockIdx.z == 1) { A = g_kc; Wt = g_wk; bias = bk; out = g_K; }
    else                      { A = g_vc; Wt = g_wv; bias = bv; out = g_V; }

    const int tid  = threadIdx.x;
    const int warp = tid >> 5;
    const int lane = tid & 31;
    const int g    = lane >> 2;
    const int t    = lane & 3;

    const int m0 = blockIdx.y * 128;
    const int n0 = blockIdx.x * 128;
    const int wm = (warp & 3) * 32;
    const int wn = (warp >> 2) * 64;

    const unsigned sbase = (unsigned)__cvta_generic_to_shared(psm);
    const unsigned aB0 = sbase
        + (((wm + (lane & 7) + ((lane >> 3) & 1) * 8) * PASTR + (lane >> 4) * 4) << 2);
    const unsigned bB0 = sbase + ((PSM_B) << 2)
        + (((wn + ((lane >> 4) & 1) * 8 + (lane & 7)) * PBT + ((lane >> 3) & 1) * 4) << 2);

    auto prefA = [&](int k0, int buf) {
        const float* src = A + (size_t)m0 * Dc + k0;
        unsigned dstb = sbase + ((buf * ABUF) << 2);
        #pragma unroll
        for (int i = 0; i < 4; i++) {
            int idx = tid + 256 * i;
            int r = idx >> 3, kc = (idx & 7) << 2;
            cpa16(dstb + ((r * PASTR + kc) << 2), src + (size_t)r * Dc + kc);
        }
    };
    auto prefB = [&](int k0, int buf) {
        const float* src = Wt + (size_t)n0 * Dc + k0;   // [n][k]
        unsigned dstb = sbase + ((PSM_B + buf * BBUF) << 2);
        #pragma unroll
        for (int i = 0; i < 4; i++) {
            int idx = tid + 256 * i;
            int r = idx >> 3, kc = (idx & 7) << 2;
            cpa16(dstb + ((r * PBT + kc) << 2), src + (size_t)r * Dc + kc);
        }
    };

    float C[2][8][4] = {};

    prefA(0, 0); prefB(0, 0); CP_COMMIT();

    for (int it = 0; it < Dc / 32; it++) {
        CP_WAIT0();
        __syncthreads();
        if (it + 1 < Dc / 32) {
            prefA((it + 1) * 32, (it + 1) & 1);
            prefB((it + 1) * 32, (it + 1) & 1);
            CP_COMMIT();
        }
        const int buf = it & 1;
        const unsigned aBase = aB0 + (unsigned)((buf * ABUF) << 2);
        const unsigned bBase = bB0 + (unsigned)((buf * BBUF) << 2);

        #pragma unroll
        for (int ks = 0; ks < 4; ks++) {
            unsigned a[2][4];
            #pragma unroll
            for (int mi = 0; mi < 2; mi++)
                ldsm4(a[mi][0], a[mi][1], a[mi][2], a[mi][3],
                      aBase + (unsigned)((mi * 16 * PASTR + ks * 8) << 2));
            #pragma unroll
            for (int nii = 0; nii < 4; nii++) {
                unsigned b0, b1, b2, b3;
                ldsm4(b0, b1, b2, b3,
                      bBase + (unsigned)(((nii * 16 * PBT) << 2) + ks * 32));
                #pragma unroll
                for (int mi = 0; mi < 2; mi++) {
                    mma8(C[mi][nii * 2],     a[mi][0], a[mi][1], a[mi][2], a[mi][3], b0, b1);
                    mma8(C[mi][nii * 2 + 1], a[mi][0], a[mi][1], a[mi][2], a[mi][3], b2, b3);
                }
            }
        }
        __syncthreads();
    }

    const int h = blockIdx.x;
    if (blockIdx.z != 2) {
        #pragma unroll
        for (int mi = 0; mi < 2; mi++) {
            int row0 = m0 + wm + mi * 16 + g;
            #pragma unroll
            for (int ni = 0; ni < 8; ni++) {
                int col = wn + ni * 8 + 2 * t;
                float b0v = bias[n0 + col], b1v = bias[n0 + col + 1];
                int bb0 = row0 >> 11, s0 = row0 & (Sc - 1);
                float* d0 = out + (((size_t)(bb0 * Hc + h)) * Sc + s0) * HDc + col;
                *(float2*)d0 = make_float2(__uint_as_float(f2tf(C[mi][ni][0] + b0v)),
                                           __uint_as_float(f2tf(C[mi][ni][1] + b1v)));
                int r1 = row0 + 8;
                int bb1 = r1 >> 11, s1 = r1 & (Sc - 1);
                float* d1 = out + (((size_t)(bb1 * Hc + h)) * Sc + s1) * HDc + col;
                *(float2*)d1 = make_float2(__uint_as_float(f2tf(C[mi][ni][2] + b0v)),
                                           __uint_as_float(f2tf(C[mi][ni][3] + b1v)));
            }
        }
    } else {
        #pragma unroll
        for (int mi = 0; mi < 2; mi++) {
            int row0 = m0 + wm + mi * 16 + g;
            #pragma unroll
            for (int ni = 0; ni < 8; ni++) {
                int col = wn + ni * 8 + 2 * t;
                float b0v = bias[n0 + col], b1v = bias[n0 + col + 1];
                int bb0 = row0 >> 11, s0 = row0 & (Sc - 1);
                float* base0 = out + ((size_t)(bb0 * Hc + h)) * HDc * Sc;
                base0[(size_t)col * Sc + s0]       = __uint_as_float(f2tf(C[mi][ni][0] + b0v));
                base0[(size_t)(col + 1) * Sc + s0] = __uint_as_float(f2tf(C[mi][ni][1] + b1v));
                int r1 = row0 + 8;
                int bb1 = r1 >> 11, s1 = r1 & (Sc - 1);
                float* base1 = out + ((size_t)(bb1 * Hc + h)) * HDc * Sc;
                base1[(size_t)col * Sc + s1]       = __uint_as_float(f2tf(C[mi][ni][2] + b0v));
                base1[(size_t)(col + 1) * Sc + s1] = __uint_as_float(f2tf(C[mi][ni][3] + b1v));
            }
        }
    }
}

// ------------------------------------------------------------------
// Flash attention (unchanged from round 11): TQ=128, TK=64, cp.async
// pipelined, register softmax, mask staged with K.
// ------------------------------------------------------------------
#define QSTR  132
#define KSTR  132
#define VTSTR 68
#define SSTR  68
#define MSTR  68

#define SM_Q    0
#define SM_K    (128 * QSTR)
#define SM_VT   (SM_K   + 64 * KSTR)
#define SM_S    (SM_VT  + 128 * VTSTR)
#define SM_MSK  (SM_S   + 128 * SSTR)
#define SM_M    (SM_MSK + 128 * MSTR)
#define SM_L    (SM_M + 128)
#define SM_PM   (SM_L + 128)
#define SM_PS   (SM_PM + 256)
#define ATTN_SMEM_FLOATS (SM_PS + 256)
#define ATTN_SMEM_BYTES  (ATTN_SMEM_FLOATS * 4)

#define NTILE (Sc / 64)

__global__ __launch_bounds__(256, 1) void attn_kernel(
    const unsigned int* __restrict__ mask, float* __restrict__ out)
{
    extern __shared__ float smem[];
    float* sQ   = smem + SM_Q;
    float* sS   = smem + SM_S;
    float* mrow = smem + SM_M;
    float* lrow = smem + SM_L;
    float* pmax = smem + SM_PM;
    float* psum = smem + SM_PS;
    const unsigned int* sMsk = (const unsigned int*)(smem + SM_MSK);

    const int tid  = threadIdx.x;
    const int warp = tid >> 5;
    const int lane = tid & 31;
    const int g    = lane >> 2;
    const int t    = lane & 3;

    const int bh = blockIdx.y;
    const int b  = bh >> 3;
    const int h  = bh & (Hc - 1);
    const int q0 = blockIdx.x * 128;

    const int rw = (warp & 3) * 32;
    const int cg = warp >> 2;
    const int cw = cg * 32;
    const int dw = cg * 64;

    const float* Qg = g_Q + (size_t)bh * Sc * HDc;
    const float* Kg = g_K + (size_t)bh * Sc * HDc;
    const float* Vg = g_V + (size_t)bh * HDc * Sc;
    const unsigned int* maskb = mask + (size_t)b * Sc * Sc;

    const unsigned sbase = (unsigned)__cvta_generic_to_shared(smem);
    const unsigned aQ = sbase + ((SM_Q  + (rw + (lane & 7) + ((lane >> 3) & 1) * 8) * QSTR  + (lane >> 4) * 4) << 2);
    const unsigned bK = sbase + ((SM_K  + (cw + ((lane >> 4) & 1) * 8 + (lane & 7)) * KSTR  + ((lane >> 3) & 1) * 4) << 2);
    const unsigned aS = sbase + ((SM_S  + (rw + (lane & 7) + ((lane >> 3) & 1) * 8) * SSTR  + (lane >> 4) * 4) << 2);
    const unsigned bV = sbase + ((SM_VT + (dw + ((lane >> 4) & 1) * 8 + (lane & 7)) * VTSTR + ((lane >> 3) & 1) * 4) << 2);

    auto prefK = [&](int kt) {
        const float* src = Kg + (size_t)kt * 64 * HDc;
        #pragma unroll
        for (int i = 0; i < 8; i++) {
            int idx = tid + 256 * i;
            int r = idx >> 5, d = (idx & 31) << 2;
            cpa16(sbase + ((SM_K + r * KSTR + d) << 2), src + (size_t)r * HDc + d);
        }
    };
    auto prefV = [&](int kt) {
        const float* src = Vg + kt * 64;
        #pragma unroll
        for (int i = 0; i < 8; i++) {
            int idx = tid + 256 * i;
            int d = idx >> 4, c4 = (idx & 15) << 2;
            cpa16(sbase + ((SM_VT + d * VTSTR + c4) << 2), src + (size_t)d * Sc + c4);
        }
    };
    auto prefM = [&](int kt) {
        const unsigned int* src = maskb + (size_t)q0 * Sc + kt * 64;
        #pragma unroll
        for (int i = 0; i < 8; i++) {
            int idx = tid + 256 * i;
            int r = idx >> 4, c = (idx & 15) << 2;
            cpa16(sbase + ((SM_MSK + r * MSTR + c) << 2), src + (size_t)r * Sc + c);
        }
    };

    #pragma unroll
    for (int i = 0; i < 16; i++) {
        int idx = tid + 256 * i;
        int r = idx >> 5, d = (idx & 31) << 2;
        *(float4*)(&sQ[r * QSTR + d]) = *(const float4*)(Qg + (size_t)(q0 + r) * HDc + d);
    }
    if (tid < 128) { mrow[tid] = -1e30f; lrow[tid] = 0.0f; }

    prefK(0); prefM(0); CP_COMMIT();
    prefV(0); CP_COMMIT();

    float O[2][8][4] = {};
    const float scale = 0.08838834764831845f;  // 1/sqrt(128)

    for (int kt = 0; kt < NTILE; kt++) {
        const int ktn = (kt + 1 < NTILE) ? kt + 1 : NTILE - 1;

        CP_WAIT1();
        __syncthreads();

        float S[2][4][4] = {};
        #pragma unroll
        for (int ks = 0; ks < 16; ks++) {
            unsigned a[2][4];
            #pragma unroll
            for (int mi = 0; mi < 2; mi++)
                ldsm4(a[mi][0], a[mi][1], a[mi][2], a[mi][3],
                      aQ + (unsigned)(((mi * 16 * QSTR) << 2) + ks * 32));
            #pragma unroll
            for (int nii = 0; nii < 2; nii++) {
                unsigned b0, b1, b2, b3;
                ldsm4(b0, b1, b2, b3, bK + (unsigned)(((nii * 16 * KSTR) << 2) + ks * 32));
                #pragma unroll
                for (int mi = 0; mi < 2; mi++) {
                    mma8(S[mi][nii * 2],     a[mi][0], a[mi][1], a[mi][2], a[mi][3], b0, b1);
                    mma8(S[mi][nii * 2 + 1], a[mi][0], a[mi][1], a[mi][2], a[mi][3], b2, b3);
                }
            }
        }

        #pragma unroll
        for (int mi = 0; mi < 2; mi++) {
            int r0 = rw + mi * 16 + g;
            float mx0 = -1e30f, mx1 = -1e30f;
            #pragma unroll
            for (int ni = 0; ni < 4; ni++) {
                int col = cw + ni * 8 + 2 * t;
                uint2 mv0 = *(const uint2*)(sMsk + r0 * MSTR + col);
                uint2 mv1 = *(const uint2*)(sMsk + (r0 + 8) * MSTR + col);
                float v0 = (mv0.x ? -1e6f : S[mi][ni][0]) * scale;
                float v1 = (mv0.y ? -1e6f : S[mi][ni][1]) * scale;
                float v2 = (mv1.x ? -1e6f : S[mi][ni][2]) * scale;
                float v3 = (mv1.y ? -1e6f : S[mi][ni][3]) * scale;
                S[mi][ni][0] = v0; S[mi][ni][1] = v1;
                S[mi][ni][2] = v2; S[mi][ni][3] = v3;
                mx0 = fmaxf(mx0, fmaxf(v0, v1));
                mx1 = fmaxf(mx1, fmaxf(v2, v3));
            }
            mx0 = fmaxf(mx0, __shfl_xor_sync(0xffffffffu, mx0, 1, 4));
            mx0 = fmaxf(mx0, __shfl_xor_sync(0xffffffffu, mx0, 2, 4));
            mx1 = fmaxf(mx1, __shfl_xor_sync(0xffffffffu, mx1, 1, 4));
            mx1 = fmaxf(mx1, __shfl_xor_sync(0xffffffffu, mx1, 2, 4));
            if (t == 0) {
                pmax[r0 * 2 + cg]       = mx0;
                pmax[(r0 + 8) * 2 + cg] = mx1;
            }
        }
        __syncthreads();

        prefK(ktn); prefM(ktn); CP_COMMIT();

        float av[2][2], mn[2][2];
        #pragma unroll
        for (int mi = 0; mi < 2; mi++) {
            int r0 = rw + mi * 16 + g;
            float M0 = fmaxf(pmax[r0 * 2],       pmax[r0 * 2 + 1]);
            float M1 = fmaxf(pmax[(r0 + 8) * 2], pmax[(r0 + 8) * 2 + 1]);
            float mold0 = mrow[r0], mold1 = mrow[r0 + 8];
            float mnew0 = fmaxf(mold0, M0), mnew1 = fmaxf(mold1, M1);
            float s0 = 0.0f, s1 = 0.0f;
            #pragma unroll
            for (int ni = 0; ni < 4; ni++) {
                float p0 = __uint_as_float(f2tf(__expf(S[mi][ni][0] - mnew0)));
                float p1 = __uint_as_float(f2tf(__expf(S[mi][ni][1] - mnew0)));
                float p2 = __uint_as_float(f2tf(__expf(S[mi][ni][2] - mnew1)));
                float p3 = __uint_as_float(f2tf(__expf(S[mi][ni][3] - mnew1)));
                s0 += p0 + p1;
                s1 += p2 + p3;
                int col = cw + ni * 8 + 2 * t;
                *(float2*)(&sS[r0 * SSTR + col])       = make_float2(p0, p1);
                *(float2*)(&sS[(r0 + 8) * SSTR + col]) = make_float2(p2, p3);
            }
            s0 += __shfl_xor_sync(0xffffffffu, s0, 1, 4);
            s0 += __shfl_xor_sync(0xffffffffu, s0, 2, 4);
            s1 += __shfl_xor_sync(0xffffffffu, s1, 1, 4);
            s1 += __shfl_xor_sync(0xffffffffu, s1, 2, 4);
            if (t == 0) {
                psum[r0 * 2 + cg]       = s0;
                psum[(r0 + 8) * 2 + cg] = s1;
            }
            av[mi][0] = __expf(mold0 - mnew0);
            av[mi][1] = __expf(mold1 - mnew1);
            mn[mi][0] = mnew0;
            mn[mi][1] = mnew1;
        }

        CP_WAIT1();
        __syncthreads();

        if (cg == 0 && t == 0) {
            #pragma unroll
            for (int mi = 0; mi < 2; mi++) {
                int r0 = rw + mi * 16 + g;
                lrow[r0]     = lrow[r0]     * av[mi][0] + psum[r0 * 2]       + psum[r0 * 2 + 1];
                lrow[r0 + 8] = lrow[r0 + 8] * av[mi][1] + psum[(r0 + 8) * 2] + psum[(r0 + 8) * 2 + 1];
                mrow[r0]     = mn[mi][0];
                mrow[r0 + 8] = mn[mi][1];
            }
        }
        #pragma unroll
        for (int mi = 0; mi < 2; mi++)
            #pragma unroll
            for (int ni = 0; ni < 8; ni++) {
                O[mi][ni][0] *= av[mi][0]; O[mi][ni][1] *= av[mi][0];
                O[mi][ni][2] *= av[mi][1]; O[mi][ni][3] *= av[mi][1];
            }
        #pragma unroll
        for (int ks = 0; ks < 8; ks++) {
            unsigned a[2][4];
            #pragma unroll
            for (int mi = 0; mi < 2; mi++)
                ldsm4(a[mi][0], a[mi][1], a[mi][2], a[mi][3],
                      aS + (unsigned)(((mi * 16 * SSTR) << 2) + ks * 32));
            #pragma unroll
            for (int nii = 0; nii < 4; nii++) {
                unsigned b0, b1, b2, b3;
                ldsm4(b0, b1, b2, b3, bV + (unsigned)(((nii * 16 * VTSTR) << 2) + ks * 32));
                #pragma unroll
                for (int mi = 0; mi < 2; mi++) {
                    mma8(O[mi][nii * 2],     a[mi][0], a[mi][1], a[mi][2], a[mi][3], b0, b1);
                    mma8(O[mi][nii * 2 + 1], a[mi][0], a[mi][1], a[mi][2], a[mi][3], b2, b3);
                }
            }
        }
        __syncthreads();

        prefV(ktn); CP_COMMIT();
    }

    CP_WAIT0();

    #pragma unroll
    for (int mi = 0; mi < 2; mi++) {
        float linv0 = 1.0f / lrow[rw + mi * 16 + g];
        float linv1 = 1.0f / lrow[rw + mi * 16 + 8 + g];
        int row0 = q0 + rw + mi * 16 + g;
        #pragma unroll
        for (int ni = 0; ni < 8; ni++) {
            int col = dw + ni * 8 + 2 * t;
            float* d0 = out + ((size_t)b * Sc + row0) * Dc + h * HDc + col;
            *(float2*)d0 = make_float2(O[mi][ni][0] * linv0, O[mi][ni][1] * linv0);
            float* d1 = out + ((size_t)b * Sc + row0 + 8) * Dc + h * HDc + col;
            *(float2*)d1 = make_float2(O[mi][ni][2] * linv1, O[mi][ni][3] * linv1);
        }
    }
}

// ------------------------------------------------------------------
extern "C" void kernel_launch(void* const* d_in, const int* in_sizes, int n_in,
                              void* d_out, int out_size)
{
    const float* q  = (const float*)d_in[0];
    const float* k  = (const float*)d_in[1];
    const float* v  = (const float*)d_in[2];
    const unsigned int* mask = (const unsigned int*)d_in[3];
    const float* Wq = (const float*)d_in[4];
    const float* bq = (const float*)d_in[5];
    const float* Wk = (const float*)d_in[6];
    const float* bk = (const float*)d_in[7];
    const float* Wv = (const float*)d_in[8];
    const float* bv = (const float*)d_in[9];
    float* out = (float*)d_out;

    dim3 cgrid(Mc * Dc / 4 / 256, 3);
    cvt_kernel<<<cgrid, 256>>>(q, k, v);
    dim3 tgrid(Dc / 32, Dc / 32, 3);
    cvtT_kernel<<<tgrid, 256>>>(Wq, Wk, Wv);

    cudaFuncSetAttribute(proj_kernel,
                         cudaFuncAttributeMaxDynamicSharedMemorySize,
                         PROJ_SMEM_BYTES);
    dim3 pgrid(Dc / 128, Mc / 128, 3);
    proj_kernel<<<pgrid, 256, PROJ_SMEM_BYTES>>>(bq, bk, bv);

    cudaFuncSetAttribute(attn_kernel,
                         cudaFuncAttributeMaxDynamicSharedMemorySize,
                         ATTN_SMEM_BYTES);
    dim3 agrid(Sc / 128, Bc * Hc);
    attn_kernel<<<agrid, 256, ATTN_SMEM_BYTES>>>(mask, out);
}

// round 13
// speedup vs baseline: 4.6707x; 1.0257x over previous
#include <cuda_runtime.h>
#include <math.h>

#define Bc 2
#define Sc 2048
#define Dc 1024
#define Hc 8
#define HDc 128
#define Mc (Bc*Sc)   // 4096

// scratch (tf32-rounded fp32): Q,K as [B,H,S,HD]; V as [B,H,HD,S] (transposed)
__device__ float g_Q[Bc*Hc*Sc*HDc];
__device__ float g_K[Bc*Hc*Sc*HDc];
__device__ float g_V[Bc*Hc*Sc*HDc];
// weights tf32-rounded + TRANSPOSED [n][k]
__device__ float g_wq[Dc*Dc];
__device__ float g_wk[Dc*Dc];
__device__ float g_wv[Dc*Dc];
// byte-packed mask (nonzero -> 1)
__device__ unsigned char g_mb[Bc*Sc*Sc];

__device__ __forceinline__ unsigned f2tf(float x) {
    unsigned u;
    asm("cvt.rna.tf32.f32 %0, %1;" : "=r"(u) : "f"(x));
    return u;
}

__device__ __forceinline__ void mma8(float* c,
    unsigned a0, unsigned a1, unsigned a2, unsigned a3,
    unsigned b0, unsigned b1)
{
    asm volatile(
        "mma.sync.aligned.m16n8k8.row.col.f32.tf32.tf32.f32 "
        "{%0,%1,%2,%3}, {%4,%5,%6,%7}, {%8,%9}, {%0,%1,%2,%3};"
        : "+f"(c[0]), "+f"(c[1]), "+f"(c[2]), "+f"(c[3])
        : "r"(a0), "r"(a1), "r"(a2), "r"(a3), "r"(b0), "r"(b1));
}

__device__ __forceinline__ void ldsm4(unsigned& r0, unsigned& r1, unsigned& r2, unsigned& r3,
                                      unsigned addr)
{
    asm volatile("ldmatrix.sync.aligned.m8n8.x4.shared.b16 {%0,%1,%2,%3}, [%4];"
        : "=r"(r0), "=r"(r1), "=r"(r2), "=r"(r3) : "r"(addr));
}

__device__ __forceinline__ void cpa16(unsigned dst, const void* src) {
    asm volatile("cp.async.cg.shared.global [%0], [%1], 16;" :: "r"(dst), "l"(src));
}
#define CP_COMMIT() asm volatile("cp.async.commit_group;")
#define CP_WAIT1()  asm volatile("cp.async.wait_group 1;")
#define CP_WAIT0()  asm volatile("cp.async.wait_group 0;")

// ------------------------------------------------------------------
// maskpack: uint32 bool -> packed bytes (nonzero -> 1)
// ------------------------------------------------------------------
__global__ __launch_bounds__(256) void maskpack_kernel(const unsigned int* __restrict__ m)
{
    size_t i = ((size_t)blockIdx.x * 256 + threadIdx.x) * 16;
    uint4 a0 = *(const uint4*)(m + i);
    uint4 a1 = *(const uint4*)(m + i + 4);
    uint4 a2 = *(const uint4*)(m + i + 8);
    uint4 a3 = *(const uint4*)(m + i + 12);
    unsigned p0 = (a0.x?1u:0u) | (a0.y?0x100u:0u) | (a0.z?0x10000u:0u) | (a0.w?0x1000000u:0u);
    unsigned p1 = (a1.x?1u:0u) | (a1.y?0x100u:0u) | (a1.z?0x10000u:0u) | (a1.w?0x1000000u:0u);
    unsigned p2 = (a2.x?1u:0u) | (a2.y?0x100u:0u) | (a2.z?0x10000u:0u) | (a2.w?0x1000000u:0u);
    unsigned p3 = (a3.x?1u:0u) | (a3.y?0x100u:0u) | (a3.z?0x10000u:0u) | (a3.w?0x1000000u:0u);
    uint4 o = {p0, p1, p2, p3};
    *(uint4*)(g_mb + i) = o;
}

// cvtT: tf32-round + transpose W -> Wt[n][k]
__global__ __launch_bounds__(256) void cvtT_kernel(
    const float* __restrict__ Wq, const float* __restrict__ Wk, const float* __restrict__ Wv)
{
    __shared__ float tile[32][33];
    const float* src; float* dst;
    switch (blockIdx.z) {
        case 0: src = Wq; dst = g_wq; break;
        case 1: src = Wk; dst = g_wk; break;
        default: src = Wv; dst = g_wv; break;
    }
    int x0 = blockIdx.x * 32, y0 = blockIdx.y * 32;   // x=n, y=k
    int tx = threadIdx.x & 31, ty = threadIdx.x >> 5; // 32 x 8
    #pragma unroll
    for (int j = 0; j < 32; j += 8)
        tile[ty + j][tx] = __uint_as_float(f2tf(src[(size_t)(y0 + ty + j) * Dc + x0 + tx]));
    __syncthreads();
    #pragma unroll
    for (int j = 0; j < 32; j += 8)
        dst[(size_t)(x0 + ty + j) * Dc + y0 + tx] = tile[tx][ty + j];
}

// ------------------------------------------------------------------
// Projection GEMM (tf32 mma.sync): 128x128 tile, BK=32, cp.async 2-stage.
// A read RAW from inputs, tf32-rounded on fragments post-ldmatrix.
// Wt pre-rounded [n][k]; both operands ldmatrix-fed. V output [B,H,HD,S].
// ------------------------------------------------------------------
#define PASTR 36
#define PBT   36
#define ABUF  (128 * PASTR)
#define BBUF  (128 * PBT)
#define PSM_B (2 * ABUF)
#define PROJ_SMEM_FLOATS (2 * ABUF + 2 * BBUF)
#define PROJ_SMEM_BYTES  (PROJ_SMEM_FLOATS * 4)

__global__ __launch_bounds__(256, 2) void proj_kernel(
    const float* __restrict__ q, const float* __restrict__ k, const float* __restrict__ v,
    const float* __restrict__ bq, const float* __restrict__ bk, const float* __restrict__ bv)
{
    extern __shared__ float psm[];

    const float* A; const float* Wt; const float* bias; float* out;
    if (blockIdx.z == 0)      { A = q; Wt = g_wq; bias = bq; out = g_Q; }
    else if (blockIdx.z == 1) { A = k; Wt = g_wk; bias = bk; out = g_K; }
    else                      { A = v; Wt = g_wv; bias = bv; out = g_V; }

    const int tid  = threadIdx.x;
    const int warp = tid >> 5;
    const int lane = tid & 31;
    const int g    = lane >> 2;
    const int t    = lane & 3;

    const int m0 = blockIdx.y * 128;
    const int n0 = blockIdx.x * 128;
    const int wm = (warp & 3) * 32;
    const int wn = (warp >> 2) * 64;

    const unsigned sbase = (unsigned)__cvta_generic_to_shared(psm);
    const unsigned aB0 = sbase
        + (((wm + (lane & 7) + ((lane >> 3) & 1) * 8) * PASTR + (lane >> 4) * 4) << 2);
    const unsigned bB0 = sbase + ((PSM_B) << 2)
        + (((wn + ((lane >> 4) & 1) * 8 + (lane & 7)) * PBT + ((lane >> 3) & 1) * 4) << 2);

    auto prefA = [&](int k0, int buf) {
        const float* src = A + (size_t)m0 * Dc + k0;
        unsigned dstb = sbase + ((buf * ABUF) << 2);
        #pragma unroll
        for (int i = 0; i < 4; i++) {
            int idx = tid + 256 * i;
            int r = idx >> 3, kc = (idx & 7) << 2;
            cpa16(dstb + ((r * PASTR + kc) << 2), src + (size_t)r * Dc + kc);
        }
    };
    auto prefB = [&](int k0, int buf) {
        const float* src = Wt + (size_t)n0 * Dc + k0;   // [n][k]
        unsigned dstb = sbase + ((PSM_B + buf * BBUF) << 2);
        #pragma unroll
        for (int i = 0; i < 4; i++) {
            int idx = tid + 256 * i;
            int r = idx >> 3, kc = (idx & 7) << 2;
            cpa16(dstb + ((r * PBT + kc) << 2), src + (size_t)r * Dc + kc);
        }
    };

    float C[2][8][4] = {};

    prefA(0, 0); prefB(0, 0); CP_COMMIT();

    for (int it = 0; it < Dc / 32; it++) {
        CP_WAIT0();
        __syncthreads();
        if (it + 1 < Dc / 32) {
            prefA((it + 1) * 32, (it + 1) & 1);
            prefB((it + 1) * 32, (it + 1) & 1);
            CP_COMMIT();
        }
        const int buf = it & 1;
        const unsigned aBase = aB0 + (unsigned)((buf * ABUF) << 2);
        const unsigned bBase = bB0 + (unsigned)((buf * BBUF) << 2);

        #pragma unroll
        for (int ks = 0; ks < 4; ks++) {
            unsigned a[2][4];
            #pragma unroll
            for (int mi = 0; mi < 2; mi++) {
                ldsm4(a[mi][0], a[mi][1], a[mi][2], a[mi][3],
                      aBase + (unsigned)((mi * 16 * PASTR + ks * 8) << 2));
                // tf32-round raw A fragments (bit-identical to pre-rounding)
                a[mi][0] = f2tf(__uint_as_float(a[mi][0]));
                a[mi][1] = f2tf(__uint_as_float(a[mi][1]));
                a[mi][2] = f2tf(__uint_as_float(a[mi][2]));
                a[mi][3] = f2tf(__uint_as_float(a[mi][3]));
            }
            #pragma unroll
            for (int nii = 0; nii < 4; nii++) {
                unsigned b0, b1, b2, b3;
                ldsm4(b0, b1, b2, b3,
                      bBase + (unsigned)(((nii * 16 * PBT) << 2) + ks * 32));
                #pragma unroll
                for (int mi = 0; mi < 2; mi++) {
                    mma8(C[mi][nii * 2],     a[mi][0], a[mi][1], a[mi][2], a[mi][3], b0, b1);
                    mma8(C[mi][nii * 2 + 1], a[mi][0], a[mi][1], a[mi][2], a[mi][3], b2, b3);
                }
            }
        }
        __syncthreads();
    }

    const int h = blockIdx.x;
    if (blockIdx.z != 2) {
        #pragma unroll
        for (int mi = 0; mi < 2; mi++) {
            int row0 = m0 + wm + mi * 16 + g;
            #pragma unroll
            for (int ni = 0; ni < 8; ni++) {
                int col = wn + ni * 8 + 2 * t;
                float b0v = bias[n0 + col], b1v = bias[n0 + col + 1];
                int bb0 = row0 >> 11, s0 = row0 & (Sc - 1);
                float* d0 = out + (((size_t)(bb0 * Hc + h)) * Sc + s0) * HDc + col;
                *(float2*)d0 = make_float2(__uint_as_float(f2tf(C[mi][ni][0] + b0v)),
                                           __uint_as_float(f2tf(C[mi][ni][1] + b1v)));
                int r1 = row0 + 8;
                int bb1 = r1 >> 11, s1 = r1 & (Sc - 1);
                float* d1 = out + (((size_t)(bb1 * Hc + h)) * Sc + s1) * HDc + col;
                *(float2*)d1 = make_float2(__uint_as_float(f2tf(C[mi][ni][2] + b0v)),
                                           __uint_as_float(f2tf(C[mi][ni][3] + b1v)));
            }
        }
    } else {
        #pragma unroll
        for (int mi = 0; mi < 2; mi++) {
            int row0 = m0 + wm + mi * 16 + g;
            #pragma unroll
            for (int ni = 0; ni < 8; ni++) {
                int col = wn + ni * 8 + 2 * t;
                float b0v = bias[n0 + col], b1v = bias[n0 + col + 1];
                int bb0 = row0 >> 11, s0 = row0 & (Sc - 1);
                float* base0 = out + ((size_t)(bb0 * Hc + h)) * HDc * Sc;
                base0[(size_t)col * Sc + s0]       = __uint_as_float(f2tf(C[mi][ni][0] + b0v));
                base0[(size_t)(col + 1) * Sc + s0] = __uint_as_float(f2tf(C[mi][ni][1] + b1v));
                int r1 = row0 + 8;
                int bb1 = r1 >> 11, s1 = r1 & (Sc - 1);
                float* base1 = out + ((size_t)(bb1 * Hc + h)) * HDc * Sc;
                base1[(size_t)col * Sc + s1]       = __uint_as_float(f2tf(C[mi][ni][2] + b0v));
                base1[(size_t)(col + 1) * Sc + s1] = __uint_as_float(f2tf(C[mi][ni][3] + b1v));
            }
        }
    }
}

// ------------------------------------------------------------------
// Flash attention: TQ=128, TK=64, cp.async pipelined, register softmax.
// Mask = packed bytes (stride 80B/row), staged with K.
// ------------------------------------------------------------------
#define QSTR  132
#define KSTR  132
#define VTSTR 68
#define SSTR  68
#define MROWB 80     // mask row stride in BYTES

#define SM_Q    0
#define SM_K    (128 * QSTR)
#define SM_VT   (SM_K   + 64 * KSTR)
#define SM_S    (SM_VT  + 128 * VTSTR)
#define SM_MSKF (SM_S   + 128 * SSTR)          // 128*80B = 2560 floats
#define SM_M    (SM_MSKF + 2560)
#define SM_L    (SM_M + 128)
#define SM_PM   (SM_L + 128)
#define SM_PS   (SM_PM + 256)
#define ATTN_SMEM_FLOATS (SM_PS + 256)
#define ATTN_SMEM_BYTES  (ATTN_SMEM_FLOATS * 4)

#define NTILE (Sc / 64)

__global__ __launch_bounds__(256, 1) void attn_kernel(float* __restrict__ out)
{
    extern __shared__ float smem[];
    float* sQ   = smem + SM_Q;
    float* sS   = smem + SM_S;
    float* mrow = smem + SM_M;
    float* lrow = smem + SM_L;
    float* pmax = smem + SM_PM;
    float* psum = smem + SM_PS;
    const unsigned char* sMskB = (const unsigned char*)(smem + SM_MSKF);

    const int tid  = threadIdx.x;
    const int warp = tid >> 5;
    const int lane = tid & 31;
    const int g    = lane >> 2;
    const int t    = lane & 3;

    const int bh = blockIdx.y;
    const int b  = bh >> 3;
    const int h  = bh & (Hc - 1);
    const int q0 = blockIdx.x * 128;

    const int rw = (warp & 3) * 32;
    const int cg = warp >> 2;
    const int cw = cg * 32;
    const int dw = cg * 64;

    const float* Qg = g_Q + (size_t)bh * Sc * HDc;
    const float* Kg = g_K + (size_t)bh * Sc * HDc;
    const float* Vg = g_V + (size_t)bh * HDc * Sc;
    const unsigned char* maskb = g_mb + (size_t)b * Sc * Sc;

    const unsigned sbase = (unsigned)__cvta_generic_to_shared(smem);
    const unsigned aQ = sbase + ((SM_Q  + (rw + (lane & 7) + ((lane >> 3) & 1) * 8) * QSTR  + (lane >> 4) * 4) << 2);
    const unsigned bK = sbase + ((SM_K  + (cw + ((lane >> 4) & 1) * 8 + (lane & 7)) * KSTR  + ((lane >> 3) & 1) * 4) << 2);
    const unsigned aS = sbase + ((SM_S  + (rw + (lane & 7) + ((lane >> 3) & 1) * 8) * SSTR  + (lane >> 4) * 4) << 2);
    const unsigned bV = sbase + ((SM_VT + (dw + ((lane >> 4) & 1) * 8 + (lane & 7)) * VTSTR + ((lane >> 3) & 1) * 4) << 2);
    const unsigned mskBase = sbase + (SM_MSKF << 2);

    auto prefK = [&](int kt) {
        const float* src = Kg + (size_t)kt * 64 * HDc;
        #pragma unroll
        for (int i = 0; i < 8; i++) {
            int idx = tid + 256 * i;
            int r = idx >> 5, d = (idx & 31) << 2;
            cpa16(sbase + ((SM_K + r * KSTR + d) << 2), src + (size_t)r * HDc + d);
        }
    };
    auto prefV = [&](int kt) {
        const float* src = Vg + kt * 64;
        #pragma unroll
        for (int i = 0; i < 8; i++) {
            int idx = tid + 256 * i;
            int d = idx >> 4, c4 = (idx & 15) << 2;
            cpa16(sbase + ((SM_VT + d * VTSTR + c4) << 2), src + (size_t)d * Sc + c4);
        }
    };
    auto prefM = [&](int kt) {
        const unsigned char* src = maskb + (size_t)q0 * Sc + kt * 64;
        #pragma unroll
        for (int i = 0; i < 2; i++) {
            int idx = tid + 256 * i;          // 0..511
            int r = idx >> 2, c16 = (idx & 3) << 4;
            cpa16(mskBase + (unsigned)(r * MROWB + c16), src + (size_t)r * Sc + c16);
        }
    };

    #pragma unroll
    for (int i = 0; i < 16; i++) {
        int idx = tid + 256 * i;
        int r = idx >> 5, d = (idx & 31) << 2;
        *(float4*)(&sQ[r * QSTR + d]) = *(const float4*)(Qg + (size_t)(q0 + r) * HDc + d);
    }
    if (tid < 128) { mrow[tid] = -1e30f; lrow[tid] = 0.0f; }

    prefK(0); prefM(0); CP_COMMIT();
    prefV(0); CP_COMMIT();

    float O[2][8][4] = {};
    const float scale = 0.08838834764831845f;  // 1/sqrt(128)

    for (int kt = 0; kt < NTILE; kt++) {
        const int ktn = (kt + 1 < NTILE) ? kt + 1 : NTILE - 1;

        CP_WAIT1();
        __syncthreads();

        float S[2][4][4] = {};
        #pragma unroll
        for (int ks = 0; ks < 16; ks++) {
            unsigned a[2][4];
            #pragma unroll
            for (int mi = 0; mi < 2; mi++)
                ldsm4(a[mi][0], a[mi][1], a[mi][2], a[mi][3],
                      aQ + (unsigned)(((mi * 16 * QSTR) << 2) + ks * 32));
            #pragma unroll
            for (int nii = 0; nii < 2; nii++) {
                unsigned b0, b1, b2, b3;
                ldsm4(b0, b1, b2, b3, bK + (unsigned)(((nii * 16 * KSTR) << 2) + ks * 32));
                #pragma unroll
                for (int mi = 0; mi < 2; mi++) {
                    mma8(S[mi][nii * 2],     a[mi][0], a[mi][1], a[mi][2], a[mi][3], b0, b1);
                    mma8(S[mi][nii * 2 + 1], a[mi][0], a[mi][1], a[mi][2], a[mi][3], b2, b3);
                }
            }
        }

        // Phase A: mask+scale in regs, partial row max -> pmax
        #pragma unroll
        for (int mi = 0; mi < 2; mi++) {
            int r0 = rw + mi * 16 + g;
            float mx0 = -1e30f, mx1 = -1e30f;
            #pragma unroll
            for (int ni = 0; ni < 4; ni++) {
                int col = cw + ni * 8 + 2 * t;
                unsigned char m00 = sMskB[r0 * MROWB + col];
                unsigned char m01 = sMskB[r0 * MROWB + col + 1];
                unsigned char m10 = sMskB[(r0 + 8) * MROWB + col];
                unsigned char m11 = sMskB[(r0 + 8) * MROWB + col + 1];
                float v0 = (m00 ? -1e6f : S[mi][ni][0]) * scale;
                float v1 = (m01 ? -1e6f : S[mi][ni][1]) * scale;
                float v2 = (m10 ? -1e6f : S[mi][ni][2]) * scale;
                float v3 = (m11 ? -1e6f : S[mi][ni][3]) * scale;
                S[mi][ni][0] = v0; S[mi][ni][1] = v1;
                S[mi][ni][2] = v2; S[mi][ni][3] = v3;
                mx0 = fmaxf(mx0, fmaxf(v0, v1));
                mx1 = fmaxf(mx1, fmaxf(v2, v3));
            }
            mx0 = fmaxf(mx0, __shfl_xor_sync(0xffffffffu, mx0, 1, 4));
            mx0 = fmaxf(mx0, __shfl_xor_sync(0xffffffffu, mx0, 2, 4));
            mx1 = fmaxf(mx1, __shfl_xor_sync(0xffffffffu, mx1, 1, 4));
            mx1 = fmaxf(mx1, __shfl_xor_sync(0xffffffffu, mx1, 2, 4));
            if (t == 0) {
                pmax[r0 * 2 + cg]       = mx0;
                pmax[(r0 + 8) * 2 + cg] = mx1;
            }
        }
        __syncthreads();

        prefK(ktn); prefM(ktn); CP_COMMIT();

        // Phase B: exp in regs, write P + psum
        float av[2][2], mn[2][2];
        #pragma unroll
        for (int mi = 0; mi < 2; mi++) {
            int r0 = rw + mi * 16 + g;
            float M0 = fmaxf(pmax[r0 * 2],       pmax[r0 * 2 + 1]);
            float M1 = fmaxf(pmax[(r0 + 8) * 2], pmax[(r0 + 8) * 2 + 1]);
            float mold0 = mrow[r0], mold1 = mrow[r0 + 8];
            float mnew0 = fmaxf(mold0, M0), mnew1 = fmaxf(mold1, M1);
            float s0 = 0.0f, s1 = 0.0f;
            #pragma unroll
            for (int ni = 0; ni < 4; ni++) {
                float p0 = __uint_as_float(f2tf(__expf(S[mi][ni][0] - mnew0)));
                float p1 = __uint_as_float(f2tf(__expf(S[mi][ni][1] - mnew0)));
                float p2 = __uint_as_float(f2tf(__expf(S[mi][ni][2] - mnew1)));
                float p3 = __uint_as_float(f2tf(__expf(S[mi][ni][3] - mnew1)));
                s0 += p0 + p1;
                s1 += p2 + p3;
                int col = cw + ni * 8 + 2 * t;
                *(float2*)(&sS[r0 * SSTR + col])       = make_float2(p0, p1);
                *(float2*)(&sS[(r0 + 8) * SSTR + col]) = make_float2(p2, p3);
            }
            s0 += __shfl_xor_sync(0xffffffffu, s0, 1, 4);
            s0 += __shfl_xor_sync(0xffffffffu, s0, 2, 4);
            s1 += __shfl_xor_sync(0xffffffffu, s1, 1, 4);
            s1 += __shfl_xor_sync(0xffffffffu, s1, 2, 4);
            if (t == 0) {
                psum[r0 * 2 + cg]       = s0;
                psum[(r0 + 8) * 2 + cg] = s1;
            }
            av[mi][0] = __expf(mold0 - mnew0);
            av[mi][1] = __expf(mold1 - mnew1);
            mn[mi][0] = mnew0;
            mn[mi][1] = mnew1;
        }

        CP_WAIT1();
        __syncthreads();

        // Phase C: m/l update, O rescale, PV
        if (cg == 0 && t == 0) {
            #pragma unroll
            for (int mi = 0; mi < 2; mi++) {
                int r0 = rw + mi * 16 + g;
                lrow[r0]     = lrow[r0]     * av[mi][0] + psum[r0 * 2]       + psum[r0 * 2 + 1];
                lrow[r0 + 8] = lrow[r0 + 8] * av[mi][1] + psum[(r0 + 8) * 2] + psum[(r0 + 8) * 2 + 1];
                mrow[r0]     = mn[mi][0];
                mrow[r0 + 8] = mn[mi][1];
            }
        }
        #pragma unroll
        for (int mi = 0; mi < 2; mi++)
            #pragma unroll
            for (int ni = 0; ni < 8; ni++) {
                O[mi][ni][0] *= av[mi][0]; O[mi][ni][1] *= av[mi][0];
                O[mi][ni][2] *= av[mi][1]; O[mi][ni][3] *= av[mi][1];
            }
        #pragma unroll
        for (int ks = 0; ks < 8; ks++) {
            unsigned a[2][4];
            #pragma unroll
            for (int mi = 0; mi < 2; mi++)
                ldsm4(a[mi][0], a[mi][1], a[mi][2], a[mi][3],
                      aS + (unsigned)(((mi * 16 * SSTR) << 2) + ks * 32));
            #pragma unroll
            for (int nii = 0; nii < 4; nii++) {
                unsigned b0, b1, b2, b3;
                ldsm4(b0, b1, b2, b3, bV + (unsigned)(((nii * 16 * VTSTR) << 2) + ks * 32));
                #pragma unroll
                for (int mi = 0; mi < 2; mi++) {
                    mma8(O[mi][nii * 2],     a[mi][0], a[mi][1], a[mi][2], a[mi][3], b0, b1);
                    mma8(O[mi][nii * 2 + 1], a[mi][0], a[mi][1], a[mi][2], a[mi][3], b2, b3);
                }
            }
        }
        __syncthreads();

        prefV(ktn); CP_COMMIT();
    }

    CP_WAIT0();

    #pragma unroll
    for (int mi = 0; mi < 2; mi++) {
        float linv0 = 1.0f / lrow[rw + mi * 16 + g];
        float linv1 = 1.0f / lrow[rw + mi * 16 + 8 + g];
        int row0 = q0 + rw + mi * 16 + g;
        #pragma unroll
        for (int ni = 0; ni < 8; ni++) {
            int col = dw + ni * 8 + 2 * t;
            float* d0 = out + ((size_t)b * Sc + row0) * Dc + h * HDc + col;
            *(float2*)d0 = make_float2(O[mi][ni][0] * linv0, O[mi][ni][1] * linv0);
            float* d1 = out + ((size_t)b * Sc + row0 + 8) * Dc + h * HDc + col;
            *(float2*)d1 = make_float2(O[mi][ni][2] * linv1, O[mi][ni][3] * linv1);
        }
    }
}

// ------------------------------------------------------------------
extern "C" void kernel_launch(void* const* d_in, const int* in_sizes, int n_in,
                              void* d_out, int out_size)
{
    const float* q  = (const float*)d_in[0];
    const float* k  = (const float*)d_in[1];
    const float* v  = (const float*)d_in[2];
    const unsigned int* mask = (const unsigned int*)d_in[3];
    const float* Wq = (const float*)d_in[4];
    const float* bq = (const float*)d_in[5];
    const float* Wk = (const float*)d_in[6];
    const float* bk = (const float*)d_in[7];
    const float* Wv = (const float*)d_in[8];
    const float* bv = (const float*)d_in[9];
    float* out = (float*)d_out;

    maskpack_kernel<<<(Bc * Sc * Sc) / 16 / 256, 256>>>(mask);
    dim3 tgrid(Dc / 32, Dc / 32, 3);
    cvtT_kernel<<<tgrid, 256>>>(Wq, Wk, Wv);

    cudaFuncSetAttribute(proj_kernel,
                         cudaFuncAttributeMaxDynamicSharedMemorySize,
                         PROJ_SMEM_BYTES);
    dim3 pgrid(Dc / 128, Mc / 128, 3);
    proj_kernel<<<pgrid, 256, PROJ_SMEM_BYTES>>>(q, k, v, bq, bk, bv);

    cudaFuncSetAttribute(attn_kernel,
                         cudaFuncAttributeMaxDynamicSharedMemorySize,
                         ATTN_SMEM_BYTES);
    dim3 agrid(Sc / 128, Bc * Hc);
    attn_kernel<<<agrid, 256, ATTN_SMEM_BYTES>>>(out);
}

// round 14
// speedup vs baseline: 6.8404x; 1.4645x over previous
#include <cuda_runtime.h>
#include <cuda_fp16.h>
#include <math.h>

#define Bc 2
#define Sc 2048
#define Dc 1024
#define Hc 8
#define HDc 128
#define Mc (Bc*Sc)   // 4096

// fp16 scratch: Q,K as [B,H,S,HD]; V as [B,H,HD,S] (transposed)
__device__ __half g_Qh[Bc*Hc*Sc*HDc];
__device__ __half g_Kh[Bc*Hc*Sc*HDc];
__device__ __half g_Vh[Bc*Hc*Sc*HDc];
// fp16 inputs (flat [m][k]) and weights TRANSPOSED [n][k]
__device__ __half g_qh[Mc*Dc];
__device__ __half g_kh[Mc*Dc];
__device__ __half g_vh[Mc*Dc];
__device__ __half g_wqh[Dc*Dc];
__device__ __half g_wkh[Dc*Dc];
__device__ __half g_wvh[Dc*Dc];
// byte-packed mask (nonzero -> 1)
__device__ unsigned char g_mb[Bc*Sc*Sc];

__device__ __forceinline__ void mma16(float* c,
    unsigned a0, unsigned a1, unsigned a2, unsigned a3,
    unsigned b0, unsigned b1)
{
    asm volatile(
        "mma.sync.aligned.m16n8k16.row.col.f32.f16.f16.f32 "
        "{%0,%1,%2,%3}, {%4,%5,%6,%7}, {%8,%9}, {%0,%1,%2,%3};"
        : "+f"(c[0]), "+f"(c[1]), "+f"(c[2]), "+f"(c[3])
        : "r"(a0), "r"(a1), "r"(a2), "r"(a3), "r"(b0), "r"(b1));
}

__device__ __forceinline__ void ldsm4(unsigned& r0, unsigned& r1, unsigned& r2, unsigned& r3,
                                      unsigned addr)
{
    asm volatile("ldmatrix.sync.aligned.m8n8.x4.shared.b16 {%0,%1,%2,%3}, [%4];"
        : "=r"(r0), "=r"(r1), "=r"(r2), "=r"(r3) : "r"(addr));
}

__device__ __forceinline__ void cpa16(unsigned dst, const void* src) {
    asm volatile("cp.async.cg.shared.global [%0], [%1], 16;" :: "r"(dst), "l"(src));
}
#define CP_COMMIT() asm volatile("cp.async.commit_group;")
#define CP_WAIT1()  asm volatile("cp.async.wait_group 1;")
#define CP_WAIT0()  asm volatile("cp.async.wait_group 0;")

// ------------------------------------------------------------------
// maskpack: uint32 bool -> packed bytes (nonzero -> 1)
// ------------------------------------------------------------------
__global__ __launch_bounds__(256) void maskpack_kernel(const unsigned int* __restrict__ m)
{
    size_t i = ((size_t)blockIdx.x * 256 + threadIdx.x) * 16;
    uint4 a0 = *(const uint4*)(m + i);
    uint4 a1 = *(const uint4*)(m + i + 4);
    uint4 a2 = *(const uint4*)(m + i + 8);
    uint4 a3 = *(const uint4*)(m + i + 12);
    unsigned p0 = (a0.x?1u:0u) | (a0.y?0x100u:0u) | (a0.z?0x10000u:0u) | (a0.w?0x1000000u:0u);
    unsigned p1 = (a1.x?1u:0u) | (a1.y?0x100u:0u) | (a1.z?0x10000u:0u) | (a1.w?0x1000000u:0u);
    unsigned p2 = (a2.x?1u:0u) | (a2.y?0x100u:0u) | (a2.z?0x10000u:0u) | (a2.w?0x1000000u:0u);
    unsigned p3 = (a3.x?1u:0u) | (a3.y?0x100u:0u) | (a3.z?0x10000u:0u) | (a3.w?0x1000000u:0u);
    uint4 o = {p0, p1, p2, p3};
    *(uint4*)(g_mb + i) = o;
}

// ------------------------------------------------------------------
// cvt: fp32 -> fp16 for q,k,v
// ------------------------------------------------------------------
__global__ __launch_bounds__(256) void cvt_kernel(
    const float* __restrict__ q, const float* __restrict__ k, const float* __restrict__ v)
{
    const float* src; __half* dst;
    switch (blockIdx.y) {
        case 0: src = q; dst = g_qh; break;
        case 1: src = k; dst = g_kh; break;
        default: src = v; dst = g_vh; break;
    }
    size_t idx = ((size_t)blockIdx.x * 256 + threadIdx.x) * 8;
    float4 v0 = *(const float4*)(src + idx);
    float4 v1 = *(const float4*)(src + idx + 4);
    __half2 h0 = __floats2half2_rn(v0.x, v0.y);
    __half2 h1 = __floats2half2_rn(v0.z, v0.w);
    __half2 h2 = __floats2half2_rn(v1.x, v1.y);
    __half2 h3 = __floats2half2_rn(v1.z, v1.w);
    uint4 o = {*(unsigned*)&h0, *(unsigned*)&h1, *(unsigned*)&h2, *(unsigned*)&h3};
    *(uint4*)(dst + idx) = o;
}

// cvtT: fp16-round + transpose W -> Wt[n][k]
__global__ __launch_bounds__(256) void cvtT_kernel(
    const float* __restrict__ Wq, const float* __restrict__ Wk, const float* __restrict__ Wv)
{
    __shared__ float tile[32][33];
    const float* src; __half* dst;
    switch (blockIdx.z) {
        case 0: src = Wq; dst = g_wqh; break;
        case 1: src = Wk; dst = g_wkh; break;
        default: src = Wv; dst = g_wvh; break;
    }
    int x0 = blockIdx.x * 32, y0 = blockIdx.y * 32;   // x=n, y=k
    int tx = threadIdx.x & 31, ty = threadIdx.x >> 5;
    #pragma unroll
    for (int j = 0; j < 32; j += 8)
        tile[ty + j][tx] = src[(size_t)(y0 + ty + j) * Dc + x0 + tx];
    __syncthreads();
    #pragma unroll
    for (int j = 0; j < 32; j += 8)
        dst[(size_t)(x0 + ty + j) * Dc + y0 + tx] = __float2half_rn(tile[tx][ty + j]);
}

// ------------------------------------------------------------------
// Projection GEMM (fp16 m16n8k16): 128x128 tile, BK=64, cp.async 2-stage.
// Both operands ldmatrix-fed. V output stored transposed [B,H,HD,S].
// ------------------------------------------------------------------
#define PSTRB 144                 // row stride bytes (64 halves + 8 pad)
#define ABUFB (128 * PSTRB)       // 18432 B
#define PSMB_B (2 * ABUFB)
#define PROJ_SMEM_BYTES (4 * ABUFB)   // 73728 B

__global__ __launch_bounds__(256, 2) void proj_kernel(
    const float* __restrict__ bq, const float* __restrict__ bk, const float* __restrict__ bv)
{
    extern __shared__ char psm[];

    const __half* A; const __half* Wt; const float* bias; __half* out;
    if (blockIdx.z == 0)      { A = g_qh; Wt = g_wqh; bias = bq; out = g_Qh; }
    else if (blockIdx.z == 1) { A = g_kh; Wt = g_wkh; bias = bk; out = g_Kh; }
    else                      { A = g_vh; Wt = g_wvh; bias = bv; out = g_Vh; }

    const int tid  = threadIdx.x;
    const int warp = tid >> 5;
    const int lane = tid & 31;
    const int g    = lane >> 2;
    const int t    = lane & 3;

    const int m0 = blockIdx.y * 128;
    const int n0 = blockIdx.x * 128;
    const int wm = (warp & 3) * 32;
    const int wn = (warp >> 2) * 64;

    const unsigned sbase = (unsigned)__cvta_generic_to_shared(psm);
    const unsigned aB0 = sbase + (unsigned)((wm + (lane & 15)) * PSTRB + (lane >> 4) * 16);
    const unsigned bB0 = sbase + (unsigned)(PSMB_B + (wn + (lane & 15)) * PSTRB + (lane >> 4) * 16);

    auto prefA = [&](int it, int buf) {
        const __half* src = A + (size_t)m0 * Dc + it * 64;
        unsigned dstb = sbase + (unsigned)(buf * ABUFB);
        #pragma unroll
        for (int i = 0; i < 4; i++) {
            int idx = tid + 256 * i;
            int r = idx >> 3, c = idx & 7;
            cpa16(dstb + (unsigned)(r * PSTRB + c * 16), src + (size_t)r * Dc + c * 8);
        }
    };
    auto prefB = [&](int it, int buf) {
        const __half* src = Wt + (size_t)n0 * Dc + it * 64;
        unsigned dstb = sbase + (unsigned)(PSMB_B + buf * ABUFB);
        #pragma unroll
        for (int i = 0; i < 4; i++) {
            int idx = tid + 256 * i;
            int r = idx >> 3, c = idx & 7;
            cpa16(dstb + (unsigned)(r * PSTRB + c * 16), src + (size_t)r * Dc + c * 8);
        }
    };

    float C[2][8][4] = {};

    prefA(0, 0); prefB(0, 0); CP_COMMIT();

    for (int it = 0; it < 16; it++) {
        CP_WAIT0();
        __syncthreads();
        if (it + 1 < 16) {
            prefA(it + 1, (it + 1) & 1);
            prefB(it + 1, (it + 1) & 1);
            CP_COMMIT();
        }
        const int buf = it & 1;
        const unsigned aBase = aB0 + (unsigned)(buf * ABUFB);
        const unsigned bBase = bB0 + (unsigned)(buf * ABUFB);

        #pragma unroll
        for (int ks = 0; ks < 4; ks++) {
            unsigned a[2][4];
            #pragma unroll
            for (int mi = 0; mi < 2; mi++)
                ldsm4(a[mi][0], a[mi][1], a[mi][2], a[mi][3],
                      aBase + (unsigned)(mi * 16 * PSTRB + ks * 32));
            #pragma unroll
            for (int nb = 0; nb < 4; nb++) {
                unsigned b0, b1, b2, b3;
                ldsm4(b0, b1, b2, b3, bBase + (unsigned)(nb * 16 * PSTRB + ks * 32));
                #pragma unroll
                for (int mi = 0; mi < 2; mi++) {
                    mma16(C[mi][nb * 2],     a[mi][0], a[mi][1], a[mi][2], a[mi][3], b0, b2);
                    mma16(C[mi][nb * 2 + 1], a[mi][0], a[mi][1], a[mi][2], a[mi][3], b1, b3);
                }
            }
        }
        __syncthreads();
    }

    const int h = blockIdx.x;
    if (blockIdx.z != 2) {
        #pragma unroll
        for (int mi = 0; mi < 2; mi++) {
            int row0 = m0 + wm + mi * 16 + g;
            #pragma unroll
            for (int ni = 0; ni < 8; ni++) {
                int col = wn + ni * 8 + 2 * t;
                float b0v = bias[n0 + col], b1v = bias[n0 + col + 1];
                int bb0 = row0 >> 11, s0 = row0 & (Sc - 1);
                __half2 o0 = __floats2half2_rn(C[mi][ni][0] + b0v, C[mi][ni][1] + b1v);
                *(__half2*)(out + (((size_t)(bb0 * Hc + h)) * Sc + s0) * HDc + col) = o0;
                int r1 = row0 + 8;
                int bb1 = r1 >> 11, s1 = r1 & (Sc - 1);
                __half2 o1 = __floats2half2_rn(C[mi][ni][2] + b0v, C[mi][ni][3] + b1v);
                *(__half2*)(out + (((size_t)(bb1 * Hc + h)) * Sc + s1) * HDc + col) = o1;
            }
        }
    } else {
        #pragma unroll
        for (int mi = 0; mi < 2; mi++) {
            int row0 = m0 + wm + mi * 16 + g;
            #pragma unroll
            for (int ni = 0; ni < 8; ni++) {
                int col = wn + ni * 8 + 2 * t;
                float b0v = bias[n0 + col], b1v = bias[n0 + col + 1];
                int bb0 = row0 >> 11, s0 = row0 & (Sc - 1);
                __half* base0 = out + ((size_t)(bb0 * Hc + h)) * HDc * Sc;
                base0[(size_t)col * Sc + s0]       = __float2half_rn(C[mi][ni][0] + b0v);
                base0[(size_t)(col + 1) * Sc + s0] = __float2half_rn(C[mi][ni][1] + b1v);
                int r1 = row0 + 8;
                int bb1 = r1 >> 11, s1 = r1 & (Sc - 1);
                __half* base1 = out + ((size_t)(bb1 * Hc + h)) * HDc * Sc;
                base1[(size_t)col * Sc + s1]       = __float2half_rn(C[mi][ni][2] + b0v);
                base1[(size_t)(col + 1) * Sc + s1] = __float2half_rn(C[mi][ni][3] + b1v);
            }
        }
    }
}

// ------------------------------------------------------------------
// Flash attention (fp16 m16n8k16): TQ=128, TK=64, cp.async pipelined,
// register softmax, byte mask staged with K.
// ------------------------------------------------------------------
#define QSTRB  272    // 128 halves + 8 pad
#define KSTRB  272
#define VSTRB  144    // 64 halves + 8 pad
#define SSTRB  144
#define SSTRH  72
#define MROWB  80

#define SMB_Q    0
#define SMB_K    (128 * QSTRB)                 // 34816
#define SMB_VT   (SMB_K + 64 * KSTRB)          // 52224
#define SMB_S    (SMB_VT + 128 * VSTRB)        // 70656
#define SMB_MSK  (SMB_S + 128 * SSTRB)         // 89088
#define SMB_M    (SMB_MSK + 128 * MROWB)       // 99328
#define SMB_L    (SMB_M + 512)
#define SMB_PM   (SMB_L + 512)
#define SMB_PS   (SMB_PM + 1024)
#define ATTN_SMEM_BYTES (SMB_PS + 1024)        // 102400

#define NTILE (Sc / 64)

__global__ __launch_bounds__(256, 1) void attn_kernel(float* __restrict__ out)
{
    extern __shared__ char smem[];
    __half* sSh  = (__half*)(smem + SMB_S);
    float* mrow = (float*)(smem + SMB_M);
    float* lrow = (float*)(smem + SMB_L);
    float* pmax = (float*)(smem + SMB_PM);
    float* psum = (float*)(smem + SMB_PS);
    const unsigned char* sMskB = (const unsigned char*)(smem + SMB_MSK);

    const int tid  = threadIdx.x;
    const int warp = tid >> 5;
    const int lane = tid & 31;
    const int g    = lane >> 2;
    const int t    = lane & 3;

    const int bh = blockIdx.y;
    const int b  = bh >> 3;
    const int h  = bh & (Hc - 1);
    const int q0 = blockIdx.x * 128;

    const int rw = (warp & 3) * 32;
    const int cg = warp >> 2;
    const int cw = cg * 32;
    const int dw = cg * 64;

    const __half* Qg = g_Qh + (size_t)bh * Sc * HDc;
    const __half* Kg = g_Kh + (size_t)bh * Sc * HDc;
    const __half* Vg = g_Vh + (size_t)bh * HDc * Sc;
    const unsigned char* maskb = g_mb + (size_t)b * Sc * Sc;

    const unsigned sbase = (unsigned)__cvta_generic_to_shared(smem);
    const unsigned aQ = sbase + (unsigned)(SMB_Q  + (rw + (lane & 15)) * QSTRB + (lane >> 4) * 16);
    const unsigned bK = sbase + (unsigned)(SMB_K  + (cw + (lane & 15)) * KSTRB + (lane >> 4) * 16);
    const unsigned aS = sbase + (unsigned)(SMB_S  + (rw + (lane & 15)) * SSTRB + (lane >> 4) * 16);
    const unsigned bV = sbase + (unsigned)(SMB_VT + (dw + (lane & 15)) * VSTRB + (lane >> 4) * 16);

    auto prefK = [&](int kt) {
        const __half* src = Kg + (size_t)kt * 64 * HDc;
        #pragma unroll
        for (int i = 0; i < 4; i++) {
            int idx = tid + 256 * i;
            int r = idx >> 4, c = idx & 15;
            cpa16(sbase + (unsigned)(SMB_K + r * KSTRB + c * 16), src + (size_t)r * HDc + c * 8);
        }
    };
    auto prefV = [&](int kt) {
        const __half* src = Vg + kt * 64;
        #pragma unroll
        for (int i = 0; i < 4; i++) {
            int idx = tid + 256 * i;
            int d = idx >> 3, c = idx & 7;
            cpa16(sbase + (unsigned)(SMB_VT + d * VSTRB + c * 16), src + (size_t)d * Sc + c * 8);
        }
    };
    auto prefM = [&](int kt) {
        const unsigned char* src = maskb + (size_t)q0 * Sc + kt * 64;
        #pragma unroll
        for (int i = 0; i < 2; i++) {
            int idx = tid + 256 * i;
            int r = idx >> 2, c16 = (idx & 3) << 4;
            cpa16(sbase + (unsigned)(SMB_MSK + r * MROWB + c16), src + (size_t)r * Sc + c16);
        }
    };

    // Q tile: 128 rows x 128 halves
    #pragma unroll
    for (int i = 0; i < 8; i++) {
        int idx = tid + 256 * i;
        int r = idx >> 4, c = idx & 15;
        *(uint4*)(smem + SMB_Q + r * QSTRB + c * 16) =
            *(const uint4*)(Qg + (size_t)(q0 + r) * HDc + c * 8);
    }
    if (tid < 128) { mrow[tid] = -1e30f; lrow[tid] = 0.0f; }

    prefK(0); prefM(0); CP_COMMIT();
    prefV(0); CP_COMMIT();

    float O[2][8][4] = {};
    const float scale = 0.08838834764831845f;  // 1/sqrt(128)

    for (int kt = 0; kt < NTILE; kt++) {
        const int ktn = (kt + 1 < NTILE) ? kt + 1 : NTILE - 1;

        CP_WAIT1();          // {K,M}(kt) landed
        __syncthreads();

        // ---- QK^T: warp tile 32 rows x 32 keys, k=128 (8 k16 steps) ----
        float S[2][4][4] = {};
        #pragma unroll
        for (int ks = 0; ks < 8; ks++) {
            unsigned a[2][4];
            #pragma unroll
            for (int mi = 0; mi < 2; mi++)
                ldsm4(a[mi][0], a[mi][1], a[mi][2], a[mi][3],
                      aQ + (unsigned)(mi * 16 * QSTRB + ks * 32));
            #pragma unroll
            for (int nb = 0; nb < 2; nb++) {
                unsigned b0, b1, b2, b3;
                ldsm4(b0, b1, b2, b3, bK + (unsigned)(nb * 16 * KSTRB + ks * 32));
                #pragma unroll
                for (int mi = 0; mi < 2; mi++) {
                    mma16(S[mi][nb * 2],     a[mi][0], a[mi][1], a[mi][2], a[mi][3], b0, b2);
                    mma16(S[mi][nb * 2 + 1], a[mi][0], a[mi][1], a[mi][2], a[mi][3], b1, b3);
                }
            }
        }

        // ---- Phase A: mask+scale in regs, partial row max -> pmax ----
        #pragma unroll
        for (int mi = 0; mi < 2; mi++) {
            int r0 = rw + mi * 16 + g;
            float mx0 = -1e30f, mx1 = -1e30f;
            #pragma unroll
            for (int ni = 0; ni < 4; ni++) {
                int col = cw + ni * 8 + 2 * t;
                unsigned char m00 = sMskB[r0 * MROWB + col];
                unsigned char m01 = sMskB[r0 * MROWB + col + 1];
                unsigned char m10 = sMskB[(r0 + 8) * MROWB + col];
                unsigned char m11 = sMskB[(r0 + 8) * MROWB + col + 1];
                float v0 = (m00 ? -1e6f : S[mi][ni][0]) * scale;
                float v1 = (m01 ? -1e6f : S[mi][ni][1]) * scale;
                float v2 = (m10 ? -1e6f : S[mi][ni][2]) * scale;
                float v3 = (m11 ? -1e6f : S[mi][ni][3]) * scale;
                S[mi][ni][0] = v0; S[mi][ni][1] = v1;
                S[mi][ni][2] = v2; S[mi][ni][3] = v3;
                mx0 = fmaxf(mx0, fmaxf(v0, v1));
                mx1 = fmaxf(mx1, fmaxf(v2, v3));
            }
            mx0 = fmaxf(mx0, __shfl_xor_sync(0xffffffffu, mx0, 1, 4));
            mx0 = fmaxf(mx0, __shfl_xor_sync(0xffffffffu, mx0, 2, 4));
            mx1 = fmaxf(mx1, __shfl_xor_sync(0xffffffffu, mx1, 1, 4));
            mx1 = fmaxf(mx1, __shfl_xor_sync(0xffffffffu, mx1, 2, 4));
            if (t == 0) {
                pmax[r0 * 2 + cg]       = mx0;
                pmax[(r0 + 8) * 2 + cg] = mx1;
            }
        }
        __syncthreads();

        prefK(ktn); prefM(ktn); CP_COMMIT();

        // ---- Phase B: exp in regs, write P (fp16) + psum ----
        float av[2][2], mn[2][2];
        #pragma unroll
        for (int mi = 0; mi < 2; mi++) {
            int r0 = rw + mi * 16 + g;
            float M0 = fmaxf(pmax[r0 * 2],       pmax[r0 * 2 + 1]);
            float M1 = fmaxf(pmax[(r0 + 8) * 2], pmax[(r0 + 8) * 2 + 1]);
            float mold0 = mrow[r0], mold1 = mrow[r0 + 8];
            float mnew0 = fmaxf(mold0, M0), mnew1 = fmaxf(mold1, M1);
            float s0 = 0.0f, s1 = 0.0f;
            #pragma unroll
            for (int ni = 0; ni < 4; ni++) {
                __half h0 = __float2half_rn(__expf(S[mi][ni][0] - mnew0));
                __half h1 = __float2half_rn(__expf(S[mi][ni][1] - mnew0));
                __half h2 = __float2half_rn(__expf(S[mi][ni][2] - mnew1));
                __half h3 = __float2half_rn(__expf(S[mi][ni][3] - mnew1));
                s0 += __half2float(h0) + __half2float(h1);
                s1 += __half2float(h2) + __half2float(h3);
                int col = cw + ni * 8 + 2 * t;
                *(__half2*)(sSh + r0 * SSTRH + col)       = __halves2half2(h0, h1);
                *(__half2*)(sSh + (r0 + 8) * SSTRH + col) = __halves2half2(h2, h3);
            }
            s0 += __shfl_xor_sync(0xffffffffu, s0, 1, 4);
            s0 += __shfl_xor_sync(0xffffffffu, s0, 2, 4);
            s1 += __shfl_xor_sync(0xffffffffu, s1, 1, 4);
            s1 += __shfl_xor_sync(0xffffffffu, s1, 2, 4);
            if (t == 0) {
                psum[r0 * 2 + cg]       = s0;
                psum[(r0 + 8) * 2 + cg] = s1;
            }
            av[mi][0] = __expf(mold0 - mnew0);
            av[mi][1] = __expf(mold1 - mnew1);
            mn[mi][0] = mnew0;
            mn[mi][1] = mnew1;
        }

        CP_WAIT1();          // V(kt) landed
        __syncthreads();

        // ---- Phase C: m/l update, O rescale, PV (k=64, 4 k16 steps) ----
        if (cg == 0 && t == 0) {
            #pragma unroll
            for (int mi = 0; mi < 2; mi++) {
                int r0 = rw + mi * 16 + g;
                lrow[r0]     = lrow[r0]     * av[mi][0] + psum[r0 * 2]       + psum[r0 * 2 + 1];
                lrow[r0 + 8] = lrow[r0 + 8] * av[mi][1] + psum[(r0 + 8) * 2] + psum[(r0 + 8) * 2 + 1];
                mrow[r0]     = mn[mi][0];
                mrow[r0 + 8] = mn[mi][1];
            }
        }
        #pragma unroll
        for (int mi = 0; mi < 2; mi++)
            #pragma unroll
            for (int ni = 0; ni < 8; ni++) {
                O[mi][ni][0] *= av[mi][0]; O[mi][ni][1] *= av[mi][0];
                O[mi][ni][2] *= av[mi][1]; O[mi][ni][3] *= av[mi][1];
            }
        #pragma unroll
        for (int ks = 0; ks < 4; ks++) {
            unsigned a[2][4];
            #pragma unroll
            for (int mi = 0; mi < 2; mi++)
                ldsm4(a[mi][0], a[mi][1], a[mi][2], a[mi][3],
                      aS + (unsigned)(mi * 16 * SSTRB + ks * 32));
            #pragma unroll
            for (int nb = 0; nb < 4; nb++) {
                unsigned b0, b1, b2, b3;
                ldsm4(b0, b1, b2, b3, bV + (unsigned)(nb * 16 * VSTRB + ks * 32));
                #pragma unroll
                for (int mi = 0; mi < 2; mi++) {
                    mma16(O[mi][nb * 2],     a[mi][0], a[mi][1], a[mi][2], a[mi][3], b0, b2);
                    mma16(O[mi][nb * 2 + 1], a[mi][0], a[mi][1], a[mi][2], a[mi][3], b1, b3);
                }
            }
        }
        __syncthreads();

        prefV(ktn); CP_COMMIT();
    }

    CP_WAIT0();

    // epilogue
    #pragma unroll
    for (int mi = 0; mi < 2; mi++) {
        float linv0 = 1.0f / lrow[rw + mi * 16 + g];
        float linv1 = 1.0f / lrow[rw + mi * 16 + 8 + g];
        int row0 = q0 + rw + mi * 16 + g;
        #pragma unroll
        for (int ni = 0; ni < 8; ni++) {
            int col = dw + ni * 8 + 2 * t;
            float* d0 = out + ((size_t)b * Sc + row0) * Dc + h * HDc + col;
            *(float2*)d0 = make_float2(O[mi][ni][0] * linv0, O[mi][ni][1] * linv0);
            float* d1 = out + ((size_t)b * Sc + row0 + 8) * Dc + h * HDc + col;
            *(float2*)d1 = make_float2(O[mi][ni][2] * linv1, O[mi][ni][3] * linv1);
        }
    }
}

// ------------------------------------------------------------------
extern "C" void kernel_launch(void* const* d_in, const int* in_sizes, int n_in,
                              void* d_out, int out_size)
{
    const float* q  = (const float*)d_in[0];
    const float* k  = (const float*)d_in[1];
    const float* v  = (const float*)d_in[2];
    const unsigned int* mask = (const unsigned int*)d_in[3];
    const float* Wq = (const float*)d_in[4];
    const float* bq = (const float*)d_in[5];
    const float* Wk = (const float*)d_in[6];
    const float* bk = (const float*)d_in[7];
    const float* Wv = (const float*)d_in[8];
    const float* bv = (const float*)d_in[9];
    float* out = (float*)d_out;

    maskpack_kernel<<<(Bc * Sc * Sc) / 16 / 256, 256>>>(mask);
    dim3 cgrid(Mc * Dc / 8 / 256, 3);
    cvt_kernel<<<cgrid, 256>>>(q, k, v);
    dim3 tgrid(Dc / 32, Dc / 32, 3);
    cvtT_kernel<<<tgrid, 256>>>(Wq, Wk, Wv);

    cudaFuncSetAttribute(proj_kernel,
                         cudaFuncAttributeMaxDynamicSharedMemorySize,
                         PROJ_SMEM_BYTES);
    dim3 pgrid(Dc / 128, Mc / 128, 3);
    proj_kernel<<<pgrid, 256, PROJ_SMEM_BYTES>>>(bq, bk, bv);

    cudaFuncSetAttribute(attn_kernel,
                         cudaFuncAttributeMaxDynamicSharedMemorySize,
                         ATTN_SMEM_BYTES);
    dim3 agrid(Sc / 128, Bc * Hc);
    attn_kernel<<<agrid, 256, ATTN_SMEM_BYTES>>>(out);
}

// round 15
// speedup vs baseline: 7.2586x; 1.0611x over previous
#include <cuda_runtime.h>
#include <cuda_fp16.h>
#include <math.h>

#define Bc 2
#define Sc 2048
#define Dc 1024
#define Hc 8
#define HDc 128
#define Mc (Bc*Sc)   // 4096

// fp16 scratch: Q,K as [B,H,S,HD]; V as [B,H,HD,S] (transposed)
__device__ __half g_Qh[Bc*Hc*Sc*HDc];
__device__ __half g_Kh[Bc*Hc*Sc*HDc];
__device__ __half g_Vh[Bc*Hc*Sc*HDc];
// fp16 inputs (flat [m][k]) and weights TRANSPOSED [n][k]
__device__ __half g_qh[Mc*Dc];
__device__ __half g_kh[Mc*Dc];
__device__ __half g_vh[Mc*Dc];
__device__ __half g_wqh[Dc*Dc];
__device__ __half g_wkh[Dc*Dc];
__device__ __half g_wvh[Dc*Dc];
// byte-packed mask (nonzero -> 1)
__device__ unsigned char g_mb[Bc*Sc*Sc];

__device__ __forceinline__ void mma16(float* c,
    unsigned a0, unsigned a1, unsigned a2, unsigned a3,
    unsigned b0, unsigned b1)
{
    asm volatile(
        "mma.sync.aligned.m16n8k16.row.col.f32.f16.f16.f32 "
        "{%0,%1,%2,%3}, {%4,%5,%6,%7}, {%8,%9}, {%0,%1,%2,%3};"
        : "+f"(c[0]), "+f"(c[1]), "+f"(c[2]), "+f"(c[3])
        : "r"(a0), "r"(a1), "r"(a2), "r"(a3), "r"(b0), "r"(b1));
}

__device__ __forceinline__ void ldsm4(unsigned& r0, unsigned& r1, unsigned& r2, unsigned& r3,
                                      unsigned addr)
{
    asm volatile("ldmatrix.sync.aligned.m8n8.x4.shared.b16 {%0,%1,%2,%3}, [%4];"
        : "=r"(r0), "=r"(r1), "=r"(r2), "=r"(r3) : "r"(addr));
}

__device__ __forceinline__ void cpa16(unsigned dst, const void* src) {
    asm volatile("cp.async.cg.shared.global [%0], [%1], 16;" :: "r"(dst), "l"(src));
}
#define CP_COMMIT() asm volatile("cp.async.commit_group;")
#define CP_WAIT1()  asm volatile("cp.async.wait_group 1;")
#define CP_WAIT0()  asm volatile("cp.async.wait_group 0;")

// ------------------------------------------------------------------
// maskpack: uint32 bool -> packed bytes (nonzero -> 1)
// ------------------------------------------------------------------
__global__ __launch_bounds__(256) void maskpack_kernel(const unsigned int* __restrict__ m)
{
    size_t i = ((size_t)blockIdx.x * 256 + threadIdx.x) * 16;
    uint4 a0 = *(const uint4*)(m + i);
    uint4 a1 = *(const uint4*)(m + i + 4);
    uint4 a2 = *(const uint4*)(m + i + 8);
    uint4 a3 = *(const uint4*)(m + i + 12);
    unsigned p0 = (a0.x?1u:0u) | (a0.y?0x100u:0u) | (a0.z?0x10000u:0u) | (a0.w?0x1000000u:0u);
    unsigned p1 = (a1.x?1u:0u) | (a1.y?0x100u:0u) | (a1.z?0x10000u:0u) | (a1.w?0x1000000u:0u);
    unsigned p2 = (a2.x?1u:0u) | (a2.y?0x100u:0u) | (a2.z?0x10000u:0u) | (a2.w?0x1000000u:0u);
    unsigned p3 = (a3.x?1u:0u) | (a3.y?0x100u:0u) | (a3.z?0x10000u:0u) | (a3.w?0x1000000u:0u);
    uint4 o = {p0, p1, p2, p3};
    *(uint4*)(g_mb + i) = o;
}

// ------------------------------------------------------------------
// cvt: fp32 -> fp16 for q,k,v
// ------------------------------------------------------------------
__global__ __launch_bounds__(256) void cvt_kernel(
    const float* __restrict__ q, const float* __restrict__ k, const float* __restrict__ v)
{
    const float* src; __half* dst;
    switch (blockIdx.y) {
        case 0: src = q; dst = g_qh; break;
        case 1: src = k; dst = g_kh; break;
        default: src = v; dst = g_vh; break;
    }
    size_t idx = ((size_t)blockIdx.x * 256 + threadIdx.x) * 8;
    float4 v0 = *(const float4*)(src + idx);
    float4 v1 = *(const float4*)(src + idx + 4);
    __half2 h0 = __floats2half2_rn(v0.x, v0.y);
    __half2 h1 = __floats2half2_rn(v0.z, v0.w);
    __half2 h2 = __floats2half2_rn(v1.x, v1.y);
    __half2 h3 = __floats2half2_rn(v1.z, v1.w);
    uint4 o = {*(unsigned*)&h0, *(unsigned*)&h1, *(unsigned*)&h2, *(unsigned*)&h3};
    *(uint4*)(dst + idx) = o;
}

// cvtT: fp16-round + transpose W -> Wt[n][k]
__global__ __launch_bounds__(256) void cvtT_kernel(
    const float* __restrict__ Wq, const float* __restrict__ Wk, const float* __restrict__ Wv)
{
    __shared__ float tile[32][33];
    const float* src; __half* dst;
    switch (blockIdx.z) {
        case 0: src = Wq; dst = g_wqh; break;
        case 1: src = Wk; dst = g_wkh; break;
        default: src = Wv; dst = g_wvh; break;
    }
    int x0 = blockIdx.x * 32, y0 = blockIdx.y * 32;
    int tx = threadIdx.x & 31, ty = threadIdx.x >> 5;
    #pragma unroll
    for (int j = 0; j < 32; j += 8)
        tile[ty + j][tx] = src[(size_t)(y0 + ty + j) * Dc + x0 + tx];
    __syncthreads();
    #pragma unroll
    for (int j = 0; j < 32; j += 8)
        dst[(size_t)(x0 + ty + j) * Dc + y0 + tx] = __float2half_rn(tile[tx][ty + j]);
}

// ------------------------------------------------------------------
// Projection GEMM (fp16 m16n8k16) — unchanged from round 14.
// ------------------------------------------------------------------
#define PSTRB 144
#define ABUFB (128 * PSTRB)
#define PSMB_B (2 * ABUFB)
#define PROJ_SMEM_BYTES (4 * ABUFB)

__global__ __launch_bounds__(256, 2) void proj_kernel(
    const float* __restrict__ bq, const float* __restrict__ bk, const float* __restrict__ bv)
{
    extern __shared__ char psm[];

    const __half* A; const __half* Wt; const float* bias; __half* out;
    if (blockIdx.z == 0)      { A = g_qh; Wt = g_wqh; bias = bq; out = g_Qh; }
    else if (blockIdx.z == 1) { A = g_kh; Wt = g_wkh; bias = bk; out = g_Kh; }
    else                      { A = g_vh; Wt = g_wvh; bias = bv; out = g_Vh; }

    const int tid  = threadIdx.x;
    const int warp = tid >> 5;
    const int lane = tid & 31;
    const int g    = lane >> 2;
    const int t    = lane & 3;

    const int m0 = blockIdx.y * 128;
    const int n0 = blockIdx.x * 128;
    const int wm = (warp & 3) * 32;
    const int wn = (warp >> 2) * 64;

    const unsigned sbase = (unsigned)__cvta_generic_to_shared(psm);
    const unsigned aB0 = sbase + (unsigned)((wm + (lane & 15)) * PSTRB + (lane >> 4) * 16);
    const unsigned bB0 = sbase + (unsigned)(PSMB_B + (wn + (lane & 15)) * PSTRB + (lane >> 4) * 16);

    auto prefA = [&](int it, int buf) {
        const __half* src = A + (size_t)m0 * Dc + it * 64;
        unsigned dstb = sbase + (unsigned)(buf * ABUFB);
        #pragma unroll
        for (int i = 0; i < 4; i++) {
            int idx = tid + 256 * i;
            int r = idx >> 3, c = idx & 7;
            cpa16(dstb + (unsigned)(r * PSTRB + c * 16), src + (size_t)r * Dc + c * 8);
        }
    };
    auto prefB = [&](int it, int buf) {
        const __half* src = Wt + (size_t)n0 * Dc + it * 64;
        unsigned dstb = sbase + (unsigned)(PSMB_B + buf * ABUFB);
        #pragma unroll
        for (int i = 0; i < 4; i++) {
            int idx = tid + 256 * i;
            int r = idx >> 3, c = idx & 7;
            cpa16(dstb + (unsigned)(r * PSTRB + c * 16), src + (size_t)r * Dc + c * 8);
        }
    };

    float C[2][8][4] = {};

    prefA(0, 0); prefB(0, 0); CP_COMMIT();

    for (int it = 0; it < 16; it++) {
        CP_WAIT0();
        __syncthreads();
        if (it + 1 < 16) {
            prefA(it + 1, (it + 1) & 1);
            prefB(it + 1, (it + 1) & 1);
            CP_COMMIT();
        }
        const int buf = it & 1;
        const unsigned aBase = aB0 + (unsigned)(buf * ABUFB);
        const unsigned bBase = bB0 + (unsigned)(buf * ABUFB);

        #pragma unroll
        for (int ks = 0; ks < 4; ks++) {
            unsigned a[2][4];
            #pragma unroll
            for (int mi = 0; mi < 2; mi++)
                ldsm4(a[mi][0], a[mi][1], a[mi][2], a[mi][3],
                      aBase + (unsigned)(mi * 16 * PSTRB + ks * 32));
            #pragma unroll
            for (int nb = 0; nb < 4; nb++) {
                unsigned b0, b1, b2, b3;
                ldsm4(b0, b1, b2, b3, bBase + (unsigned)(nb * 16 * PSTRB + ks * 32));
                #pragma unroll
                for (int mi = 0; mi < 2; mi++) {
                    mma16(C[mi][nb * 2],     a[mi][0], a[mi][1], a[mi][2], a[mi][3], b0, b2);
                    mma16(C[mi][nb * 2 + 1], a[mi][0], a[mi][1], a[mi][2], a[mi][3], b1, b3);
                }
            }
        }
        __syncthreads();
    }

    const int h = blockIdx.x;
    if (blockIdx.z != 2) {
        #pragma unroll
        for (int mi = 0; mi < 2; mi++) {
            int row0 = m0 + wm + mi * 16 + g;
            #pragma unroll
            for (int ni = 0; ni < 8; ni++) {
                int col = wn + ni * 8 + 2 * t;
                float b0v = bias[n0 + col], b1v = bias[n0 + col + 1];
                int bb0 = row0 >> 11, s0 = row0 & (Sc - 1);
                __half2 o0 = __floats2half2_rn(C[mi][ni][0] + b0v, C[mi][ni][1] + b1v);
                *(__half2*)(out + (((size_t)(bb0 * Hc + h)) * Sc + s0) * HDc + col) = o0;
                int r1 = row0 + 8;
                int bb1 = r1 >> 11, s1 = r1 & (Sc - 1);
                __half2 o1 = __floats2half2_rn(C[mi][ni][2] + b0v, C[mi][ni][3] + b1v);
                *(__half2*)(out + (((size_t)(bb1 * Hc + h)) * Sc + s1) * HDc + col) = o1;
            }
        }
    } else {
        #pragma unroll
        for (int mi = 0; mi < 2; mi++) {
            int row0 = m0 + wm + mi * 16 + g;
            #pragma unroll
            for (int ni = 0; ni < 8; ni++) {
                int col = wn + ni * 8 + 2 * t;
                float b0v = bias[n0 + col], b1v = bias[n0 + col + 1];
                int bb0 = row0 >> 11, s0 = row0 & (Sc - 1);
                __half* base0 = out + ((size_t)(bb0 * Hc + h)) * HDc * Sc;
                base0[(size_t)col * Sc + s0]       = __float2half_rn(C[mi][ni][0] + b0v);
                base0[(size_t)(col + 1) * Sc + s0] = __float2half_rn(C[mi][ni][1] + b1v);
                int r1 = row0 + 8;
                int bb1 = r1 >> 11, s1 = r1 & (Sc - 1);
                __half* base1 = out + ((size_t)(bb1 * Hc + h)) * HDc * Sc;
                base1[(size_t)col * Sc + s1]       = __float2half_rn(C[mi][ni][2] + b0v);
                base1[(size_t)(col + 1) * Sc + s1] = __float2half_rn(C[mi][ni][3] + b1v);
            }
        }
    }
}

// ------------------------------------------------------------------
// Flash attention FA2-style: warp owns 16 q-rows x ALL 64 keys.
// P stays in registers (C-fragment == A-fragment); softmax warp-local;
// m/l in registers. No S buffer, no pmax/psum smem.
// ------------------------------------------------------------------
#define QSTRB  272
#define KSTRB  272
#define VSTRB  144
#define MROWB  80

#define SMB_Q    0
#define SMB_K    (128 * QSTRB)            // 34816
#define SMB_VT   (SMB_K + 64 * KSTRB)     // 52224
#define SMB_MSK  (SMB_VT + 128 * VSTRB)   // 70656
#define ATTN_SMEM_BYTES (SMB_MSK + 128 * MROWB)   // 80896

#define NTILE (Sc / 64)

__global__ __launch_bounds__(256, 1) void attn_kernel(float* __restrict__ out)
{
    extern __shared__ char smem[];
    const unsigned char* sMskB = (const unsigned char*)(smem + SMB_MSK);

    const int tid  = threadIdx.x;
    const int warp = tid >> 5;
    const int lane = tid & 31;
    const int g    = lane >> 2;
    const int t    = lane & 3;

    const int bh = blockIdx.y;
    const int b  = bh >> 3;
    const int h  = bh & (Hc - 1);
    const int q0 = blockIdx.x * 128;

    const int rw = warp * 16;   // 16 q-rows per warp

    const __half* Qg = g_Qh + (size_t)bh * Sc * HDc;
    const __half* Kg = g_Kh + (size_t)bh * Sc * HDc;
    const __half* Vg = g_Vh + (size_t)bh * HDc * Sc;
    const unsigned char* maskb = g_mb + (size_t)b * Sc * Sc;

    const unsigned sbase = (unsigned)__cvta_generic_to_shared(smem);
    const unsigned aQ = sbase + (unsigned)(SMB_Q  + (rw + (lane & 15)) * QSTRB + (lane >> 4) * 16);
    const unsigned bK = sbase + (unsigned)(SMB_K  + (lane & 15) * KSTRB + (lane >> 4) * 16);
    const unsigned bV = sbase + (unsigned)(SMB_VT + (lane & 15) * VSTRB + (lane >> 4) * 16);

    auto prefK = [&](int kt) {
        const __half* src = Kg + (size_t)kt * 64 * HDc;
        #pragma unroll
        for (int i = 0; i < 4; i++) {
            int idx = tid + 256 * i;
            int r = idx >> 4, c = idx & 15;
            cpa16(sbase + (unsigned)(SMB_K + r * KSTRB + c * 16), src + (size_t)r * HDc + c * 8);
        }
    };
    auto prefV = [&](int kt) {
        const __half* src = Vg + kt * 64;
        #pragma unroll
        for (int i = 0; i < 4; i++) {
            int idx = tid + 256 * i;
            int d = idx >> 3, c = idx & 7;
            cpa16(sbase + (unsigned)(SMB_VT + d * VSTRB + c * 16), src + (size_t)d * Sc + c * 8);
        }
    };
    auto prefM = [&](int kt) {
        const unsigned char* src = maskb + (size_t)q0 * Sc + kt * 64;
        #pragma unroll
        for (int i = 0; i < 2; i++) {
            int idx = tid + 256 * i;
            int r = idx >> 2, c16 = (idx & 3) << 4;
            cpa16(sbase + (unsigned)(SMB_MSK + r * MROWB + c16), src + (size_t)r * Sc + c16);
        }
    };

    // Q tile: 128 rows x 128 halves
    #pragma unroll
    for (int i = 0; i < 8; i++) {
        int idx = tid + 256 * i;
        int r = idx >> 4, c = idx & 15;
        *(uint4*)(smem + SMB_Q + r * QSTRB + c * 16) =
            *(const uint4*)(Qg + (size_t)(q0 + r) * HDc + c * 8);
    }

    prefK(0); prefM(0); CP_COMMIT();
    prefV(0); CP_COMMIT();

    float O[16][4] = {};
    float m0r = -1e30f, m1r = -1e30f;   // row g, row g+8 running max
    float l0r = 0.0f,   l1r = 0.0f;     // running sums
    const float scale = 0.08838834764831845f;  // 1/sqrt(128)
    const int r0 = rw + g;

    for (int kt = 0; kt < NTILE; kt++) {
        const int ktn = (kt + 1 < NTILE) ? kt + 1 : NTILE - 1;

        CP_WAIT1();          // {K,M}(kt) landed
        __syncthreads();

        // ---- QK^T: warp tile 16 rows x 64 keys, k=128 (8 k16 steps) ----
        float S[8][4] = {};
        #pragma unroll
        for (int ks = 0; ks < 8; ks++) {
            unsigned a0, a1, a2, a3;
            ldsm4(a0, a1, a2, a3, aQ + (unsigned)(ks * 32));
            #pragma unroll
            for (int nb = 0; nb < 4; nb++) {
                unsigned b0, b1, b2, b3;
                ldsm4(b0, b1, b2, b3, bK + (unsigned)(nb * 16 * KSTRB + ks * 32));
                mma16(S[nb * 2],     a0, a1, a2, a3, b0, b2);
                mma16(S[nb * 2 + 1], a0, a1, a2, a3, b1, b3);
            }
        }

        // ---- mask+scale in regs, warp-local row max (shfl width 4) ----
        float mx0 = -1e30f, mx1 = -1e30f;
        #pragma unroll
        for (int ni = 0; ni < 8; ni++) {
            int col = ni * 8 + 2 * t;
            unsigned char m00 = sMskB[r0 * MROWB + col];
            unsigned char m01 = sMskB[r0 * MROWB + col + 1];
            unsigned char m10 = sMskB[(r0 + 8) * MROWB + col];
            unsigned char m11 = sMskB[(r0 + 8) * MROWB + col + 1];
            float v0 = (m00 ? -1e6f : S[ni][0]) * scale;
            float v1 = (m01 ? -1e6f : S[ni][1]) * scale;
            float v2 = (m10 ? -1e6f : S[ni][2]) * scale;
            float v3 = (m11 ? -1e6f : S[ni][3]) * scale;
            S[ni][0] = v0; S[ni][1] = v1; S[ni][2] = v2; S[ni][3] = v3;
            mx0 = fmaxf(mx0, fmaxf(v0, v1));
            mx1 = fmaxf(mx1, fmaxf(v2, v3));
        }
        mx0 = fmaxf(mx0, __shfl_xor_sync(0xffffffffu, mx0, 1, 4));
        mx0 = fmaxf(mx0, __shfl_xor_sync(0xffffffffu, mx0, 2, 4));
        mx1 = fmaxf(mx1, __shfl_xor_sync(0xffffffffu, mx1, 1, 4));
        mx1 = fmaxf(mx1, __shfl_xor_sync(0xffffffffu, mx1, 2, 4));

        // ---- exp in regs; P packed as A-fragments (half2) ----
        float mnew0 = fmaxf(m0r, mx0), mnew1 = fmaxf(m1r, mx1);
        unsigned ph[8][2];   // ph[ni][0]: row g keys 8ni+2t,+1; ph[ni][1]: row g+8
        float s0 = 0.0f, s1 = 0.0f;
        #pragma unroll
        for (int ni = 0; ni < 8; ni++) {
            __half h0 = __float2half_rn(__expf(S[ni][0] - mnew0));
            __half h1 = __float2half_rn(__expf(S[ni][1] - mnew0));
            __half h2 = __float2half_rn(__expf(S[ni][2] - mnew1));
            __half h3 = __float2half_rn(__expf(S[ni][3] - mnew1));
            s0 += __half2float(h0) + __half2float(h1);
            s1 += __half2float(h2) + __half2float(h3);
            __half2 p0 = __halves2half2(h0, h1);
            __half2 p1 = __halves2half2(h2, h3);
            ph[ni][0] = *(unsigned*)&p0;
            ph[ni][1] = *(unsigned*)&p1;
        }
        s0 += __shfl_xor_sync(0xffffffffu, s0, 1, 4);
        s0 += __shfl_xor_sync(0xffffffffu, s0, 2, 4);
        s1 += __shfl_xor_sync(0xffffffffu, s1, 1, 4);
        s1 += __shfl_xor_sync(0xffffffffu, s1, 2, 4);
        float a0f = __expf(m0r - mnew0);
        float a1f = __expf(m1r - mnew1);
        l0r = l0r * a0f + s0;
        l1r = l1r * a1f + s1;
        m0r = mnew0;
        m1r = mnew1;

        __syncthreads();     // sK + sMsk consumed
        prefK(ktn); prefM(ktn); CP_COMMIT();

        CP_WAIT1();          // V(kt) landed
        __syncthreads();

        // ---- O rescale + PV: 16 rows x 128 d, keys as k (4 k16 steps) ----
        #pragma unroll
        for (int ni = 0; ni < 16; ni++) {
            O[ni][0] *= a0f; O[ni][1] *= a0f;
            O[ni][2] *= a1f; O[ni][3] *= a1f;
        }
        #pragma unroll
        for (int ks = 0; ks < 4; ks++) {
            unsigned pa0 = ph[2 * ks][0];      // row g,   keys 16ks+2t..+1
            unsigned pa1 = ph[2 * ks][1];      // row g+8
            unsigned pa2 = ph[2 * ks + 1][0];  // row g,   keys 16ks+8+2t..+1
            unsigned pa3 = ph[2 * ks + 1][1];  // row g+8
            #pragma unroll
            for (int nb = 0; nb < 8; nb++) {
                unsigned b0, b1, b2, b3;
                ldsm4(b0, b1, b2, b3, bV + (unsigned)(nb * 16 * VSTRB + ks * 32));
                mma16(O[nb * 2],     pa0, pa1, pa2, pa3, b0, b2);
                mma16(O[nb * 2 + 1], pa0, pa1, pa2, pa3, b1, b3);
            }
        }
        __syncthreads();     // sVT consumed

        prefV(ktn); CP_COMMIT();
    }

    CP_WAIT0();

    // epilogue (l in registers)
    {
        float linv0 = 1.0f / l0r;
        float linv1 = 1.0f / l1r;
        int row0 = q0 + rw + g;
        #pragma unroll
        for (int ni = 0; ni < 16; ni++) {
            int col = ni * 8 + 2 * t;
            float* d0 = out + ((size_t)b * Sc + row0) * Dc + h * HDc + col;
            *(float2*)d0 = make_float2(O[ni][0] * linv0, O[ni][1] * linv0);
            float* d1 = out + ((size_t)b * Sc + row0 + 8) * Dc + h * HDc + col;
            *(float2*)d1 = make_float2(O[ni][2] * linv1, O[ni][3] * linv1);
        }
    }
}

// ------------------------------------------------------------------
extern "C" void kernel_launch(void* const* d_in, const int* in_sizes, int n_in,
                              void* d_out, int out_size)
{
    const float* q  = (const float*)d_in[0];
    const float* k  = (const float*)d_in[1];
    const float* v  = (const float*)d_in[2];
    const unsigned int* mask = (const unsigned int*)d_in[3];
    const float* Wq = (const float*)d_in[4];
    const float* bq = (const float*)d_in[5];
    const float* Wk = (const float*)d_in[6];
    const float* bk = (const float*)d_in[7];
    const float* Wv = (const float*)d_in[8];
    const float* bv = (const float*)d_in[9];
    float* out = (float*)d_out;

    maskpack_kernel<<<(Bc * Sc * Sc) / 16 / 256, 256>>>(mask);
    dim3 cgrid(Mc * Dc / 8 / 256, 3);
    cvt_kernel<<<cgrid, 256>>>(q, k, v);
    dim3 tgrid(Dc / 32, Dc / 32, 3);
    cvtT_kernel<<<tgrid, 256>>>(Wq, Wk, Wv);

    cudaFuncSetAttribute(proj_kernel,
                         cudaFuncAttributeMaxDynamicSharedMemorySize,
                         PROJ_SMEM_BYTES);
    dim3 pgrid(Dc / 128, Mc / 128, 3);
    proj_kernel<<<pgrid, 256, PROJ_SMEM_BYTES>>>(bq, bk, bv);

    cudaFuncSetAttribute(attn_kernel,
                         cudaFuncAttributeMaxDynamicSharedMemorySize,
                         ATTN_SMEM_BYTES);
    dim3 agrid(Sc / 128, Bc * Hc);
    attn_kernel<<<agrid, 256, ATTN_SMEM_BYTES>>>(out);
}

// round 16
// speedup vs baseline: 7.6317x; 1.0514x over previous
#include <cuda_runtime.h>
#include <cuda_fp16.h>
#include <math.h>

#define Bc 2
#define Sc 2048
#define Dc 1024
#define Hc 8
#define HDc 128
#define Mc (Bc*Sc)   // 4096

// fp16 scratch: Q,K as [B,H,S,HD]; V as [B,H,HD,S] (transposed)
__device__ __half g_Qh[Bc*Hc*Sc*HDc];
__device__ __half g_Kh[Bc*Hc*Sc*HDc];
__device__ __half g_Vh[Bc*Hc*Sc*HDc];
// fp16 inputs (flat [m][k]) and weights TRANSPOSED [n][k]
__device__ __half g_qh[Mc*Dc];
__device__ __half g_kh[Mc*Dc];
__device__ __half g_vh[Mc*Dc];
__device__ __half g_wqh[Dc*Dc];
__device__ __half g_wkh[Dc*Dc];
__device__ __half g_wvh[Dc*Dc];
// byte-packed mask (nonzero -> 1)
__device__ unsigned char g_mb[Bc*Sc*Sc];

__device__ __forceinline__ void mma16(float* c,
    unsigned a0, unsigned a1, unsigned a2, unsigned a3,
    unsigned b0, unsigned b1)
{
    asm volatile(
        "mma.sync.aligned.m16n8k16.row.col.f32.f16.f16.f32 "
        "{%0,%1,%2,%3}, {%4,%5,%6,%7}, {%8,%9}, {%0,%1,%2,%3};"
        : "+f"(c[0]), "+f"(c[1]), "+f"(c[2]), "+f"(c[3])
        : "r"(a0), "r"(a1), "r"(a2), "r"(a3), "r"(b0), "r"(b1));
}

__device__ __forceinline__ void ldsm4(unsigned& r0, unsigned& r1, unsigned& r2, unsigned& r3,
                                      unsigned addr)
{
    asm volatile("ldmatrix.sync.aligned.m8n8.x4.shared.b16 {%0,%1,%2,%3}, [%4];"
        : "=r"(r0), "=r"(r1), "=r"(r2), "=r"(r3) : "r"(addr));
}

__device__ __forceinline__ void cpa16(unsigned dst, const void* src) {
    asm volatile("cp.async.cg.shared.global [%0], [%1], 16;" :: "r"(dst), "l"(src));
}
#define CP_COMMIT() asm volatile("cp.async.commit_group;")
#define CP_WAIT1()  asm volatile("cp.async.wait_group 1;")
#define CP_WAIT0()  asm volatile("cp.async.wait_group 0;")

// ------------------------------------------------------------------
// maskpack: uint32 bool -> packed bytes (nonzero -> 1)
// ------------------------------------------------------------------
__global__ __launch_bounds__(256) void maskpack_kernel(const unsigned int* __restrict__ m)
{
    size_t i = ((size_t)blockIdx.x * 256 + threadIdx.x) * 16;
    uint4 a0 = *(const uint4*)(m + i);
    uint4 a1 = *(const uint4*)(m + i + 4);
    uint4 a2 = *(const uint4*)(m + i + 8);
    uint4 a3 = *(const uint4*)(m + i + 12);
    unsigned p0 = (a0.x?1u:0u) | (a0.y?0x100u:0u) | (a0.z?0x10000u:0u) | (a0.w?0x1000000u:0u);
    unsigned p1 = (a1.x?1u:0u) | (a1.y?0x100u:0u) | (a1.z?0x10000u:0u) | (a1.w?0x1000000u:0u);
    unsigned p2 = (a2.x?1u:0u) | (a2.y?0x100u:0u) | (a2.z?0x10000u:0u) | (a2.w?0x1000000u:0u);
    unsigned p3 = (a3.x?1u:0u) | (a3.y?0x100u:0u) | (a3.z?0x10000u:0u) | (a3.w?0x1000000u:0u);
    uint4 o = {p0, p1, p2, p3};
    *(uint4*)(g_mb + i) = o;
}

// ------------------------------------------------------------------
// cvt: fp32 -> fp16 for q,k,v
// ------------------------------------------------------------------
__global__ __launch_bounds__(256) void cvt_kernel(
    const float* __restrict__ q, const float* __restrict__ k, const float* __restrict__ v)
{
    const float* src; __half* dst;
    switch (blockIdx.y) {
        case 0: src = q; dst = g_qh; break;
        case 1: src = k; dst = g_kh; break;
        default: src = v; dst = g_vh; break;
    }
    size_t idx = ((size_t)blockIdx.x * 256 + threadIdx.x) * 8;
    float4 v0 = *(const float4*)(src + idx);
    float4 v1 = *(const float4*)(src + idx + 4);
    __half2 h0 = __floats2half2_rn(v0.x, v0.y);
    __half2 h1 = __floats2half2_rn(v0.z, v0.w);
    __half2 h2 = __floats2half2_rn(v1.x, v1.y);
    __half2 h3 = __floats2half2_rn(v1.z, v1.w);
    uint4 o = {*(unsigned*)&h0, *(unsigned*)&h1, *(unsigned*)&h2, *(unsigned*)&h3};
    *(uint4*)(dst + idx) = o;
}

// cvtT: fp16-round + transpose W -> Wt[n][k]
__global__ __launch_bounds__(256) void cvtT_kernel(
    const float* __restrict__ Wq, const float* __restrict__ Wk, const float* __restrict__ Wv)
{
    __shared__ float tile[32][33];
    const float* src; __half* dst;
    switch (blockIdx.z) {
        case 0: src = Wq; dst = g_wqh; break;
        case 1: src = Wk; dst = g_wkh; break;
        default: src = Wv; dst = g_wvh; break;
    }
    int x0 = blockIdx.x * 32, y0 = blockIdx.y * 32;
    int tx = threadIdx.x & 31, ty = threadIdx.x >> 5;
    #pragma unroll
    for (int j = 0; j < 32; j += 8)
        tile[ty + j][tx] = src[(size_t)(y0 + ty + j) * Dc + x0 + tx];
    __syncthreads();
    #pragma unroll
    for (int j = 0; j < 32; j += 8)
        dst[(size_t)(x0 + ty + j) * Dc + y0 + tx] = __float2half_rn(tile[tx][ty + j]);
}

// ------------------------------------------------------------------
// Projection GEMM (fp16 m16n8k16) — unchanged from round 14/15.
// ------------------------------------------------------------------
#define PSTRB 144
#define ABUFB (128 * PSTRB)
#define PSMB_B (2 * ABUFB)
#define PROJ_SMEM_BYTES (4 * ABUFB)

__global__ __launch_bounds__(256, 2) void proj_kernel(
    const float* __restrict__ bq, const float* __restrict__ bk, const float* __restrict__ bv)
{
    extern __shared__ char psm[];

    const __half* A; const __half* Wt; const float* bias; __half* out;
    if (blockIdx.z == 0)      { A = g_qh; Wt = g_wqh; bias = bq; out = g_Qh; }
    else if (blockIdx.z == 1) { A = g_kh; Wt = g_wkh; bias = bk; out = g_Kh; }
    else                      { A = g_vh; Wt = g_wvh; bias = bv; out = g_Vh; }

    const int tid  = threadIdx.x;
    const int warp = tid >> 5;
    const int lane = tid & 31;
    const int g    = lane >> 2;
    const int t    = lane & 3;

    const int m0 = blockIdx.y * 128;
    const int n0 = blockIdx.x * 128;
    const int wm = (warp & 3) * 32;
    const int wn = (warp >> 2) * 64;

    const unsigned sbase = (unsigned)__cvta_generic_to_shared(psm);
    const unsigned aB0 = sbase + (unsigned)((wm + (lane & 15)) * PSTRB + (lane >> 4) * 16);
    const unsigned bB0 = sbase + (unsigned)(PSMB_B + (wn + (lane & 15)) * PSTRB + (lane >> 4) * 16);

    auto prefA = [&](int it, int buf) {
        const __half* src = A + (size_t)m0 * Dc + it * 64;
        unsigned dstb = sbase + (unsigned)(buf * ABUFB);
        #pragma unroll
        for (int i = 0; i < 4; i++) {
            int idx = tid + 256 * i;
            int r = idx >> 3, c = idx & 7;
            cpa16(dstb + (unsigned)(r * PSTRB + c * 16), src + (size_t)r * Dc + c * 8);
        }
    };
    auto prefB = [&](int it, int buf) {
        const __half* src = Wt + (size_t)n0 * Dc + it * 64;
        unsigned dstb = sbase + (unsigned)(PSMB_B + buf * ABUFB);
        #pragma unroll
        for (int i = 0; i < 4; i++) {
            int idx = tid + 256 * i;
            int r = idx >> 3, c = idx & 7;
            cpa16(dstb + (unsigned)(r * PSTRB + c * 16), src + (size_t)r * Dc + c * 8);
        }
    };

    float C[2][8][4] = {};

    prefA(0, 0); prefB(0, 0); CP_COMMIT();

    for (int it = 0; it < 16; it++) {
        CP_WAIT0();
        __syncthreads();
        if (it + 1 < 16) {
            prefA(it + 1, (it + 1) & 1);
            prefB(it + 1, (it + 1) & 1);
            CP_COMMIT();
        }
        const int buf = it & 1;
        const unsigned aBase = aB0 + (unsigned)(buf * ABUFB);
        const unsigned bBase = bB0 + (unsigned)(buf * ABUFB);

        #pragma unroll
        for (int ks = 0; ks < 4; ks++) {
            unsigned a[2][4];
            #pragma unroll
            for (int mi = 0; mi < 2; mi++)
                ldsm4(a[mi][0], a[mi][1], a[mi][2], a[mi][3],
                      aBase + (unsigned)(mi * 16 * PSTRB + ks * 32));
            #pragma unroll
            for (int nb = 0; nb < 4; nb++) {
                unsigned b0, b1, b2, b3;
                ldsm4(b0, b1, b2, b3, bBase + (unsigned)(nb * 16 * PSTRB + ks * 32));
                #pragma unroll
                for (int mi = 0; mi < 2; mi++) {
                    mma16(C[mi][nb * 2],     a[mi][0], a[mi][1], a[mi][2], a[mi][3], b0, b2);
                    mma16(C[mi][nb * 2 + 1], a[mi][0], a[mi][1], a[mi][2], a[mi][3], b1, b3);
                }
            }
        }
        __syncthreads();
    }

    const int h = blockIdx.x;
    if (blockIdx.z != 2) {
        #pragma unroll
        for (int mi = 0; mi < 2; mi++) {
            int row0 = m0 + wm + mi * 16 + g;
            #pragma unroll
            for (int ni = 0; ni < 8; ni++) {
                int col = wn + ni * 8 + 2 * t;
                float b0v = bias[n0 + col], b1v = bias[n0 + col + 1];
                int bb0 = row0 >> 11, s0 = row0 & (Sc - 1);
                __half2 o0 = __floats2half2_rn(C[mi][ni][0] + b0v, C[mi][ni][1] + b1v);
                *(__half2*)(out + (((size_t)(bb0 * Hc + h)) * Sc + s0) * HDc + col) = o0;
                int r1 = row0 + 8;
                int bb1 = r1 >> 11, s1 = r1 & (Sc - 1);
                __half2 o1 = __floats2half2_rn(C[mi][ni][2] + b0v, C[mi][ni][3] + b1v);
                *(__half2*)(out + (((size_t)(bb1 * Hc + h)) * Sc + s1) * HDc + col) = o1;
            }
        }
    } else {
        #pragma unroll
        for (int mi = 0; mi < 2; mi++) {
            int row0 = m0 + wm + mi * 16 + g;
            #pragma unroll
            for (int ni = 0; ni < 8; ni++) {
                int col = wn + ni * 8 + 2 * t;
                float b0v = bias[n0 + col], b1v = bias[n0 + col + 1];
                int bb0 = row0 >> 11, s0 = row0 & (Sc - 1);
                __half* base0 = out + ((size_t)(bb0 * Hc + h)) * HDc * Sc;
                base0[(size_t)col * Sc + s0]       = __float2half_rn(C[mi][ni][0] + b0v);
                base0[(size_t)(col + 1) * Sc + s0] = __float2half_rn(C[mi][ni][1] + b1v);
                int r1 = row0 + 8;
                int bb1 = r1 >> 11, s1 = r1 & (Sc - 1);
                __half* base1 = out + ((size_t)(bb1 * Hc + h)) * HDc * Sc;
                base1[(size_t)col * Sc + s1]       = __float2half_rn(C[mi][ni][2] + b0v);
                base1[(size_t)(col + 1) * Sc + s1] = __float2half_rn(C[mi][ni][3] + b1v);
            }
        }
    }
}

// ------------------------------------------------------------------
// Flash attention FA2, TQ=64, 128 threads (4 warps x 16 rows), Q hoisted
// into registers. 2+ CTAs/SM for cross-CTA phase overlap.
// ------------------------------------------------------------------
#define QSTRB  272
#define KSTRB  272
#define VSTRB  144
#define MROWB  80
#define ATHREADS 128

#define SMB_Q    0
#define SMB_K    (64 * QSTRB)             // 17408
#define SMB_VT   (SMB_K + 64 * KSTRB)     // 34816
#define SMB_MSK  (SMB_VT + 128 * VSTRB)   // 53248
#define ATTN_SMEM_BYTES (SMB_MSK + 64 * MROWB)   // 58368

#define NTILE (Sc / 64)

__global__ __launch_bounds__(ATHREADS) void attn_kernel(float* __restrict__ out)
{
    extern __shared__ char smem[];
    const unsigned char* sMskB = (const unsigned char*)(smem + SMB_MSK);

    const int tid  = threadIdx.x;
    const int warp = tid >> 5;
    const int lane = tid & 31;
    const int g    = lane >> 2;
    const int t    = lane & 3;

    const int bh = blockIdx.y;
    const int b  = bh >> 3;
    const int h  = bh & (Hc - 1);
    const int q0 = blockIdx.x * 64;

    const int rw = warp * 16;   // 16 q-rows per warp (4 warps = 64 rows)

    const __half* Qg = g_Qh + (size_t)bh * Sc * HDc;
    const __half* Kg = g_Kh + (size_t)bh * Sc * HDc;
    const __half* Vg = g_Vh + (size_t)bh * HDc * Sc;
    const unsigned char* maskb = g_mb + (size_t)b * Sc * Sc;

    const unsigned sbase = (unsigned)__cvta_generic_to_shared(smem);
    const unsigned aQ = sbase + (unsigned)(SMB_Q  + (rw + (lane & 15)) * QSTRB + (lane >> 4) * 16);
    const unsigned bK = sbase + (unsigned)(SMB_K  + (lane & 15) * KSTRB + (lane >> 4) * 16);
    const unsigned bV = sbase + (unsigned)(SMB_VT + (lane & 15) * VSTRB + (lane >> 4) * 16);

    auto prefK = [&](int kt) {
        const __half* src = Kg + (size_t)kt * 64 * HDc;
        #pragma unroll
        for (int i = 0; i < 8; i++) {
            int idx = tid + ATHREADS * i;
            int r = idx >> 4, c = idx & 15;
            cpa16(sbase + (unsigned)(SMB_K + r * KSTRB + c * 16), src + (size_t)r * HDc + c * 8);
        }
    };
    auto prefV = [&](int kt) {
        const __half* src = Vg + kt * 64;
        #pragma unroll
        for (int i = 0; i < 8; i++) {
            int idx = tid + ATHREADS * i;
            int d = idx >> 3, c = idx & 7;
            cpa16(sbase + (unsigned)(SMB_VT + d * VSTRB + c * 16), src + (size_t)d * Sc + c * 8);
        }
    };
    auto prefM = [&](int kt) {
        const unsigned char* src = maskb + (size_t)q0 * Sc + kt * 64;
        #pragma unroll
        for (int i = 0; i < 2; i++) {
            int idx = tid + ATHREADS * i;
            int r = idx >> 2, c16 = (idx & 3) << 4;
            cpa16(sbase + (unsigned)(SMB_MSK + r * MROWB + c16), src + (size_t)r * Sc + c16);
        }
    };

    // Q tile: 64 rows x 128 halves -> smem, then hoist fragments to regs
    #pragma unroll
    for (int i = 0; i < 8; i++) {
        int idx = tid + ATHREADS * i;
        int r = idx >> 4, c = idx & 15;
        *(uint4*)(smem + SMB_Q + r * QSTRB + c * 16) =
            *(const uint4*)(Qg + (size_t)(q0 + r) * HDc + c * 8);
    }

    prefK(0); prefM(0); CP_COMMIT();
    prefV(0); CP_COMMIT();

    __syncthreads();   // Q smem ready
    unsigned qa[8][4];
    #pragma unroll
    for (int ks = 0; ks < 8; ks++)
        ldsm4(qa[ks][0], qa[ks][1], qa[ks][2], qa[ks][3], aQ + (unsigned)(ks * 32));

    float O[16][4] = {};
    float m0r = -1e30f, m1r = -1e30f;
    float l0r = 0.0f,   l1r = 0.0f;
    const float scale = 0.08838834764831845f;  // 1/sqrt(128)
    const int r0 = rw + g;

    for (int kt = 0; kt < NTILE; kt++) {
        const int ktn = (kt + 1 < NTILE) ? kt + 1 : NTILE - 1;

        CP_WAIT1();          // {K,M}(kt) landed
        __syncthreads();

        // ---- QK^T: 16 rows x 64 keys, k=128 (Q from registers) ----
        float S[8][4] = {};
        #pragma unroll
        for (int ks = 0; ks < 8; ks++) {
            #pragma unroll
            for (int nb = 0; nb < 4; nb++) {
                unsigned b0, b1, b2, b3;
                ldsm4(b0, b1, b2, b3, bK + (unsigned)(nb * 16 * KSTRB + ks * 32));
                mma16(S[nb * 2],     qa[ks][0], qa[ks][1], qa[ks][2], qa[ks][3], b0, b2);
                mma16(S[nb * 2 + 1], qa[ks][0], qa[ks][1], qa[ks][2], qa[ks][3], b1, b3);
            }
        }

        // ---- mask+scale in regs, warp-local row max ----
        float mx0 = -1e30f, mx1 = -1e30f;
        #pragma unroll
        for (int ni = 0; ni < 8; ni++) {
            int col = ni * 8 + 2 * t;
            unsigned char m00 = sMskB[r0 * MROWB + col];
            unsigned char m01 = sMskB[r0 * MROWB + col + 1];
            unsigned char m10 = sMskB[(r0 + 8) * MROWB + col];
            unsigned char m11 = sMskB[(r0 + 8) * MROWB + col + 1];
            float v0 = (m00 ? -1e6f : S[ni][0]) * scale;
            float v1 = (m01 ? -1e6f : S[ni][1]) * scale;
            float v2 = (m10 ? -1e6f : S[ni][2]) * scale;
            float v3 = (m11 ? -1e6f : S[ni][3]) * scale;
            S[ni][0] = v0; S[ni][1] = v1; S[ni][2] = v2; S[ni][3] = v3;
            mx0 = fmaxf(mx0, fmaxf(v0, v1));
            mx1 = fmaxf(mx1, fmaxf(v2, v3));
        }
        mx0 = fmaxf(mx0, __shfl_xor_sync(0xffffffffu, mx0, 1, 4));
        mx0 = fmaxf(mx0, __shfl_xor_sync(0xffffffffu, mx0, 2, 4));
        mx1 = fmaxf(mx1, __shfl_xor_sync(0xffffffffu, mx1, 1, 4));
        mx1 = fmaxf(mx1, __shfl_xor_sync(0xffffffffu, mx1, 2, 4));

        // ---- exp in regs; P packed as A-fragments ----
        float mnew0 = fmaxf(m0r, mx0), mnew1 = fmaxf(m1r, mx1);
        unsigned ph[8][2];
        float s0 = 0.0f, s1 = 0.0f;
        #pragma unroll
        for (int ni = 0; ni < 8; ni++) {
            __half h0 = __float2half_rn(__expf(S[ni][0] - mnew0));
            __half h1 = __float2half_rn(__expf(S[ni][1] - mnew0));
            __half h2 = __float2half_rn(__expf(S[ni][2] - mnew1));
            __half h3 = __float2half_rn(__expf(S[ni][3] - mnew1));
            s0 += __half2float(h0) + __half2float(h1);
            s1 += __half2float(h2) + __half2float(h3);
            __half2 p0 = __halves2half2(h0, h1);
            __half2 p1 = __halves2half2(h2, h3);
            ph[ni][0] = *(unsigned*)&p0;
            ph[ni][1] = *(unsigned*)&p1;
        }
        s0 += __shfl_xor_sync(0xffffffffu, s0, 1, 4);
        s0 += __shfl_xor_sync(0xffffffffu, s0, 2, 4);
        s1 += __shfl_xor_sync(0xffffffffu, s1, 1, 4);
        s1 += __shfl_xor_sync(0xffffffffu, s1, 2, 4);
        float a0f = __expf(m0r - mnew0);
        float a1f = __expf(m1r - mnew1);
        l0r = l0r * a0f + s0;
        l1r = l1r * a1f + s1;
        m0r = mnew0;
        m1r = mnew1;

        __syncthreads();     // sK + sMsk consumed
        prefK(ktn); prefM(ktn); CP_COMMIT();

        CP_WAIT1();          // V(kt) landed
        __syncthreads();

        // ---- O rescale + PV ----
        #pragma unroll
        for (int ni = 0; ni < 16; ni++) {
            O[ni][0] *= a0f; O[ni][1] *= a0f;
            O[ni][2] *= a1f; O[ni][3] *= a1f;
        }
        #pragma unroll
        for (int ks = 0; ks < 4; ks++) {
            unsigned pa0 = ph[2 * ks][0];
            unsigned pa1 = ph[2 * ks][1];
            unsigned pa2 = ph[2 * ks + 1][0];
            unsigned pa3 = ph[2 * ks + 1][1];
            #pragma unroll
            for (int nb = 0; nb < 8; nb++) {
                unsigned b0, b1, b2, b3;
                ldsm4(b0, b1, b2, b3, bV + (unsigned)(nb * 16 * VSTRB + ks * 32));
                mma16(O[nb * 2],     pa0, pa1, pa2, pa3, b0, b2);
                mma16(O[nb * 2 + 1], pa0, pa1, pa2, pa3, b1, b3);
            }
        }
        __syncthreads();     // sVT consumed

        prefV(ktn); CP_COMMIT();
    }

    CP_WAIT0();

    // epilogue
    {
        float linv0 = 1.0f / l0r;
        float linv1 = 1.0f / l1r;
        int row0 = q0 + rw + g;
        #pragma unroll
        for (int ni = 0; ni < 16; ni++) {
            int col = ni * 8 + 2 * t;
            float* d0 = out + ((size_t)b * Sc + row0) * Dc + h * HDc + col;
            *(float2*)d0 = make_float2(O[ni][0] * linv0, O[ni][1] * linv0);
            float* d1 = out + ((size_t)b * Sc + row0 + 8) * Dc + h * HDc + col;
            *(float2*)d1 = make_float2(O[ni][2] * linv1, O[ni][3] * linv1);
        }
    }
}

// ------------------------------------------------------------------
extern "C" void kernel_launch(void* const* d_in, const int* in_sizes, int n_in,
                              void* d_out, int out_size)
{
    const float* q  = (const float*)d_in[0];
    const float* k  = (const float*)d_in[1];
    const float* v  = (const float*)d_in[2];
    const unsigned int* mask = (const unsigned int*)d_in[3];
    const float* Wq = (const float*)d_in[4];
    const float* bq = (const float*)d_in[5];
    const float* Wk = (const float*)d_in[6];
    const float* bk = (const float*)d_in[7];
    const float* Wv = (const float*)d_in[8];
    const float* bv = (const float*)d_in[9];
    float* out = (float*)d_out;

    maskpack_kernel<<<(Bc * Sc * Sc) / 16 / 256, 256>>>(mask);
    dim3 cgrid(Mc * Dc / 8 / 256, 3);
    cvt_kernel<<<cgrid, 256>>>(q, k, v);
    dim3 tgrid(Dc / 32, Dc / 32, 3);
    cvtT_kernel<<<tgrid, 256>>>(Wq, Wk, Wv);

    cudaFuncSetAttribute(proj_kernel,
                         cudaFuncAttributeMaxDynamicSharedMemorySize,
                         PROJ_SMEM_BYTES);
    dim3 pgrid(Dc / 128, Mc / 128, 3);
    proj_kernel<<<pgrid, 256, PROJ_SMEM_BYTES>>>(bq, bk, bv);

    cudaFuncSetAttribute(attn_kernel,
                         cudaFuncAttributeMaxDynamicSharedMemorySize,
                         ATTN_SMEM_BYTES);
    dim3 agrid(Sc / 64, Bc * Hc);
    attn_kernel<<<agrid, ATHREADS, ATTN_SMEM_BYTES>>>(out);
}